// round 1
// baseline (speedup 1.0000x reference)
#include <cuda_runtime.h>

#define Bn 8
#define Sn 4096
#define Dn 512
#define Hn 8
#define DKn 64
#define DFFn 1024
#define Mn (Bn*Sn)          // 32768 rows
#define NCH 16              // seq chunks for partial KV
#define CHROWS 256          // rows per chunk
#define EPSA 1e-6f
#define LNEPS 1e-5f

// ---------------- scratch (device globals; no allocation allowed) ----------
__device__ float g_q   [(size_t)Mn*Dn];
__device__ float g_k   [(size_t)Mn*Dn];
__device__ float g_v   [(size_t)Mn*Dn];
__device__ float g_q2  [(size_t)Mn*Dn];
__device__ float g_attn[(size_t)Mn*Dn];
__device__ float g_y   [(size_t)Mn*Dn];
__device__ float g_x1  [(size_t)Mn*Dn];
__device__ float g_h   [(size_t)Mn*DFFn];
__device__ float g_y2  [(size_t)Mn*Dn];
__device__ float g_kvp [(size_t)Bn*Hn*NCH*DKn*DKn];
__device__ float g_ksp [(size_t)Bn*Hn*NCH*DKn];
__device__ float g_kv  [(size_t)Bn*Hn*DKn*DKn];
__device__ float g_ks  [(size_t)Bn*Hn*DKn];

// ---------------- SGEMM: C[M,N] = A[M,K] @ W[N,K]^T + bias (+epilogue) -----
// EPI: 0 = bias, 1 = bias + residual, 2 = bias + gelu(x)^2 (exact gelu)
template<int EPI>
__global__ __launch_bounds__(256, 2) void sgemm(
    const float* __restrict__ A, const float* __restrict__ W,
    const float* __restrict__ bias, const float* __restrict__ res,
    float* __restrict__ C, int M, int N, int K)
{
    __shared__ float As[8][132];
    __shared__ float Bs[8][132];
    const int t  = threadIdx.x;
    const int tx = t & 15, ty = t >> 4;
    const int bm = blockIdx.y * 128, bn = blockIdx.x * 128;
    const int lr = t >> 1;          // 0..127
    const int lk = (t & 1) * 4;     // 0 or 4
    const float* Ap = A + (size_t)(bm + lr) * K + lk;
    const float* Wp = W + (size_t)(bn + lr) * K + lk;

    float acc[8][8];
#pragma unroll
    for (int i = 0; i < 8; i++)
#pragma unroll
        for (int j = 0; j < 8; j++) acc[i][j] = 0.f;

    for (int kt = 0; kt < K; kt += 8) {
        float4 a4 = *(const float4*)(Ap + kt);
        float4 b4 = *(const float4*)(Wp + kt);
        __syncthreads();
        As[lk+0][lr] = a4.x; As[lk+1][lr] = a4.y;
        As[lk+2][lr] = a4.z; As[lk+3][lr] = a4.w;
        Bs[lk+0][lr] = b4.x; Bs[lk+1][lr] = b4.y;
        Bs[lk+2][lr] = b4.z; Bs[lk+3][lr] = b4.w;
        __syncthreads();
#pragma unroll
        for (int kk = 0; kk < 8; kk++) {
            const float4* ap = (const float4*)&As[kk][ty * 8];
            const float4* bp = (const float4*)&Bs[kk][tx * 8];
            float4 a0 = ap[0], a1 = ap[1];
            float4 b0 = bp[0], b1 = bp[1];
            float a[8] = {a0.x,a0.y,a0.z,a0.w,a1.x,a1.y,a1.z,a1.w};
            float b[8] = {b0.x,b0.y,b0.z,b0.w,b1.x,b1.y,b1.z,b1.w};
#pragma unroll
            for (int i = 0; i < 8; i++)
#pragma unroll
                for (int j = 0; j < 8; j++)
                    acc[i][j] = fmaf(a[i], b[j], acc[i][j]);
        }
    }

#pragma unroll
    for (int i = 0; i < 8; i++) {
        const int row = bm + ty * 8 + i;
        const size_t ro = (size_t)row * N;
#pragma unroll
        for (int j = 0; j < 8; j++) {
            const int col = bn + tx * 8 + j;
            float v = acc[i][j] + bias[col];
            if (EPI == 1) v += res[ro + col];
            if (EPI == 2) {
                float gl = 0.5f * v * (1.0f + erff(v * 0.7071067811865476f));
                v = gl * gl;
            }
            C[ro + col] = v;
        }
    }
}

// ------------- conv(q,k,v) + elu+1(q,k) + partial KV / Ksum ---------------
// grid (NCH, H, B), 256 threads. Writes g_q2, g_kvp, g_ksp.
__global__ __launch_bounds__(256) void conv_pre(
    const float* __restrict__ qb, const float* __restrict__ kb,
    const float* __restrict__ vb,
    const float* __restrict__ qcw, const float* __restrict__ qcb,
    const float* __restrict__ kcw, const float* __restrict__ kcb,
    const float* __restrict__ vcw, const float* __restrict__ vcb)
{
    const int c = blockIdx.x, h = blockIdx.y, b = blockIdx.z;
    const int t  = threadIdx.x;
    const int ch = t & 63, rl = t >> 6;           // conv mapping
    const int d0 = (t & 15) * 4, e0 = (t >> 4) * 4; // KV acc mapping

    __shared__ float k2s[64][68];
    __shared__ float v2s[64][68];

    const float qw0 = qcw[ch*3+0], qw1 = qcw[ch*3+1], qw2 = qcw[ch*3+2], qbv = qcb[ch];
    const float kw0 = kcw[ch*3+0], kw1 = kcw[ch*3+1], kw2 = kcw[ch*3+2], kbv = kcb[ch];
    const float vw0 = vcw[ch*3+0], vw1 = vcw[ch*3+1], vw2 = vcw[ch*3+2], vbv = vcb[ch];

    float acc[4][4];
#pragma unroll
    for (int i = 0; i < 4; i++)
#pragma unroll
        for (int j = 0; j < 4; j++) acc[i][j] = 0.f;
    float ksacc = 0.f;

    for (int sub = 0; sub < 4; sub++) {
        __syncthreads();   // protect smem against previous sub's readers
#pragma unroll 4
        for (int i = 0; i < 16; i++) {
            const int r = rl + 4 * i;                  // 0..63
            const int s = c * CHROWS + sub * 64 + r;   // in-batch seq index
            const size_t base = ((size_t)(b * Sn + s)) * Dn + h * DKn + ch;

            float x0  = qb[base];
            float xm1 = (s >= 1) ? qb[base - Dn]     : 0.f;
            float xm2 = (s >= 2) ? qb[base - 2*Dn]   : 0.f;
            float qc = qw0*xm2 + qw1*xm1 + qw2*x0 + qbv;
            g_q2[base] = qc > 0.f ? qc + 1.f : expf(qc);   // elu(x)+1

            x0  = kb[base];
            xm1 = (s >= 1) ? kb[base - Dn]   : 0.f;
            xm2 = (s >= 2) ? kb[base - 2*Dn] : 0.f;
            float kc = kw0*xm2 + kw1*xm1 + kw2*x0 + kbv;
            k2s[r][ch] = kc > 0.f ? kc + 1.f : expf(kc);

            x0  = vb[base];
            xm1 = (s >= 1) ? vb[base - Dn]   : 0.f;
            xm2 = (s >= 2) ? vb[base - 2*Dn] : 0.f;
            v2s[r][ch] = vw0*xm2 + vw1*xm1 + vw2*x0 + vbv;
        }
        __syncthreads();
        if (t < 64) {
#pragma unroll 8
            for (int r = 0; r < 64; r++) ksacc += k2s[r][t];
        }
#pragma unroll 4
        for (int r = 0; r < 64; r++) {
            float4 kd = *(const float4*)&k2s[r][d0];
            float4 ve = *(const float4*)&v2s[r][e0];
            float kda[4] = {kd.x, kd.y, kd.z, kd.w};
            float vea[4] = {ve.x, ve.y, ve.z, ve.w};
#pragma unroll
            for (int i = 0; i < 4; i++)
#pragma unroll
                for (int j = 0; j < 4; j++)
                    acc[i][j] = fmaf(kda[i], vea[j], acc[i][j]);
        }
    }

    const int bh = b * Hn + h;
    const size_t kvbase = ((size_t)bh * NCH + c) * (DKn * DKn);
#pragma unroll
    for (int i = 0; i < 4; i++)
#pragma unroll
        for (int j = 0; j < 4; j++)
            g_kvp[kvbase + (size_t)(d0 + i) * DKn + (e0 + j)] = acc[i][j];
    if (t < 64)
        g_ksp[((size_t)bh * NCH + c) * DKn + t] = ksacc;
}

// -------------- reduce partial KV / Ksum over chunks ----------------------
__global__ void kv_reduce()
{
    const int bh = blockIdx.x, t = threadIdx.x;
    for (int idx = t; idx < DKn * DKn; idx += 256) {
        float s = 0.f;
#pragma unroll
        for (int c = 0; c < NCH; c++)
            s += g_kvp[((size_t)bh * NCH + c) * (DKn * DKn) + idx];
        g_kv[(size_t)bh * (DKn * DKn) + idx] = s;
    }
    if (t < DKn) {
        float s = 0.f;
#pragma unroll
        for (int c = 0; c < NCH; c++)
            s += g_ksp[((size_t)bh * NCH + c) * DKn + t];
        g_ks[(size_t)bh * DKn + t] = s;
    }
}

// -------------- attn apply: Vn = (Q @ KV) / (Q . (Ksum+eps)) --------------
// grid (S/64, H, B), 256 threads
__global__ __launch_bounds__(256) void attn_apply()
{
    const int st = blockIdx.x, h = blockIdx.y, b = blockIdx.z;
    const int t = threadIdx.x;
    const int bh = b * Hn + h;
    __shared__ float qs [64][68];
    __shared__ float kvs[64][68];
    __shared__ float kss[64];

    for (int idx = t; idx < DKn * DKn; idx += 256) {
        const int r = idx >> 6, chn = idx & 63;
        qs [r][chn] = g_q2[((size_t)(b * Sn + st * 64 + r)) * Dn + h * DKn + chn];
        kvs[r][chn] = g_kv[(size_t)bh * (DKn * DKn) + idx];
    }
    if (t < DKn) kss[t] = g_ks[(size_t)bh * DKn + t] + EPSA;
    __syncthreads();

    const int sl = t >> 2;            // local row 0..63
    const int e0 = (t & 3) * 16;      // output col group
    float z = 0.f;
    float o[16];
#pragma unroll
    for (int j = 0; j < 16; j++) o[j] = 0.f;

#pragma unroll 8
    for (int d = 0; d < 64; d++) {
        const float qd = qs[sl][d];
        z = fmaf(qd, kss[d], z);
        const float4* kp = (const float4*)&kvs[d][e0];
        float4 k0 = kp[0], k1 = kp[1], k2 = kp[2], k3 = kp[3];
        o[0]  = fmaf(qd, k0.x, o[0]);  o[1]  = fmaf(qd, k0.y, o[1]);
        o[2]  = fmaf(qd, k0.z, o[2]);  o[3]  = fmaf(qd, k0.w, o[3]);
        o[4]  = fmaf(qd, k1.x, o[4]);  o[5]  = fmaf(qd, k1.y, o[5]);
        o[6]  = fmaf(qd, k1.z, o[6]);  o[7]  = fmaf(qd, k1.w, o[7]);
        o[8]  = fmaf(qd, k2.x, o[8]);  o[9]  = fmaf(qd, k2.y, o[9]);
        o[10] = fmaf(qd, k2.z, o[10]); o[11] = fmaf(qd, k2.w, o[11]);
        o[12] = fmaf(qd, k3.x, o[12]); o[13] = fmaf(qd, k3.y, o[13]);
        o[14] = fmaf(qd, k3.z, o[14]); o[15] = fmaf(qd, k3.w, o[15]);
    }
    const float zi = 1.0f / z;
    const size_t ob = ((size_t)(b * Sn + st * 64 + sl)) * Dn + h * DKn + e0;
#pragma unroll
    for (int j = 0; j < 16; j++) g_attn[ob + j] = zi * o[j];
}

// -------------------------- LayerNorm (D=512) ------------------------------
__global__ __launch_bounds__(256) void ln_kernel(
    const float* __restrict__ in, const float* __restrict__ gw,
    const float* __restrict__ bw, float* __restrict__ out)
{
    const int row = blockIdx.x, t = threadIdx.x;
    const float* rp = in + (size_t)row * Dn;
    const int c = t * 2;
    float2 v = *(const float2*)(rp + c);
    float s1 = v.x + v.y;
    float s2 = v.x * v.x + v.y * v.y;
#pragma unroll
    for (int o = 16; o > 0; o >>= 1) {
        s1 += __shfl_down_sync(0xffffffffu, s1, o);
        s2 += __shfl_down_sync(0xffffffffu, s2, o);
    }
    __shared__ float sh1[8], sh2[8];
    __shared__ float msh, rsh;
    if ((t & 31) == 0) { sh1[t >> 5] = s1; sh2[t >> 5] = s2; }
    __syncthreads();
    if (t == 0) {
        float a = 0.f, q = 0.f;
#pragma unroll
        for (int i = 0; i < 8; i++) { a += sh1[i]; q += sh2[i]; }
        const float m = a * (1.0f / Dn);
        const float var = q * (1.0f / Dn) - m * m;
        msh = m;
        rsh = rsqrtf(var + LNEPS);
    }
    __syncthreads();
    const float m = msh, r = rsh;
    float2 o2;
    o2.x = (v.x - m) * r * gw[c]     + bw[c];
    o2.y = (v.y - m) * r * gw[c + 1] + bw[c + 1];
    *(float2*)(out + (size_t)row * Dn + c) = o2;
}

// ------------------------------- launch ------------------------------------
extern "C" void kernel_launch(void* const* d_in, const int* in_sizes, int n_in,
                              void* d_out, int out_size)
{
    const float* x    = (const float*)d_in[0];
    const float* wq   = (const float*)d_in[1];
    const float* bq   = (const float*)d_in[2];
    const float* wk   = (const float*)d_in[3];
    const float* bk   = (const float*)d_in[4];
    const float* wv   = (const float*)d_in[5];
    const float* bv   = (const float*)d_in[6];
    const float* wo   = (const float*)d_in[7];
    const float* bo   = (const float*)d_in[8];
    const float* qcw  = (const float*)d_in[9];
    const float* qcb  = (const float*)d_in[10];
    const float* kcw  = (const float*)d_in[11];
    const float* kcb  = (const float*)d_in[12];
    const float* vcw  = (const float*)d_in[13];
    const float* vcb  = (const float*)d_in[14];
    const float* w1   = (const float*)d_in[15];
    const float* b1   = (const float*)d_in[16];
    const float* w2   = (const float*)d_in[17];
    const float* b2   = (const float*)d_in[18];
    const float* ln1g = (const float*)d_in[19];
    const float* ln1b = (const float*)d_in[20];
    const float* ln2g = (const float*)d_in[21];
    const float* ln2b = (const float*)d_in[22];
    float* out = (float*)d_out;

    float *pq, *pk, *pv, *pattn, *py, *px1, *ph, *py2;
    cudaGetSymbolAddress((void**)&pq,    g_q);
    cudaGetSymbolAddress((void**)&pk,    g_k);
    cudaGetSymbolAddress((void**)&pv,    g_v);
    cudaGetSymbolAddress((void**)&pattn, g_attn);
    cudaGetSymbolAddress((void**)&py,    g_y);
    cudaGetSymbolAddress((void**)&px1,   g_x1);
    cudaGetSymbolAddress((void**)&ph,    g_h);
    cudaGetSymbolAddress((void**)&py2,   g_y2);

    const dim3 gridD (Dn   / 128, Mn / 128);   // (4, 256)
    const dim3 gridF (DFFn / 128, Mn / 128);   // (8, 256)

    // QKV projections
    sgemm<0><<<gridD, 256>>>(x, wq, bq, nullptr, pq, Mn, Dn, Dn);
    sgemm<0><<<gridD, 256>>>(x, wk, bk, nullptr, pk, Mn, Dn, Dn);
    sgemm<0><<<gridD, 256>>>(x, wv, bv, nullptr, pv, Mn, Dn, Dn);

    // depthwise conv + elu+1 + partial KV/Ksum
    conv_pre<<<dim3(NCH, Hn, Bn), 256>>>(pq, pk, pv,
                                         qcw, qcb, kcw, kcb, vcw, vcb);
    kv_reduce<<<Bn * Hn, 256>>>();
    attn_apply<<<dim3(Sn / 64, Hn, Bn), 256>>>();

    // output projection + residual, then LN1
    sgemm<1><<<gridD, 256>>>(pattn, wo, bo, x, py, Mn, Dn, Dn);
    ln_kernel<<<Mn, 256>>>(py, ln1g, ln1b, px1);

    // FFN: gelu^2 mid, then proj + residual, then LN2
    sgemm<2><<<gridF, 256>>>(px1, w1, b1, nullptr, ph, Mn, DFFn, Dn);
    sgemm<1><<<gridD, 256>>>(ph, w2, b2, px1, py2, Mn, Dn, DFFn);
    ln_kernel<<<Mn, 256>>>(py2, ln2g, ln2b, out);
}

// round 3
// speedup vs baseline: 2.0081x; 2.0081x over previous
#include <cuda_runtime.h>
#include <cuda_bf16.h>
#include <cstdint>

#define Bn 8
#define Sn 4096
#define Dn 512
#define Hn 8
#define DKn 64
#define DFFn 1024
#define Mn (Bn*Sn)          // 32768 rows
#define NCH 16              // seq chunks for partial KV
#define CHROWS 256
#define EPSA 1e-6f
#define LNEPS 1e-5f

// ---------------- scratch (device globals; no allocation allowed) ----------
__device__ float g_q   [(size_t)Mn*Dn];
__device__ float g_k   [(size_t)Mn*Dn];
__device__ float g_v   [(size_t)Mn*Dn];
__device__ float g_q2  [(size_t)Mn*Dn];
__device__ float g_y   [(size_t)Mn*Dn];
__device__ float g_x1  [(size_t)Mn*Dn];
__device__ float g_y2  [(size_t)Mn*Dn];
__device__ float g_kvp [(size_t)Bn*Hn*NCH*DKn*DKn];
__device__ float g_ksp [(size_t)Bn*Hn*NCH*DKn];
__device__ float g_kv  [(size_t)Bn*Hn*DKn*DKn];
__device__ float g_ks  [(size_t)Bn*Hn*DKn];

// bf16 split buffers (hi/lo)
__device__ __nv_bfloat16 g_xh [(size_t)Mn*Dn],   g_xl [(size_t)Mn*Dn];
__device__ __nv_bfloat16 g_ath[(size_t)Mn*Dn],   g_atl[(size_t)Mn*Dn];
__device__ __nv_bfloat16 g_x1h[(size_t)Mn*Dn],   g_x1l[(size_t)Mn*Dn];
__device__ __nv_bfloat16 g_hh [(size_t)Mn*DFFn], g_hl [(size_t)Mn*DFFn];
// weight splits
__device__ __nv_bfloat16 g_wqh[Dn*Dn], g_wql[Dn*Dn];
__device__ __nv_bfloat16 g_wkh[Dn*Dn], g_wkl[Dn*Dn];
__device__ __nv_bfloat16 g_wvh[Dn*Dn], g_wvl[Dn*Dn];
__device__ __nv_bfloat16 g_woh[Dn*Dn], g_wol[Dn*Dn];
__device__ __nv_bfloat16 g_w1h[DFFn*Dn], g_w1l[DFFn*Dn];
__device__ __nv_bfloat16 g_w2h[Dn*DFFn], g_w2l[Dn*DFFn];

// ------------------------- PTX helpers -------------------------------------
__device__ __forceinline__ uint32_t smem_u32(const void* p) {
    uint32_t a;
    asm("{ .reg .u64 t; cvta.to.shared.u64 t, %1; cvt.u32.u64 %0, t; }"
        : "=r"(a) : "l"(p));
    return a;
}

__device__ __forceinline__ void ldm4(uint32_t* r, uint32_t addr) {
    asm volatile("ldmatrix.sync.aligned.m8n8.x4.shared.b16 {%0,%1,%2,%3}, [%4];"
                 : "=r"(r[0]), "=r"(r[1]), "=r"(r[2]), "=r"(r[3]) : "r"(addr));
}

__device__ __forceinline__ void mma16816(float* c, const uint32_t* a, const uint32_t* b) {
    asm volatile(
        "mma.sync.aligned.m16n8k16.row.col.f32.bf16.bf16.f32 "
        "{%0,%1,%2,%3}, {%4,%5,%6,%7}, {%8,%9}, {%0,%1,%2,%3};"
        : "+f"(c[0]), "+f"(c[1]), "+f"(c[2]), "+f"(c[3])
        : "r"(a[0]), "r"(a[1]), "r"(a[2]), "r"(a[3]), "r"(b[0]), "r"(b[1]));
}

// ================ HMMA split-bf16 GEMM: C = (Ah+Al)(Wh+Wl)^T + bias ========
// EPI: 0 = bias -> C fp32 ; 1 = bias+res -> C fp32 ; 2 = gelu(x)^2 -> Ch/Cl bf16
// CTA tile 128x128, K-chunk 32, 8 warps (4M x 2N), warp tile 32x64.
#define PITCH 80                 // bytes per smem row (32 bf16 + 8 pad)
#define MATB  (128 * PITCH)      // 10240 bytes per matrix tile
#define STAGE (4 * MATB)         // 40960 bytes per stage
#define GSMEM (2 * STAGE)        // 81920

template<int EPI>
__global__ void __launch_bounds__(256) gemm_mma(
    const __nv_bfloat16* __restrict__ Ah, const __nv_bfloat16* __restrict__ Al,
    const __nv_bfloat16* __restrict__ Wh, const __nv_bfloat16* __restrict__ Wl,
    const float* __restrict__ bias, const float* __restrict__ res,
    float* __restrict__ C, __nv_bfloat16* __restrict__ Ch, __nv_bfloat16* __restrict__ Cl,
    int M, int N, int K)
{
    extern __shared__ char smem[];
    const uint32_t sb = smem_u32(smem);
    const int tid  = threadIdx.x;
    const int bn = blockIdx.x * 128, bm = blockIdx.y * 128;
    const int w = tid >> 5, lane = tid & 31;
    const int wm = w & 3, wn = w >> 2;         // warp tile: rows wm*32, cols wn*64
    const int mrow = lane >> 3, mr = lane & 7; // ldmatrix sub-matrix id / row

    const __nv_bfloat16* mats[4] = { Ah + (size_t)bm * K, Al + (size_t)bm * K,
                                     Wh + (size_t)bn * K, Wl + (size_t)bn * K };
    const int nch = K >> 5;

    auto load_chunk = [&](int kt, int stg) {
        const uint32_t sbase = sb + stg * STAGE;
#pragma unroll
        for (int i = 0; i < 8; i++) {
            const int idx = tid + i * 256;
            const int mat = idx >> 9;           // 512 chunks of 16B per matrix
            const int rem = idx & 511;
            const int r = rem >> 2, c = rem & 3;
            const uint32_t dst = sbase + mat * MATB + r * PITCH + c * 16;
            const void* src = mats[mat] + (size_t)r * K + kt * 32 + c * 8;
            asm volatile("cp.async.cg.shared.global [%0], [%1], 16;"
                         :: "r"(dst), "l"(src));
        }
        asm volatile("cp.async.commit_group;");
    };

    float acc[2][8][4];
#pragma unroll
    for (int i = 0; i < 2; i++)
#pragma unroll
        for (int j = 0; j < 8; j++)
#pragma unroll
            for (int q = 0; q < 4; q++) acc[i][j][q] = 0.f;

    load_chunk(0, 0);

    for (int kt = 0; kt < nch; kt++) {
        const int stg = kt & 1;
        asm volatile("cp.async.wait_group 0;" ::: "memory");
        __syncthreads();
        if (kt + 1 < nch) load_chunk(kt + 1, stg ^ 1);

        const uint32_t base = sb + stg * STAGE;
#pragma unroll
        for (int ks = 0; ks < 2; ks++) {
            uint32_t ah[2][4], al[2][4], bh[8][2], bl[8][2];
            // A fragments: matrices (row-half = mrow&1, k-half = mrow>>1)
#pragma unroll
            for (int i = 0; i < 2; i++) {
                const int rowA = wm * 32 + i * 16 + (mrow & 1) * 8 + mr;
                const uint32_t cA = ks * 32 + (mrow >> 1) * 16; // bytes
                ldm4(ah[i], base +        rowA * PITCH + cA);
                ldm4(al[i], base + MATB + rowA * PITCH + cA);
            }
            // B fragments: matrices (k-half = mrow&1, n-half = mrow>>1)
#pragma unroll
            for (int jp = 0; jp < 4; jp++) {
                const int rowB = wn * 64 + jp * 16 + (mrow >> 1) * 8 + mr;
                const uint32_t cB = ks * 32 + (mrow & 1) * 16;
                uint32_t t0[4], t1[4];
                ldm4(t0, base + 2 * MATB + rowB * PITCH + cB);
                ldm4(t1, base + 3 * MATB + rowB * PITCH + cB);
                bh[2*jp][0] = t0[0]; bh[2*jp][1] = t0[1];
                bh[2*jp+1][0] = t0[2]; bh[2*jp+1][1] = t0[3];
                bl[2*jp][0] = t1[0]; bl[2*jp][1] = t1[1];
                bl[2*jp+1][0] = t1[2]; bl[2*jp+1][1] = t1[3];
            }
#pragma unroll
            for (int i = 0; i < 2; i++)
#pragma unroll
                for (int j = 0; j < 8; j++) {
                    mma16816(acc[i][j], ah[i], bh[j]);
                    mma16816(acc[i][j], ah[i], bl[j]);
                    mma16816(acc[i][j], al[i], bh[j]);
                }
        }
        __syncthreads();
    }

    // ------------------------------ epilogue --------------------------------
    const int tg = lane >> 2, ti = lane & 3;
#pragma unroll
    for (int i = 0; i < 2; i++) {
#pragma unroll
        for (int j = 0; j < 8; j++) {
            const int gr0 = bm + wm * 32 + i * 16 + tg;
            const int gc  = bn + wn * 64 + j * 8 + ti * 2;
            const float b0 = bias[gc], b1 = bias[gc + 1];
#pragma unroll
            for (int hfl = 0; hfl < 2; hfl++) {
                const int gr = gr0 + hfl * 8;
                float v0 = acc[i][j][2*hfl + 0] + b0;
                float v1 = acc[i][j][2*hfl + 1] + b1;
                const size_t off = (size_t)gr * N + gc;
                if (EPI == 1) {
                    float2 rv = *(const float2*)(res + off);
                    v0 += rv.x; v1 += rv.y;
                }
                if (EPI == 2) {
                    float g0 = 0.5f * v0 * (1.0f + erff(v0 * 0.7071067811865476f));
                    float g1 = 0.5f * v1 * (1.0f + erff(v1 * 0.7071067811865476f));
                    v0 = g0 * g0; v1 = g1 * g1;
                    __nv_bfloat16 h0 = __float2bfloat16_rn(v0);
                    __nv_bfloat16 h1 = __float2bfloat16_rn(v1);
                    __nv_bfloat162 hp; hp.x = h0; hp.y = h1;
                    __nv_bfloat16 l0 = __float2bfloat16_rn(v0 - __bfloat162float(h0));
                    __nv_bfloat16 l1 = __float2bfloat16_rn(v1 - __bfloat162float(h1));
                    __nv_bfloat162 lp; lp.x = l0; lp.y = l1;
                    *(__nv_bfloat162*)(Ch + off) = hp;
                    *(__nv_bfloat162*)(Cl + off) = lp;
                } else {
                    float2 ov; ov.x = v0; ov.y = v1;
                    *(float2*)(C + off) = ov;
                }
            }
        }
    }
}

// ------------------ fp32 -> bf16 hi/lo split (vectorized) ------------------
__global__ void cvt_split(const float* __restrict__ in,
                          __nv_bfloat16* __restrict__ hi,
                          __nv_bfloat16* __restrict__ lo, int n4)
{
    const int i = blockIdx.x * 256 + threadIdx.x;
    if (i >= n4) return;
    float4 v = ((const float4*)in)[i];
    __nv_bfloat16 h0 = __float2bfloat16_rn(v.x);
    __nv_bfloat16 h1 = __float2bfloat16_rn(v.y);
    __nv_bfloat16 h2 = __float2bfloat16_rn(v.z);
    __nv_bfloat16 h3 = __float2bfloat16_rn(v.w);
    __nv_bfloat162 hp0; hp0.x = h0; hp0.y = h1;
    __nv_bfloat162 hp1; hp1.x = h2; hp1.y = h3;
    __nv_bfloat16 l0 = __float2bfloat16_rn(v.x - __bfloat162float(h0));
    __nv_bfloat16 l1 = __float2bfloat16_rn(v.y - __bfloat162float(h1));
    __nv_bfloat16 l2 = __float2bfloat16_rn(v.z - __bfloat162float(h2));
    __nv_bfloat16 l3 = __float2bfloat16_rn(v.w - __bfloat162float(h3));
    __nv_bfloat162 lp0; lp0.x = l0; lp0.y = l1;
    __nv_bfloat162 lp1; lp1.x = l2; lp1.y = l3;
    ((__nv_bfloat162*)hi)[2 * i]     = hp0;
    ((__nv_bfloat162*)hi)[2 * i + 1] = hp1;
    ((__nv_bfloat162*)lo)[2 * i]     = lp0;
    ((__nv_bfloat162*)lo)[2 * i + 1] = lp1;
}

// ------------- conv(q,k,v) + elu+1(q,k) + partial KV / Ksum ---------------
__global__ __launch_bounds__(256) void conv_pre(
    const float* __restrict__ qb, const float* __restrict__ kb,
    const float* __restrict__ vb,
    const float* __restrict__ qcw, const float* __restrict__ qcb,
    const float* __restrict__ kcw, const float* __restrict__ kcb,
    const float* __restrict__ vcw, const float* __restrict__ vcb)
{
    const int c = blockIdx.x, h = blockIdx.y, b = blockIdx.z;
    const int t  = threadIdx.x;
    const int ch = t & 63, rl = t >> 6;
    const int d0 = (t & 15) * 4, e0 = (t >> 4) * 4;

    __shared__ float k2s[64][68];
    __shared__ float v2s[64][68];

    const float qw0 = qcw[ch*3+0], qw1 = qcw[ch*3+1], qw2 = qcw[ch*3+2], qbv = qcb[ch];
    const float kw0 = kcw[ch*3+0], kw1 = kcw[ch*3+1], kw2 = kcw[ch*3+2], kbv = kcb[ch];
    const float vw0 = vcw[ch*3+0], vw1 = vcw[ch*3+1], vw2 = vcw[ch*3+2], vbv = vcb[ch];

    float acc[4][4];
#pragma unroll
    for (int i = 0; i < 4; i++)
#pragma unroll
        for (int j = 0; j < 4; j++) acc[i][j] = 0.f;
    float ksacc = 0.f;

    for (int sub = 0; sub < 4; sub++) {
        __syncthreads();
#pragma unroll 4
        for (int i = 0; i < 16; i++) {
            const int r = rl + 4 * i;
            const int s = c * CHROWS + sub * 64 + r;
            const size_t base = ((size_t)(b * Sn + s)) * Dn + h * DKn + ch;

            float x0  = qb[base];
            float xm1 = (s >= 1) ? qb[base - Dn]     : 0.f;
            float xm2 = (s >= 2) ? qb[base - 2*Dn]   : 0.f;
            float qc = qw0*xm2 + qw1*xm1 + qw2*x0 + qbv;
            g_q2[base] = qc > 0.f ? qc + 1.f : expf(qc);

            x0  = kb[base];
            xm1 = (s >= 1) ? kb[base - Dn]   : 0.f;
            xm2 = (s >= 2) ? kb[base - 2*Dn] : 0.f;
            float kc = kw0*xm2 + kw1*xm1 + kw2*x0 + kbv;
            k2s[r][ch] = kc > 0.f ? kc + 1.f : expf(kc);

            x0  = vb[base];
            xm1 = (s >= 1) ? vb[base - Dn]   : 0.f;
            xm2 = (s >= 2) ? vb[base - 2*Dn] : 0.f;
            v2s[r][ch] = vw0*xm2 + vw1*xm1 + vw2*x0 + vbv;
        }
        __syncthreads();
        if (t < 64) {
#pragma unroll 8
            for (int r = 0; r < 64; r++) ksacc += k2s[r][t];
        }
#pragma unroll 4
        for (int r = 0; r < 64; r++) {
            float4 kd = *(const float4*)&k2s[r][d0];
            float4 ve = *(const float4*)&v2s[r][e0];
            float kda[4] = {kd.x, kd.y, kd.z, kd.w};
            float vea[4] = {ve.x, ve.y, ve.z, ve.w};
#pragma unroll
            for (int i = 0; i < 4; i++)
#pragma unroll
                for (int j = 0; j < 4; j++)
                    acc[i][j] = fmaf(kda[i], vea[j], acc[i][j]);
        }
    }

    const int bh = b * Hn + h;
    const size_t kvbase = ((size_t)bh * NCH + c) * (DKn * DKn);
#pragma unroll
    for (int i = 0; i < 4; i++)
#pragma unroll
        for (int j = 0; j < 4; j++)
            g_kvp[kvbase + (size_t)(d0 + i) * DKn + (e0 + j)] = acc[i][j];
    if (t < 64)
        g_ksp[((size_t)bh * NCH + c) * DKn + t] = ksacc;
}

// -------------- reduce partial KV / Ksum over chunks ----------------------
__global__ void kv_reduce()
{
    const int bh = blockIdx.x, t = threadIdx.x;
    for (int idx = t; idx < DKn * DKn; idx += 256) {
        float s = 0.f;
#pragma unroll
        for (int c = 0; c < NCH; c++)
            s += g_kvp[((size_t)bh * NCH + c) * (DKn * DKn) + idx];
        g_kv[(size_t)bh * (DKn * DKn) + idx] = s;
    }
    if (t < DKn) {
        float s = 0.f;
#pragma unroll
        for (int c = 0; c < NCH; c++)
            s += g_ksp[((size_t)bh * NCH + c) * DKn + t];
        g_ks[(size_t)bh * DKn + t] = s;
    }
}

// -------------- attn apply: Vn = (Q @ KV) / (Q . (Ksum+eps)) --------------
// writes bf16 hi/lo directly (A operand of the O-projection GEMM)
__global__ __launch_bounds__(256) void attn_apply()
{
    const int st = blockIdx.x, h = blockIdx.y, b = blockIdx.z;
    const int t = threadIdx.x;
    const int bh = b * Hn + h;
    __shared__ float qs [64][68];
    __shared__ float kvs[64][68];
    __shared__ float kss[64];

    for (int idx = t; idx < DKn * DKn; idx += 256) {
        const int r = idx >> 6, chn = idx & 63;
        qs [r][chn] = g_q2[((size_t)(b * Sn + st * 64 + r)) * Dn + h * DKn + chn];
        kvs[r][chn] = g_kv[(size_t)bh * (DKn * DKn) + idx];
    }
    if (t < DKn) kss[t] = g_ks[(size_t)bh * DKn + t] + EPSA;
    __syncthreads();

    const int sl = t >> 2;
    const int e0 = (t & 3) * 16;
    float z = 0.f;
    float o[16];
#pragma unroll
    for (int j = 0; j < 16; j++) o[j] = 0.f;

#pragma unroll 8
    for (int d = 0; d < 64; d++) {
        const float qd = qs[sl][d];
        z = fmaf(qd, kss[d], z);
        const float4* kp = (const float4*)&kvs[d][e0];
        float4 k0 = kp[0], k1 = kp[1], k2 = kp[2], k3 = kp[3];
        o[0]  = fmaf(qd, k0.x, o[0]);  o[1]  = fmaf(qd, k0.y, o[1]);
        o[2]  = fmaf(qd, k0.z, o[2]);  o[3]  = fmaf(qd, k0.w, o[3]);
        o[4]  = fmaf(qd, k1.x, o[4]);  o[5]  = fmaf(qd, k1.y, o[5]);
        o[6]  = fmaf(qd, k1.z, o[6]);  o[7]  = fmaf(qd, k1.w, o[7]);
        o[8]  = fmaf(qd, k2.x, o[8]);  o[9]  = fmaf(qd, k2.y, o[9]);
        o[10] = fmaf(qd, k2.z, o[10]); o[11] = fmaf(qd, k2.w, o[11]);
        o[12] = fmaf(qd, k3.x, o[12]); o[13] = fmaf(qd, k3.y, o[13]);
        o[14] = fmaf(qd, k3.z, o[14]); o[15] = fmaf(qd, k3.w, o[15]);
    }
    const float zi = 1.0f / z;
    const size_t ob = ((size_t)(b * Sn + st * 64 + sl)) * Dn + h * DKn + e0;
#pragma unroll
    for (int j = 0; j < 16; j += 2) {
        float v0 = zi * o[j], v1 = zi * o[j + 1];
        __nv_bfloat16 h0 = __float2bfloat16_rn(v0);
        __nv_bfloat16 h1 = __float2bfloat16_rn(v1);
        __nv_bfloat162 hp; hp.x = h0; hp.y = h1;
        __nv_bfloat16 l0 = __float2bfloat16_rn(v0 - __bfloat162float(h0));
        __nv_bfloat16 l1 = __float2bfloat16_rn(v1 - __bfloat162float(h1));
        __nv_bfloat162 lp; lp.x = l0; lp.y = l1;
        *(__nv_bfloat162*)(g_ath + ob + j) = hp;
        *(__nv_bfloat162*)(g_atl + ob + j) = lp;
    }
}

// -------------------------- LayerNorm (D=512) ------------------------------
template<bool SPLIT>
__global__ __launch_bounds__(256) void ln_kernel(
    const float* __restrict__ in, const float* __restrict__ gw,
    const float* __restrict__ bw, float* __restrict__ out,
    __nv_bfloat16* __restrict__ oh, __nv_bfloat16* __restrict__ ol)
{
    const int row = blockIdx.x, t = threadIdx.x;
    const float* rp = in + (size_t)row * Dn;
    const int c = t * 2;
    float2 v = *(const float2*)(rp + c);
    float s1 = v.x + v.y;
    float s2 = v.x * v.x + v.y * v.y;
#pragma unroll
    for (int o = 16; o > 0; o >>= 1) {
        s1 += __shfl_down_sync(0xffffffffu, s1, o);
        s2 += __shfl_down_sync(0xffffffffu, s2, o);
    }
    __shared__ float sh1[8], sh2[8];
    __shared__ float msh, rsh;
    if ((t & 31) == 0) { sh1[t >> 5] = s1; sh2[t >> 5] = s2; }
    __syncthreads();
    if (t == 0) {
        float a = 0.f, q = 0.f;
#pragma unroll
        for (int i = 0; i < 8; i++) { a += sh1[i]; q += sh2[i]; }
        const float m = a * (1.0f / Dn);
        const float var = q * (1.0f / Dn) - m * m;
        msh = m;
        rsh = rsqrtf(var + LNEPS);
    }
    __syncthreads();
    const float m = msh, r = rsh;
    float2 o2;
    o2.x = (v.x - m) * r * gw[c]     + bw[c];
    o2.y = (v.y - m) * r * gw[c + 1] + bw[c + 1];
    *(float2*)(out + (size_t)row * Dn + c) = o2;
    if (SPLIT) {
        __nv_bfloat16 h0 = __float2bfloat16_rn(o2.x);
        __nv_bfloat16 h1 = __float2bfloat16_rn(o2.y);
        __nv_bfloat162 hp; hp.x = h0; hp.y = h1;
        __nv_bfloat16 l0 = __float2bfloat16_rn(o2.x - __bfloat162float(h0));
        __nv_bfloat16 l1 = __float2bfloat16_rn(o2.y - __bfloat162float(h1));
        __nv_bfloat162 lp; lp.x = l0; lp.y = l1;
        *(__nv_bfloat162*)(oh + (size_t)row * Dn + c) = hp;
        *(__nv_bfloat162*)(ol + (size_t)row * Dn + c) = lp;
    }
}

// ------------------------------- launch ------------------------------------
extern "C" void kernel_launch(void* const* d_in, const int* in_sizes, int n_in,
                              void* d_out, int out_size)
{
    const float* x    = (const float*)d_in[0];
    const float* wq   = (const float*)d_in[1];
    const float* bq   = (const float*)d_in[2];
    const float* wk   = (const float*)d_in[3];
    const float* bk   = (const float*)d_in[4];
    const float* wv   = (const float*)d_in[5];
    const float* bv   = (const float*)d_in[6];
    const float* wo   = (const float*)d_in[7];
    const float* bo   = (const float*)d_in[8];
    const float* qcw  = (const float*)d_in[9];
    const float* qcb  = (const float*)d_in[10];
    const float* kcw  = (const float*)d_in[11];
    const float* kcb  = (const float*)d_in[12];
    const float* vcw  = (const float*)d_in[13];
    const float* vcb  = (const float*)d_in[14];
    const float* w1   = (const float*)d_in[15];
    const float* b1   = (const float*)d_in[16];
    const float* w2   = (const float*)d_in[17];
    const float* b2   = (const float*)d_in[18];
    const float* ln1g = (const float*)d_in[19];
    const float* ln1b = (const float*)d_in[20];
    const float* ln2g = (const float*)d_in[21];
    const float* ln2b = (const float*)d_in[22];
    float* out = (float*)d_out;

    float *pq, *pk, *pv, *py, *px1, *py2;
    cudaGetSymbolAddress((void**)&pq,  g_q);
    cudaGetSymbolAddress((void**)&pk,  g_k);
    cudaGetSymbolAddress((void**)&pv,  g_v);
    cudaGetSymbolAddress((void**)&py,  g_y);
    cudaGetSymbolAddress((void**)&px1, g_x1);
    cudaGetSymbolAddress((void**)&py2, g_y2);

    __nv_bfloat16 *pxh, *pxl, *path, *patl, *px1h, *px1l, *phh, *phl;
    __nv_bfloat16 *pwqh, *pwql, *pwkh, *pwkl, *pwvh, *pwvl, *pwoh, *pwol;
    __nv_bfloat16 *pw1h, *pw1l, *pw2h, *pw2l;
    cudaGetSymbolAddress((void**)&pxh,  g_xh);  cudaGetSymbolAddress((void**)&pxl,  g_xl);
    cudaGetSymbolAddress((void**)&path, g_ath); cudaGetSymbolAddress((void**)&patl, g_atl);
    cudaGetSymbolAddress((void**)&px1h, g_x1h); cudaGetSymbolAddress((void**)&px1l, g_x1l);
    cudaGetSymbolAddress((void**)&phh,  g_hh);  cudaGetSymbolAddress((void**)&phl,  g_hl);
    cudaGetSymbolAddress((void**)&pwqh, g_wqh); cudaGetSymbolAddress((void**)&pwql, g_wql);
    cudaGetSymbolAddress((void**)&pwkh, g_wkh); cudaGetSymbolAddress((void**)&pwkl, g_wkl);
    cudaGetSymbolAddress((void**)&pwvh, g_wvh); cudaGetSymbolAddress((void**)&pwvl, g_wvl);
    cudaGetSymbolAddress((void**)&pwoh, g_woh); cudaGetSymbolAddress((void**)&pwol, g_wol);
    cudaGetSymbolAddress((void**)&pw1h, g_w1h); cudaGetSymbolAddress((void**)&pw1l, g_w1l);
    cudaGetSymbolAddress((void**)&pw2h, g_w2h); cudaGetSymbolAddress((void**)&pw2l, g_w2l);

    cudaFuncSetAttribute(gemm_mma<0>, cudaFuncAttributeMaxDynamicSharedMemorySize, GSMEM);
    cudaFuncSetAttribute(gemm_mma<1>, cudaFuncAttributeMaxDynamicSharedMemorySize, GSMEM);
    cudaFuncSetAttribute(gemm_mma<2>, cudaFuncAttributeMaxDynamicSharedMemorySize, GSMEM);

    auto cvt = [](const float* p, __nv_bfloat16* h, __nv_bfloat16* l, size_t n) {
        int n4 = (int)(n / 4);
        cvt_split<<<(n4 + 255) / 256, 256>>>(p, h, l, n4);
    };

    // input + weight splits
    cvt(x,  pxh,  pxl,  (size_t)Mn * Dn);
    cvt(wq, pwqh, pwql, (size_t)Dn * Dn);
    cvt(wk, pwkh, pwkl, (size_t)Dn * Dn);
    cvt(wv, pwvh, pwvl, (size_t)Dn * Dn);
    cvt(wo, pwoh, pwol, (size_t)Dn * Dn);
    cvt(w1, pw1h, pw1l, (size_t)DFFn * Dn);
    cvt(w2, pw2h, pw2l, (size_t)Dn * DFFn);

    const dim3 gridD(Dn / 128, Mn / 128);    // (4, 256)
    const dim3 gridF(DFFn / 128, Mn / 128);  // (8, 256)

    // QKV projections (HMMA split-bf16)
    gemm_mma<0><<<gridD, 256, GSMEM>>>(pxh, pxl, pwqh, pwql, bq, nullptr,
                                       pq, nullptr, nullptr, Mn, Dn, Dn);
    gemm_mma<0><<<gridD, 256, GSMEM>>>(pxh, pxl, pwkh, pwkl, bk, nullptr,
                                       pk, nullptr, nullptr, Mn, Dn, Dn);
    gemm_mma<0><<<gridD, 256, GSMEM>>>(pxh, pxl, pwvh, pwvl, bv, nullptr,
                                       pv, nullptr, nullptr, Mn, Dn, Dn);

    // depthwise conv + elu+1 + partial KV/Ksum
    conv_pre<<<dim3(NCH, Hn, Bn), 256>>>(pq, pk, pv, qcw, qcb, kcw, kcb, vcw, vcb);
    kv_reduce<<<Bn * Hn, 256>>>();
    attn_apply<<<dim3(Sn / 64, Hn, Bn), 256>>>();

    // output projection + residual, then LN1 (LN1 also emits bf16 split)
    gemm_mma<1><<<gridD, 256, GSMEM>>>(path, patl, pwoh, pwol, bo, x,
                                       py, nullptr, nullptr, Mn, Dn, Dn);
    ln_kernel<true><<<Mn, 256>>>(py, ln1g, ln1b, px1, px1h, px1l);

    // FFN1: gelu^2, writes bf16 split directly; FFN2 consumes it (K=1024)
    gemm_mma<2><<<gridF, 256, GSMEM>>>(px1h, px1l, pw1h, pw1l, b1, nullptr,
                                       nullptr, phh, phl, Mn, DFFn, Dn);
    gemm_mma<1><<<gridD, 256, GSMEM>>>(phh, phl, pw2h, pw2l, b2, px1,
                                       py2, nullptr, nullptr, Mn, Dn, DFFn);
    ln_kernel<false><<<Mn, 256>>>(py2, ln2g, ln2b, out, nullptr, nullptr);
}

// round 4
// speedup vs baseline: 2.1213x; 1.0564x over previous
#include <cuda_runtime.h>
#include <cuda_bf16.h>
#include <cstdint>

#define Bn 8
#define Sn 4096
#define Dn 512
#define Hn 8
#define DKn 64
#define DFFn 1024
#define Mn (Bn*Sn)          // 32768 rows
#define NCH 16              // seq chunks for partial KV
#define CHROWS 256
#define EPSA 1e-6f
#define LNEPS 1e-5f

// ---------------- scratch (device globals; no allocation allowed) ----------
__device__ float g_q   [(size_t)Mn*Dn];
__device__ float g_k   [(size_t)Mn*Dn];
__device__ float g_v   [(size_t)Mn*Dn];
__device__ float g_q2  [(size_t)Mn*Dn];
__device__ float g_y   [(size_t)Mn*Dn];
__device__ float g_x1  [(size_t)Mn*Dn];
__device__ float g_y2  [(size_t)Mn*Dn];
__device__ float g_kvp [(size_t)Bn*Hn*NCH*DKn*DKn];
__device__ float g_ksp [(size_t)Bn*Hn*NCH*DKn];
__device__ float g_kv  [(size_t)Bn*Hn*DKn*DKn];
__device__ float g_ks  [(size_t)Bn*Hn*DKn];

// bf16 split buffers (hi/lo)
__device__ __nv_bfloat16 g_xh [(size_t)Mn*Dn],   g_xl [(size_t)Mn*Dn];
__device__ __nv_bfloat16 g_ath[(size_t)Mn*Dn],   g_atl[(size_t)Mn*Dn];
__device__ __nv_bfloat16 g_x1h[(size_t)Mn*Dn],   g_x1l[(size_t)Mn*Dn];
__device__ __nv_bfloat16 g_hh [(size_t)Mn*DFFn], g_hl [(size_t)Mn*DFFn];
// weight splits
__device__ __nv_bfloat16 g_wqh[Dn*Dn], g_wql[Dn*Dn];
__device__ __nv_bfloat16 g_wkh[Dn*Dn], g_wkl[Dn*Dn];
__device__ __nv_bfloat16 g_wvh[Dn*Dn], g_wvl[Dn*Dn];
__device__ __nv_bfloat16 g_woh[Dn*Dn], g_wol[Dn*Dn];
__device__ __nv_bfloat16 g_w1h[DFFn*Dn], g_w1l[DFFn*Dn];
__device__ __nv_bfloat16 g_w2h[Dn*DFFn], g_w2l[Dn*DFFn];

// ------------------------- PTX helpers -------------------------------------
__device__ __forceinline__ uint32_t smem_u32(const void* p) {
    uint32_t a;
    asm("{ .reg .u64 t; cvta.to.shared.u64 t, %1; cvt.u32.u64 %0, t; }"
        : "=r"(a) : "l"(p));
    return a;
}

__device__ __forceinline__ void ldm4(uint32_t* r, uint32_t addr) {
    asm volatile("ldmatrix.sync.aligned.m8n8.x4.shared.b16 {%0,%1,%2,%3}, [%4];"
                 : "=r"(r[0]), "=r"(r[1]), "=r"(r[2]), "=r"(r[3]) : "r"(addr));
}

__device__ __forceinline__ void mma16816(float* c, const uint32_t* a,
                                         uint32_t b0, uint32_t b1) {
    asm volatile(
        "mma.sync.aligned.m16n8k16.row.col.f32.bf16.bf16.f32 "
        "{%0,%1,%2,%3}, {%4,%5,%6,%7}, {%8,%9}, {%0,%1,%2,%3};"
        : "+f"(c[0]), "+f"(c[1]), "+f"(c[2]), "+f"(c[3])
        : "r"(a[0]), "r"(a[1]), "r"(a[2]), "r"(a[3]), "r"(b0), "r"(b1));
}

// ================ HMMA split-bf16 GEMM: C = (Ah+Al)(Wh+Wl)^T + bias ========
// EPI: 0 = bias ; 1 = bias+res ; 2 = gelu(x)^2 -> Ch/Cl bf16
// CTA tile 128x256, K-chunk 32, 16 warps (4M x 4N), warp tile 32x64, 3 stages.
#define PITCH 80                   // bytes per smem row (32 bf16 + 8 pad)
#define ABYTES (128 * PITCH)       // 10240
#define WBYTES (256 * PITCH)       // 20480
#define STAGE (2 * ABYTES + 2 * WBYTES)  // 61440
#define NSTG 3
#define GSMEM (NSTG * STAGE)       // 184320

template<int EPI>
__global__ void __launch_bounds__(512) gemm_mma(
    const __nv_bfloat16* __restrict__ Ah, const __nv_bfloat16* __restrict__ Al,
    const __nv_bfloat16* __restrict__ Wh, const __nv_bfloat16* __restrict__ Wl,
    const float* __restrict__ bias, const float* __restrict__ res,
    float* __restrict__ C, __nv_bfloat16* __restrict__ Ch, __nv_bfloat16* __restrict__ Cl,
    int M, int N, int K)
{
    extern __shared__ char smem[];
    const uint32_t sb = smem_u32(smem);
    const int tid  = threadIdx.x;
    const int bn = blockIdx.x * 256, bm = blockIdx.y * 128;
    const int w = tid >> 5, lane = tid & 31;
    const int wm = w & 3, wn = w >> 2;          // warp tile rows wm*32, cols wn*64
    const int mrow = lane >> 3, mr = lane & 7;

    const __nv_bfloat16* Ahp = Ah + (size_t)bm * K;
    const __nv_bfloat16* Alp = Al + (size_t)bm * K;
    const __nv_bfloat16* Whp = Wh + (size_t)bn * K;
    const __nv_bfloat16* Wlp = Wl + (size_t)bn * K;
    const int nch = K >> 5;

    const int lr = tid >> 2, lc = tid & 3;      // loader row 0..127, col 0..3

    auto load_chunk = [&](int kt, int stg) {
        const uint32_t base = sb + stg * STAGE;
        const int off = kt * 32 + lc * 8;
        const uint32_t dA = base + lr * PITCH + lc * 16;
        asm volatile("cp.async.cg.shared.global [%0], [%1], 16;"
                     :: "r"(dA), "l"((const void*)(Ahp + (size_t)lr * K + off)));
        asm volatile("cp.async.cg.shared.global [%0], [%1], 16;"
                     :: "r"(dA + ABYTES), "l"((const void*)(Alp + (size_t)lr * K + off)));
        const uint32_t dW = base + 2 * ABYTES + lr * PITCH + lc * 16;
        asm volatile("cp.async.cg.shared.global [%0], [%1], 16;"
                     :: "r"(dW), "l"((const void*)(Whp + (size_t)lr * K + off)));
        asm volatile("cp.async.cg.shared.global [%0], [%1], 16;"
                     :: "r"(dW + 128 * PITCH), "l"((const void*)(Whp + (size_t)(lr + 128) * K + off)));
        asm volatile("cp.async.cg.shared.global [%0], [%1], 16;"
                     :: "r"(dW + WBYTES), "l"((const void*)(Wlp + (size_t)lr * K + off)));
        asm volatile("cp.async.cg.shared.global [%0], [%1], 16;"
                     :: "r"(dW + WBYTES + 128 * PITCH), "l"((const void*)(Wlp + (size_t)(lr + 128) * K + off)));
        asm volatile("cp.async.commit_group;");
    };

    float acc[2][8][4];
#pragma unroll
    for (int i = 0; i < 2; i++)
#pragma unroll
        for (int j = 0; j < 8; j++)
#pragma unroll
            for (int q = 0; q < 4; q++) acc[i][j][q] = 0.f;

    load_chunk(0, 0);
    load_chunk(1, 1);

    int cs = 0, ls = 2;
    for (int kt = 0; kt < nch; kt++) {
        if (kt == nch - 1) {
            asm volatile("cp.async.wait_group 0;" ::: "memory");
        } else {
            asm volatile("cp.async.wait_group 1;" ::: "memory");
        }
        __syncthreads();
        if (kt + 2 < nch) {
            load_chunk(kt + 2, ls);
            ls = (ls == 2) ? 0 : ls + 1;
        }

        const uint32_t base = sb + cs * STAGE;
        cs = (cs == 2) ? 0 : cs + 1;
#pragma unroll
        for (int ks = 0; ks < 2; ks++) {
            uint32_t ah[2][4], al[2][4];
#pragma unroll
            for (int i = 0; i < 2; i++) {
                const int rowA = wm * 32 + i * 16 + (mrow & 1) * 8 + mr;
                const uint32_t cA = ks * 32 + (mrow >> 1) * 16;
                ldm4(ah[i], base +          rowA * PITCH + cA);
                ldm4(al[i], base + ABYTES + rowA * PITCH + cA);
            }
#pragma unroll
            for (int jp = 0; jp < 4; jp++) {
                const int rowB = wn * 64 + jp * 16 + (mrow >> 1) * 8 + mr;
                const uint32_t cB = ks * 32 + (mrow & 1) * 16;
                uint32_t t0[4], t1[4];
                ldm4(t0, base + 2 * ABYTES +          rowB * PITCH + cB);
                ldm4(t1, base + 2 * ABYTES + WBYTES + rowB * PITCH + cB);
#pragma unroll
                for (int i = 0; i < 2; i++) {
                    mma16816(acc[i][2*jp],     ah[i], t0[0], t0[1]);
                    mma16816(acc[i][2*jp],     ah[i], t1[0], t1[1]);
                    mma16816(acc[i][2*jp],     al[i], t0[0], t0[1]);
                    mma16816(acc[i][2*jp + 1], ah[i], t0[2], t0[3]);
                    mma16816(acc[i][2*jp + 1], ah[i], t1[2], t1[3]);
                    mma16816(acc[i][2*jp + 1], al[i], t0[2], t0[3]);
                }
            }
        }
        __syncthreads();
    }

    // ------------------------------ epilogue --------------------------------
    const int tg = lane >> 2, ti = lane & 3;
#pragma unroll
    for (int i = 0; i < 2; i++) {
#pragma unroll
        for (int j = 0; j < 8; j++) {
            const int gr0 = bm + wm * 32 + i * 16 + tg;
            const int gc  = bn + wn * 64 + j * 8 + ti * 2;
            const float b0 = bias[gc], b1 = bias[gc + 1];
#pragma unroll
            for (int hfl = 0; hfl < 2; hfl++) {
                const int gr = gr0 + hfl * 8;
                float v0 = acc[i][j][2*hfl + 0] + b0;
                float v1 = acc[i][j][2*hfl + 1] + b1;
                const size_t off = (size_t)gr * N + gc;
                if (EPI == 1) {
                    float2 rv = *(const float2*)(res + off);
                    v0 += rv.x; v1 += rv.y;
                }
                if (EPI == 2) {
                    float g0 = 0.5f * v0 * (1.0f + erff(v0 * 0.7071067811865476f));
                    float g1 = 0.5f * v1 * (1.0f + erff(v1 * 0.7071067811865476f));
                    v0 = g0 * g0; v1 = g1 * g1;
                    __nv_bfloat16 h0 = __float2bfloat16_rn(v0);
                    __nv_bfloat16 h1 = __float2bfloat16_rn(v1);
                    __nv_bfloat162 hp; hp.x = h0; hp.y = h1;
                    __nv_bfloat16 l0 = __float2bfloat16_rn(v0 - __bfloat162float(h0));
                    __nv_bfloat16 l1 = __float2bfloat16_rn(v1 - __bfloat162float(h1));
                    __nv_bfloat162 lp; lp.x = l0; lp.y = l1;
                    *(__nv_bfloat162*)(Ch + off) = hp;
                    *(__nv_bfloat162*)(Cl + off) = lp;
                } else {
                    float2 ov; ov.x = v0; ov.y = v1;
                    *(float2*)(C + off) = ov;
                }
            }
        }
    }
}

// ------------------ fp32 -> bf16 hi/lo split (vectorized) ------------------
__global__ void cvt_split(const float* __restrict__ in,
                          __nv_bfloat16* __restrict__ hi,
                          __nv_bfloat16* __restrict__ lo, int n4)
{
    const int i = blockIdx.x * 256 + threadIdx.x;
    if (i >= n4) return;
    float4 v = ((const float4*)in)[i];
    __nv_bfloat16 h0 = __float2bfloat16_rn(v.x);
    __nv_bfloat16 h1 = __float2bfloat16_rn(v.y);
    __nv_bfloat16 h2 = __float2bfloat16_rn(v.z);
    __nv_bfloat16 h3 = __float2bfloat16_rn(v.w);
    __nv_bfloat162 hp0; hp0.x = h0; hp0.y = h1;
    __nv_bfloat162 hp1; hp1.x = h2; hp1.y = h3;
    __nv_bfloat16 l0 = __float2bfloat16_rn(v.x - __bfloat162float(h0));
    __nv_bfloat16 l1 = __float2bfloat16_rn(v.y - __bfloat162float(h1));
    __nv_bfloat16 l2 = __float2bfloat16_rn(v.z - __bfloat162float(h2));
    __nv_bfloat16 l3 = __float2bfloat16_rn(v.w - __bfloat162float(h3));
    __nv_bfloat162 lp0; lp0.x = l0; lp0.y = l1;
    __nv_bfloat162 lp1; lp1.x = l2; lp1.y = l3;
    ((__nv_bfloat162*)hi)[2 * i]     = hp0;
    ((__nv_bfloat162*)hi)[2 * i + 1] = hp1;
    ((__nv_bfloat162*)lo)[2 * i]     = lp0;
    ((__nv_bfloat162*)lo)[2 * i + 1] = lp1;
}

// ------------- conv(q,k,v) + elu+1(q,k) + partial KV / Ksum ---------------
// Register-carried causal taps: each thread walks 16 consecutive rows.
__global__ __launch_bounds__(256) void conv_pre(
    const float* __restrict__ qb, const float* __restrict__ kb,
    const float* __restrict__ vb,
    const float* __restrict__ qcw, const float* __restrict__ qcb,
    const float* __restrict__ kcw, const float* __restrict__ kcb,
    const float* __restrict__ vcw, const float* __restrict__ vcb)
{
    const int c = blockIdx.x, h = blockIdx.y, b = blockIdx.z;
    const int t  = threadIdx.x;
    const int ch = t & 63, rl = t >> 6;
    const int d0 = (t & 15) * 4, e0 = (t >> 4) * 4;

    __shared__ float k2s[64][68];
    __shared__ float v2s[64][68];

    const float qw0 = qcw[ch*3+0], qw1 = qcw[ch*3+1], qw2 = qcw[ch*3+2], qbv = qcb[ch];
    const float kw0 = kcw[ch*3+0], kw1 = kcw[ch*3+1], kw2 = kcw[ch*3+2], kbv = kcb[ch];
    const float vw0 = vcw[ch*3+0], vw1 = vcw[ch*3+1], vw2 = vcw[ch*3+2], vbv = vcb[ch];

    float acc[4][4];
#pragma unroll
    for (int i = 0; i < 4; i++)
#pragma unroll
        for (int j = 0; j < 4; j++) acc[i][j] = 0.f;
    float ksacc = 0.f;

    for (int sub = 0; sub < 4; sub++) {
        __syncthreads();   // protect smem against previous sub's readers
        const int s0 = c * CHROWS + sub * 64 + rl * 16;   // first row this thread
        const size_t base0 = ((size_t)(b * Sn + s0)) * Dn + h * DKn + ch;
        float qm1 = 0.f, qm2 = 0.f, km1 = 0.f, km2 = 0.f, vm1 = 0.f, vm2 = 0.f;
        if (s0 >= 1) { qm1 = qb[base0 - Dn];     km1 = kb[base0 - Dn];     vm1 = vb[base0 - Dn]; }
        if (s0 >= 2) { qm2 = qb[base0 - 2*Dn];   km2 = kb[base0 - 2*Dn];   vm2 = vb[base0 - 2*Dn]; }
#pragma unroll
        for (int i = 0; i < 16; i++) {
            const int r = rl * 16 + i;
            const size_t base = base0 + (size_t)i * Dn;

            float q0 = qb[base];
            float qc = qw0*qm2 + qw1*qm1 + qw2*q0 + qbv;
            g_q2[base] = qc > 0.f ? qc + 1.f : expf(qc);   // elu(x)+1
            qm2 = qm1; qm1 = q0;

            float k0 = kb[base];
            float kc = kw0*km2 + kw1*km1 + kw2*k0 + kbv;
            k2s[r][ch] = kc > 0.f ? kc + 1.f : expf(kc);
            km2 = km1; km1 = k0;

            float v0 = vb[base];
            v2s[r][ch] = vw0*vm2 + vw1*vm1 + vw2*v0 + vbv;
            vm2 = vm1; vm1 = v0;
        }
        __syncthreads();
        if (t < 64) {
#pragma unroll 8
            for (int r = 0; r < 64; r++) ksacc += k2s[r][t];
        }
#pragma unroll 4
        for (int r = 0; r < 64; r++) {
            float4 kd = *(const float4*)&k2s[r][d0];
            float4 ve = *(const float4*)&v2s[r][e0];
            float kda[4] = {kd.x, kd.y, kd.z, kd.w};
            float vea[4] = {ve.x, ve.y, ve.z, ve.w};
#pragma unroll
            for (int i = 0; i < 4; i++)
#pragma unroll
                for (int j = 0; j < 4; j++)
                    acc[i][j] = fmaf(kda[i], vea[j], acc[i][j]);
        }
    }

    const int bh = b * Hn + h;
    const size_t kvbase = ((size_t)bh * NCH + c) * (DKn * DKn);
#pragma unroll
    for (int i = 0; i < 4; i++)
#pragma unroll
        for (int j = 0; j < 4; j++)
            g_kvp[kvbase + (size_t)(d0 + i) * DKn + (e0 + j)] = acc[i][j];
    if (t < 64)
        g_ksp[((size_t)bh * NCH + c) * DKn + t] = ksacc;
}

// -------------- reduce partial KV / Ksum over chunks ----------------------
__global__ void kv_reduce()
{
    const int bh = blockIdx.x, t = threadIdx.x;
    for (int idx = t; idx < DKn * DKn; idx += 256) {
        float s = 0.f;
#pragma unroll
        for (int c = 0; c < NCH; c++)
            s += g_kvp[((size_t)bh * NCH + c) * (DKn * DKn) + idx];
        g_kv[(size_t)bh * (DKn * DKn) + idx] = s;
    }
    if (t < DKn) {
        float s = 0.f;
#pragma unroll
        for (int c = 0; c < NCH; c++)
            s += g_ksp[((size_t)bh * NCH + c) * DKn + t];
        g_ks[(size_t)bh * DKn + t] = s;
    }
}

// -------------- attn apply: Vn = (Q @ KV) / (Q . (Ksum+eps)) --------------
__global__ __launch_bounds__(256) void attn_apply()
{
    const int st = blockIdx.x, h = blockIdx.y, b = blockIdx.z;
    const int t = threadIdx.x;
    const int bh = b * Hn + h;
    __shared__ float qs [64][68];
    __shared__ float kvs[64][68];
    __shared__ float kss[64];

    for (int idx = t; idx < DKn * DKn; idx += 256) {
        const int r = idx >> 6, chn = idx & 63;
        qs [r][chn] = g_q2[((size_t)(b * Sn + st * 64 + r)) * Dn + h * DKn + chn];
        kvs[r][chn] = g_kv[(size_t)bh * (DKn * DKn) + idx];
    }
    if (t < DKn) kss[t] = g_ks[(size_t)bh * DKn + t] + EPSA;
    __syncthreads();

    const int sl = t >> 2;
    const int e0 = (t & 3) * 16;
    float z = 0.f;
    float o[16];
#pragma unroll
    for (int j = 0; j < 16; j++) o[j] = 0.f;

#pragma unroll 8
    for (int d = 0; d < 64; d++) {
        const float qd = qs[sl][d];
        z = fmaf(qd, kss[d], z);
        const float4* kp = (const float4*)&kvs[d][e0];
        float4 k0 = kp[0], k1 = kp[1], k2 = kp[2], k3 = kp[3];
        o[0]  = fmaf(qd, k0.x, o[0]);  o[1]  = fmaf(qd, k0.y, o[1]);
        o[2]  = fmaf(qd, k0.z, o[2]);  o[3]  = fmaf(qd, k0.w, o[3]);
        o[4]  = fmaf(qd, k1.x, o[4]);  o[5]  = fmaf(qd, k1.y, o[5]);
        o[6]  = fmaf(qd, k1.z, o[6]);  o[7]  = fmaf(qd, k1.w, o[7]);
        o[8]  = fmaf(qd, k2.x, o[8]);  o[9]  = fmaf(qd, k2.y, o[9]);
        o[10] = fmaf(qd, k2.z, o[10]); o[11] = fmaf(qd, k2.w, o[11]);
        o[12] = fmaf(qd, k3.x, o[12]); o[13] = fmaf(qd, k3.y, o[13]);
        o[14] = fmaf(qd, k3.z, o[14]); o[15] = fmaf(qd, k3.w, o[15]);
    }
    const float zi = 1.0f / z;
    const size_t ob = ((size_t)(b * Sn + st * 64 + sl)) * Dn + h * DKn + e0;
#pragma unroll
    for (int j = 0; j < 16; j += 2) {
        float v0 = zi * o[j], v1 = zi * o[j + 1];
        __nv_bfloat16 h0 = __float2bfloat16_rn(v0);
        __nv_bfloat16 h1 = __float2bfloat16_rn(v1);
        __nv_bfloat162 hp; hp.x = h0; hp.y = h1;
        __nv_bfloat16 l0 = __float2bfloat16_rn(v0 - __bfloat162float(h0));
        __nv_bfloat16 l1 = __float2bfloat16_rn(v1 - __bfloat162float(h1));
        __nv_bfloat162 lp; lp.x = l0; lp.y = l1;
        *(__nv_bfloat162*)(g_ath + ob + j) = hp;
        *(__nv_bfloat162*)(g_atl + ob + j) = lp;
    }
}

// -------------------------- LayerNorm (D=512) ------------------------------
template<bool SPLIT>
__global__ __launch_bounds__(256) void ln_kernel(
    const float* __restrict__ in, const float* __restrict__ gw,
    const float* __restrict__ bw, float* __restrict__ out,
    __nv_bfloat16* __restrict__ oh, __nv_bfloat16* __restrict__ ol)
{
    const int row = blockIdx.x, t = threadIdx.x;
    const float* rp = in + (size_t)row * Dn;
    const int c = t * 2;
    float2 v = *(const float2*)(rp + c);
    float s1 = v.x + v.y;
    float s2 = v.x * v.x + v.y * v.y;
#pragma unroll
    for (int o = 16; o > 0; o >>= 1) {
        s1 += __shfl_down_sync(0xffffffffu, s1, o);
        s2 += __shfl_down_sync(0xffffffffu, s2, o);
    }
    __shared__ float sh1[8], sh2[8];
    __shared__ float msh, rsh;
    if ((t & 31) == 0) { sh1[t >> 5] = s1; sh2[t >> 5] = s2; }
    __syncthreads();
    if (t == 0) {
        float a = 0.f, q = 0.f;
#pragma unroll
        for (int i = 0; i < 8; i++) { a += sh1[i]; q += sh2[i]; }
        const float m = a * (1.0f / Dn);
        const float var = q * (1.0f / Dn) - m * m;
        msh = m;
        rsh = rsqrtf(var + LNEPS);
    }
    __syncthreads();
    const float m = msh, r = rsh;
    float2 o2;
    o2.x = (v.x - m) * r * gw[c]     + bw[c];
    o2.y = (v.y - m) * r * gw[c + 1] + bw[c + 1];
    *(float2*)(out + (size_t)row * Dn + c) = o2;
    if (SPLIT) {
        __nv_bfloat16 h0 = __float2bfloat16_rn(o2.x);
        __nv_bfloat16 h1 = __float2bfloat16_rn(o2.y);
        __nv_bfloat162 hp; hp.x = h0; hp.y = h1;
        __nv_bfloat16 l0 = __float2bfloat16_rn(o2.x - __bfloat162float(h0));
        __nv_bfloat16 l1 = __float2bfloat16_rn(o2.y - __bfloat162float(h1));
        __nv_bfloat162 lp; lp.x = l0; lp.y = l1;
        *(__nv_bfloat162*)(oh + (size_t)row * Dn + c) = hp;
        *(__nv_bfloat162*)(ol + (size_t)row * Dn + c) = lp;
    }
}

// ------------------------------- launch ------------------------------------
extern "C" void kernel_launch(void* const* d_in, const int* in_sizes, int n_in,
                              void* d_out, int out_size)
{
    const float* x    = (const float*)d_in[0];
    const float* wq   = (const float*)d_in[1];
    const float* bq   = (const float*)d_in[2];
    const float* wk   = (const float*)d_in[3];
    const float* bk   = (const float*)d_in[4];
    const float* wv   = (const float*)d_in[5];
    const float* bv   = (const float*)d_in[6];
    const float* wo   = (const float*)d_in[7];
    const float* bo   = (const float*)d_in[8];
    const float* qcw  = (const float*)d_in[9];
    const float* qcb  = (const float*)d_in[10];
    const float* kcw  = (const float*)d_in[11];
    const float* kcb  = (const float*)d_in[12];
    const float* vcw  = (const float*)d_in[13];
    const float* vcb  = (const float*)d_in[14];
    const float* w1   = (const float*)d_in[15];
    const float* b1   = (const float*)d_in[16];
    const float* w2   = (const float*)d_in[17];
    const float* b2   = (const float*)d_in[18];
    const float* ln1g = (const float*)d_in[19];
    const float* ln1b = (const float*)d_in[20];
    const float* ln2g = (const float*)d_in[21];
    const float* ln2b = (const float*)d_in[22];
    float* out = (float*)d_out;

    float *pq, *pk, *pv, *py, *px1, *py2;
    cudaGetSymbolAddress((void**)&pq,  g_q);
    cudaGetSymbolAddress((void**)&pk,  g_k);
    cudaGetSymbolAddress((void**)&pv,  g_v);
    cudaGetSymbolAddress((void**)&py,  g_y);
    cudaGetSymbolAddress((void**)&px1, g_x1);
    cudaGetSymbolAddress((void**)&py2, g_y2);

    __nv_bfloat16 *pxh, *pxl, *path, *patl, *px1h, *px1l, *phh, *phl;
    __nv_bfloat16 *pwqh, *pwql, *pwkh, *pwkl, *pwvh, *pwvl, *pwoh, *pwol;
    __nv_bfloat16 *pw1h, *pw1l, *pw2h, *pw2l;
    cudaGetSymbolAddress((void**)&pxh,  g_xh);  cudaGetSymbolAddress((void**)&pxl,  g_xl);
    cudaGetSymbolAddress((void**)&path, g_ath); cudaGetSymbolAddress((void**)&patl, g_atl);
    cudaGetSymbolAddress((void**)&px1h, g_x1h); cudaGetSymbolAddress((void**)&px1l, g_x1l);
    cudaGetSymbolAddress((void**)&phh,  g_hh);  cudaGetSymbolAddress((void**)&phl,  g_hl);
    cudaGetSymbolAddress((void**)&pwqh, g_wqh); cudaGetSymbolAddress((void**)&pwql, g_wql);
    cudaGetSymbolAddress((void**)&pwkh, g_wkh); cudaGetSymbolAddress((void**)&pwkl, g_wkl);
    cudaGetSymbolAddress((void**)&pwvh, g_wvh); cudaGetSymbolAddress((void**)&pwvl, g_wvl);
    cudaGetSymbolAddress((void**)&pwoh, g_woh); cudaGetSymbolAddress((void**)&pwol, g_wol);
    cudaGetSymbolAddress((void**)&pw1h, g_w1h); cudaGetSymbolAddress((void**)&pw1l, g_w1l);
    cudaGetSymbolAddress((void**)&pw2h, g_w2h); cudaGetSymbolAddress((void**)&pw2l, g_w2l);

    cudaFuncSetAttribute(gemm_mma<0>, cudaFuncAttributeMaxDynamicSharedMemorySize, GSMEM);
    cudaFuncSetAttribute(gemm_mma<1>, cudaFuncAttributeMaxDynamicSharedMemorySize, GSMEM);
    cudaFuncSetAttribute(gemm_mma<2>, cudaFuncAttributeMaxDynamicSharedMemorySize, GSMEM);

    auto cvt = [](const float* p, __nv_bfloat16* h, __nv_bfloat16* l, size_t n) {
        int n4 = (int)(n / 4);
        cvt_split<<<(n4 + 255) / 256, 256>>>(p, h, l, n4);
    };

    // input + weight splits
    cvt(x,  pxh,  pxl,  (size_t)Mn * Dn);
    cvt(wq, pwqh, pwql, (size_t)Dn * Dn);
    cvt(wk, pwkh, pwkl, (size_t)Dn * Dn);
    cvt(wv, pwvh, pwvl, (size_t)Dn * Dn);
    cvt(wo, pwoh, pwol, (size_t)Dn * Dn);
    cvt(w1, pw1h, pw1l, (size_t)DFFn * Dn);
    cvt(w2, pw2h, pw2l, (size_t)Dn * DFFn);

    const dim3 gridD(Dn / 256, Mn / 128);    // (2, 256)
    const dim3 gridF(DFFn / 256, Mn / 128);  // (4, 256)

    // QKV projections (HMMA split-bf16)
    gemm_mma<0><<<gridD, 512, GSMEM>>>(pxh, pxl, pwqh, pwql, bq, nullptr,
                                       pq, nullptr, nullptr, Mn, Dn, Dn);
    gemm_mma<0><<<gridD, 512, GSMEM>>>(pxh, pxl, pwkh, pwkl, bk, nullptr,
                                       pk, nullptr, nullptr, Mn, Dn, Dn);
    gemm_mma<0><<<gridD, 512, GSMEM>>>(pxh, pxl, pwvh, pwvl, bv, nullptr,
                                       pv, nullptr, nullptr, Mn, Dn, Dn);

    // depthwise conv + elu+1 + partial KV/Ksum
    conv_pre<<<dim3(NCH, Hn, Bn), 256>>>(pq, pk, pv, qcw, qcb, kcw, kcb, vcw, vcb);
    kv_reduce<<<Bn * Hn, 256>>>();
    attn_apply<<<dim3(Sn / 64, Hn, Bn), 256>>>();

    // output projection + residual, then LN1 (LN1 also emits bf16 split)
    gemm_mma<1><<<gridD, 512, GSMEM>>>(path, patl, pwoh, pwol, bo, x,
                                       py, nullptr, nullptr, Mn, Dn, Dn);
    ln_kernel<true><<<Mn, 256>>>(py, ln1g, ln1b, px1, px1h, px1l);

    // FFN1: gelu^2, writes bf16 split directly; FFN2 consumes it (K=1024)
    gemm_mma<2><<<gridF, 512, GSMEM>>>(px1h, px1l, pw1h, pw1l, b1, nullptr,
                                       nullptr, phh, phl, Mn, DFFn, Dn);
    gemm_mma<1><<<gridD, 512, GSMEM>>>(phh, phl, pw2h, pw2l, b2, px1,
                                       py2, nullptr, nullptr, Mn, Dn, DFFn);
    ln_kernel<false><<<Mn, 256>>>(py2, ln2g, ln2b, out, nullptr, nullptr);
}

// round 5
// speedup vs baseline: 2.6437x; 1.2462x over previous
#include <cuda_runtime.h>
#include <cuda_fp16.h>
#include <cstdint>

#define Bn 8
#define Sn 4096
#define Dn 512
#define Hn 8
#define DKn 64
#define DFFn 1024
#define Mn (Bn*Sn)          // 32768 rows
#define NCH 16              // seq chunks for partial KV
#define CHROWS 256
#define EPSA 1e-6f
#define LNEPS 1e-5f

// ---------------- scratch (device globals; no allocation allowed) ----------
__device__ float g_q   [(size_t)Mn*Dn];
__device__ float g_k   [(size_t)Mn*Dn];
__device__ float g_v   [(size_t)Mn*Dn];
__device__ float g_q2  [(size_t)Mn*Dn];
__device__ float g_y   [(size_t)Mn*Dn];
__device__ float g_x1  [(size_t)Mn*Dn];
__device__ float g_y2  [(size_t)Mn*Dn];
__device__ float g_kvp [(size_t)Bn*Hn*NCH*DKn*DKn];
__device__ float g_ksp [(size_t)Bn*Hn*NCH*DKn];
__device__ float g_kv  [(size_t)Bn*Hn*DKn*DKn];
__device__ float g_ks  [(size_t)Bn*Hn*DKn];

// fp16 activation buffers (A operands, single precision-limb)
__device__ __half g_xh [(size_t)Mn*Dn];
__device__ __half g_ath[(size_t)Mn*Dn];
__device__ __half g_x1h[(size_t)Mn*Dn];
__device__ __half g_hh [(size_t)Mn*DFFn];
// fp16 weight splits (hi/lo)
__device__ __half g_wqh[Dn*Dn], g_wql[Dn*Dn];
__device__ __half g_wkh[Dn*Dn], g_wkl[Dn*Dn];
__device__ __half g_wvh[Dn*Dn], g_wvl[Dn*Dn];
__device__ __half g_woh[Dn*Dn], g_wol[Dn*Dn];
__device__ __half g_w1h[DFFn*Dn], g_w1l[DFFn*Dn];
__device__ __half g_w2h[Dn*DFFn], g_w2l[Dn*DFFn];

// ------------------------- PTX helpers -------------------------------------
__device__ __forceinline__ uint32_t smem_u32(const void* p) {
    uint32_t a;
    asm("{ .reg .u64 t; cvta.to.shared.u64 t, %1; cvt.u32.u64 %0, t; }"
        : "=r"(a) : "l"(p));
    return a;
}

__device__ __forceinline__ void ldm4(uint32_t* r, uint32_t addr) {
    asm volatile("ldmatrix.sync.aligned.m8n8.x4.shared.b16 {%0,%1,%2,%3}, [%4];"
                 : "=r"(r[0]), "=r"(r[1]), "=r"(r[2]), "=r"(r[3]) : "r"(addr));
}

__device__ __forceinline__ void mma16816(float* c, const uint32_t* a,
                                         uint32_t b0, uint32_t b1) {
    asm volatile(
        "mma.sync.aligned.m16n8k16.row.col.f32.f16.f16.f32 "
        "{%0,%1,%2,%3}, {%4,%5,%6,%7}, {%8,%9}, {%0,%1,%2,%3};"
        : "+f"(c[0]), "+f"(c[1]), "+f"(c[2]), "+f"(c[3])
        : "r"(a[0]), "r"(a[1]), "r"(a[2]), "r"(a[3]), "r"(b0), "r"(b1));
}

// ========== HMMA fp16 2-term GEMM: C = A(fp16) @ (Wh+Wl)^T + bias ==========
// EPI: 0 = bias ; 1 = bias+res ; 2 = gelu(x)^2 -> Ch fp16
// CTA tile 128x256, K-chunk 32, 16 warps (4M x 4N), warp tile 32x64, 3 stages.
#define PITCH 80                   // bytes per smem row (32 fp16 + 8 pad)
#define ABYTES (128 * PITCH)       // 10240
#define WBYTES (256 * PITCH)       // 20480
#define STAGE (ABYTES + 2 * WBYTES)  // 51200
#define NSTG 3
#define GSMEM (NSTG * STAGE)       // 153600

template<int EPI>
__global__ void __launch_bounds__(512) gemm_mma(
    const __half* __restrict__ A,
    const __half* __restrict__ Wh, const __half* __restrict__ Wl,
    const float* __restrict__ bias, const float* __restrict__ res,
    float* __restrict__ C, __half* __restrict__ Ch,
    int M, int N, int K)
{
    extern __shared__ char smem[];
    const uint32_t sb = smem_u32(smem);
    const int tid  = threadIdx.x;
    const int bn = blockIdx.x * 256, bm = blockIdx.y * 128;
    const int w = tid >> 5, lane = tid & 31;
    const int wm = w & 3, wn = w >> 2;          // warp tile rows wm*32, cols wn*64
    const int mrow = lane >> 3, mr = lane & 7;

    const __half* Ap  = A  + (size_t)bm * K;
    const __half* Whp = Wh + (size_t)bn * K;
    const __half* Wlp = Wl + (size_t)bn * K;
    const int nch = K >> 5;

    const int lr = tid >> 2, lc = tid & 3;      // loader row 0..127, col 0..3

    auto load_chunk = [&](int kt, int stg) {
        const uint32_t base = sb + stg * STAGE;
        const int off = kt * 32 + lc * 8;
        const uint32_t dA = base + lr * PITCH + lc * 16;
        asm volatile("cp.async.cg.shared.global [%0], [%1], 16;"
                     :: "r"(dA), "l"((const void*)(Ap + (size_t)lr * K + off)));
        const uint32_t dW = base + ABYTES + lr * PITCH + lc * 16;
        asm volatile("cp.async.cg.shared.global [%0], [%1], 16;"
                     :: "r"(dW), "l"((const void*)(Whp + (size_t)lr * K + off)));
        asm volatile("cp.async.cg.shared.global [%0], [%1], 16;"
                     :: "r"(dW + 128 * PITCH), "l"((const void*)(Whp + (size_t)(lr + 128) * K + off)));
        asm volatile("cp.async.cg.shared.global [%0], [%1], 16;"
                     :: "r"(dW + WBYTES), "l"((const void*)(Wlp + (size_t)lr * K + off)));
        asm volatile("cp.async.cg.shared.global [%0], [%1], 16;"
                     :: "r"(dW + WBYTES + 128 * PITCH), "l"((const void*)(Wlp + (size_t)(lr + 128) * K + off)));
        asm volatile("cp.async.commit_group;");
    };

    float acc[2][8][4];
#pragma unroll
    for (int i = 0; i < 2; i++)
#pragma unroll
        for (int j = 0; j < 8; j++)
#pragma unroll
            for (int q = 0; q < 4; q++) acc[i][j][q] = 0.f;

    load_chunk(0, 0);
    load_chunk(1, 1);

    int cs = 0, ls = 2;
    for (int kt = 0; kt < nch; kt++) {
        if (kt == nch - 1) {
            asm volatile("cp.async.wait_group 0;" ::: "memory");
        } else {
            asm volatile("cp.async.wait_group 1;" ::: "memory");
        }
        __syncthreads();   // single barrier per chunk: 3-stage ring keeps load
                           // target 2 ahead of compute, last read was kt-1.
        if (kt + 2 < nch) {
            load_chunk(kt + 2, ls);
            ls = (ls == 2) ? 0 : ls + 1;
        }

        const uint32_t base = sb + cs * STAGE;
        cs = (cs == 2) ? 0 : cs + 1;
#pragma unroll
        for (int ks = 0; ks < 2; ks++) {
            uint32_t ah[2][4];
#pragma unroll
            for (int i = 0; i < 2; i++) {
                const int rowA = wm * 32 + i * 16 + (mrow & 1) * 8 + mr;
                const uint32_t cA = ks * 32 + (mrow >> 1) * 16;
                ldm4(ah[i], base + rowA * PITCH + cA);
            }
#pragma unroll
            for (int jp = 0; jp < 4; jp++) {
                const int rowB = wn * 64 + jp * 16 + (mrow >> 1) * 8 + mr;
                const uint32_t cB = ks * 32 + (mrow & 1) * 16;
                uint32_t t0[4], t1[4];
                ldm4(t0, base + ABYTES +          rowB * PITCH + cB);
                ldm4(t1, base + ABYTES + WBYTES + rowB * PITCH + cB);
#pragma unroll
                for (int i = 0; i < 2; i++) {
                    mma16816(acc[i][2*jp],     ah[i], t0[0], t0[1]);
                    mma16816(acc[i][2*jp],     ah[i], t1[0], t1[1]);
                    mma16816(acc[i][2*jp + 1], ah[i], t0[2], t0[3]);
                    mma16816(acc[i][2*jp + 1], ah[i], t1[2], t1[3]);
                }
            }
        }
    }
    __syncthreads();

    // ------------------------------ epilogue --------------------------------
    const int tg = lane >> 2, ti = lane & 3;
#pragma unroll
    for (int i = 0; i < 2; i++) {
#pragma unroll
        for (int j = 0; j < 8; j++) {
            const int gr0 = bm + wm * 32 + i * 16 + tg;
            const int gc  = bn + wn * 64 + j * 8 + ti * 2;
            const float b0 = bias[gc], b1 = bias[gc + 1];
#pragma unroll
            for (int hfl = 0; hfl < 2; hfl++) {
                const int gr = gr0 + hfl * 8;
                float v0 = acc[i][j][2*hfl + 0] + b0;
                float v1 = acc[i][j][2*hfl + 1] + b1;
                const size_t off = (size_t)gr * N + gc;
                if (EPI == 1) {
                    float2 rv = *(const float2*)(res + off);
                    v0 += rv.x; v1 += rv.y;
                }
                if (EPI == 2) {
                    float g0 = 0.5f * v0 * (1.0f + erff(v0 * 0.7071067811865476f));
                    float g1 = 0.5f * v1 * (1.0f + erff(v1 * 0.7071067811865476f));
                    v0 = g0 * g0; v1 = g1 * g1;
                    *(__half2*)(Ch + off) = __floats2half2_rn(v0, v1);
                } else {
                    float2 ov; ov.x = v0; ov.y = v1;
                    *(float2*)(C + off) = ov;
                }
            }
        }
    }
}

// ------------------ fp32 -> fp16 convert (activations) ---------------------
__global__ void cvt_h(const float* __restrict__ in, __half* __restrict__ out, int n4)
{
    const int i = blockIdx.x * 256 + threadIdx.x;
    if (i >= n4) return;
    float4 v = ((const float4*)in)[i];
    ((__half2*)out)[2 * i]     = __floats2half2_rn(v.x, v.y);
    ((__half2*)out)[2 * i + 1] = __floats2half2_rn(v.z, v.w);
}

// ------------------ fp32 -> fp16 hi/lo split (weights) ---------------------
__global__ void cvt_split_h(const float* __restrict__ in,
                            __half* __restrict__ hi, __half* __restrict__ lo, int n4)
{
    const int i = blockIdx.x * 256 + threadIdx.x;
    if (i >= n4) return;
    float4 v = ((const float4*)in)[i];
    __half h0 = __float2half_rn(v.x), h1 = __float2half_rn(v.y);
    __half h2 = __float2half_rn(v.z), h3 = __float2half_rn(v.w);
    __half2 hp0; hp0.x = h0; hp0.y = h1;
    __half2 hp1; hp1.x = h2; hp1.y = h3;
    __half l0 = __float2half_rn(v.x - __half2float(h0));
    __half l1 = __float2half_rn(v.y - __half2float(h1));
    __half l2 = __float2half_rn(v.z - __half2float(h2));
    __half l3 = __float2half_rn(v.w - __half2float(h3));
    __half2 lp0; lp0.x = l0; lp0.y = l1;
    __half2 lp1; lp1.x = l2; lp1.y = l3;
    ((__half2*)hi)[2 * i]     = hp0;
    ((__half2*)hi)[2 * i + 1] = hp1;
    ((__half2*)lo)[2 * i]     = lp0;
    ((__half2*)lo)[2 * i + 1] = lp1;
}

// ------------- conv(q,k,v) + elu+1(q,k) + partial KV / Ksum ---------------
__global__ __launch_bounds__(256) void conv_pre(
    const float* __restrict__ qb, const float* __restrict__ kb,
    const float* __restrict__ vb,
    const float* __restrict__ qcw, const float* __restrict__ qcb,
    const float* __restrict__ kcw, const float* __restrict__ kcb,
    const float* __restrict__ vcw, const float* __restrict__ vcb)
{
    const int c = blockIdx.x, h = blockIdx.y, b = blockIdx.z;
    const int t  = threadIdx.x;
    const int ch = t & 63, rl = t >> 6;
    const int d0 = (t & 15) * 4, e0 = (t >> 4) * 4;

    __shared__ float k2s[64][68];
    __shared__ float v2s[64][68];

    const float qw0 = qcw[ch*3+0], qw1 = qcw[ch*3+1], qw2 = qcw[ch*3+2], qbv = qcb[ch];
    const float kw0 = kcw[ch*3+0], kw1 = kcw[ch*3+1], kw2 = kcw[ch*3+2], kbv = kcb[ch];
    const float vw0 = vcw[ch*3+0], vw1 = vcw[ch*3+1], vw2 = vcw[ch*3+2], vbv = vcb[ch];

    float acc[4][4];
#pragma unroll
    for (int i = 0; i < 4; i++)
#pragma unroll
        for (int j = 0; j < 4; j++) acc[i][j] = 0.f;
    float ksacc = 0.f;

    for (int sub = 0; sub < 4; sub++) {
        __syncthreads();
        const int s0 = c * CHROWS + sub * 64 + rl * 16;
        const size_t base0 = ((size_t)(b * Sn + s0)) * Dn + h * DKn + ch;
        float qm1 = 0.f, qm2 = 0.f, km1 = 0.f, km2 = 0.f, vm1 = 0.f, vm2 = 0.f;
        if (s0 >= 1) { qm1 = qb[base0 - Dn];   km1 = kb[base0 - Dn];   vm1 = vb[base0 - Dn]; }
        if (s0 >= 2) { qm2 = qb[base0 - 2*Dn]; km2 = kb[base0 - 2*Dn]; vm2 = vb[base0 - 2*Dn]; }
#pragma unroll
        for (int i = 0; i < 16; i++) {
            const int r = rl * 16 + i;
            const size_t base = base0 + (size_t)i * Dn;

            float q0 = qb[base];
            float qc = qw0*qm2 + qw1*qm1 + qw2*q0 + qbv;
            g_q2[base] = qc > 0.f ? qc + 1.f : expf(qc);
            qm2 = qm1; qm1 = q0;

            float k0 = kb[base];
            float kc = kw0*km2 + kw1*km1 + kw2*k0 + kbv;
            k2s[r][ch] = kc > 0.f ? kc + 1.f : expf(kc);
            km2 = km1; km1 = k0;

            float v0 = vb[base];
            v2s[r][ch] = vw0*vm2 + vw1*vm1 + vw2*v0 + vbv;
            vm2 = vm1; vm1 = v0;
        }
        __syncthreads();
        if (t < 64) {
#pragma unroll 8
            for (int r = 0; r < 64; r++) ksacc += k2s[r][t];
        }
#pragma unroll 4
        for (int r = 0; r < 64; r++) {
            float4 kd = *(const float4*)&k2s[r][d0];
            float4 ve = *(const float4*)&v2s[r][e0];
            float kda[4] = {kd.x, kd.y, kd.z, kd.w};
            float vea[4] = {ve.x, ve.y, ve.z, ve.w};
#pragma unroll
            for (int i = 0; i < 4; i++)
#pragma unroll
                for (int j = 0; j < 4; j++)
                    acc[i][j] = fmaf(kda[i], vea[j], acc[i][j]);
        }
    }

    const int bh = b * Hn + h;
    const size_t kvbase = ((size_t)bh * NCH + c) * (DKn * DKn);
#pragma unroll
    for (int i = 0; i < 4; i++)
#pragma unroll
        for (int j = 0; j < 4; j++)
            g_kvp[kvbase + (size_t)(d0 + i) * DKn + (e0 + j)] = acc[i][j];
    if (t < 64)
        g_ksp[((size_t)bh * NCH + c) * DKn + t] = ksacc;
}

// -------------- reduce partial KV / Ksum over chunks ----------------------
__global__ void kv_reduce()
{
    const int bh = blockIdx.x, t = threadIdx.x;
    for (int idx = t; idx < DKn * DKn; idx += 256) {
        float s = 0.f;
#pragma unroll
        for (int c = 0; c < NCH; c++)
            s += g_kvp[((size_t)bh * NCH + c) * (DKn * DKn) + idx];
        g_kv[(size_t)bh * (DKn * DKn) + idx] = s;
    }
    if (t < DKn) {
        float s = 0.f;
#pragma unroll
        for (int c = 0; c < NCH; c++)
            s += g_ksp[((size_t)bh * NCH + c) * DKn + t];
        g_ks[(size_t)bh * DKn + t] = s;
    }
}

// -------------- attn apply: Vn = (Q @ KV) / (Q . (Ksum+eps)) --------------
// writes fp16 attn directly (A operand of the O-projection GEMM)
__global__ __launch_bounds__(256) void attn_apply()
{
    const int st = blockIdx.x, h = blockIdx.y, b = blockIdx.z;
    const int t = threadIdx.x;
    const int bh = b * Hn + h;
    __shared__ float qs [64][68];
    __shared__ float kvs[64][68];
    __shared__ float kss[64];

    for (int idx = t; idx < DKn * DKn; idx += 256) {
        const int r = idx >> 6, chn = idx & 63;
        qs [r][chn] = g_q2[((size_t)(b * Sn + st * 64 + r)) * Dn + h * DKn + chn];
        kvs[r][chn] = g_kv[(size_t)bh * (DKn * DKn) + idx];
    }
    if (t < DKn) kss[t] = g_ks[(size_t)bh * DKn + t] + EPSA;
    __syncthreads();

    const int sl = t >> 2;
    const int e0 = (t & 3) * 16;
    float z = 0.f;
    float o[16];
#pragma unroll
    for (int j = 0; j < 16; j++) o[j] = 0.f;

#pragma unroll 8
    for (int d = 0; d < 64; d++) {
        const float qd = qs[sl][d];
        z = fmaf(qd, kss[d], z);
        const float4* kp = (const float4*)&kvs[d][e0];
        float4 k0 = kp[0], k1 = kp[1], k2 = kp[2], k3 = kp[3];
        o[0]  = fmaf(qd, k0.x, o[0]);  o[1]  = fmaf(qd, k0.y, o[1]);
        o[2]  = fmaf(qd, k0.z, o[2]);  o[3]  = fmaf(qd, k0.w, o[3]);
        o[4]  = fmaf(qd, k1.x, o[4]);  o[5]  = fmaf(qd, k1.y, o[5]);
        o[6]  = fmaf(qd, k1.z, o[6]);  o[7]  = fmaf(qd, k1.w, o[7]);
        o[8]  = fmaf(qd, k2.x, o[8]);  o[9]  = fmaf(qd, k2.y, o[9]);
        o[10] = fmaf(qd, k2.z, o[10]); o[11] = fmaf(qd, k2.w, o[11]);
        o[12] = fmaf(qd, k3.x, o[12]); o[13] = fmaf(qd, k3.y, o[13]);
        o[14] = fmaf(qd, k3.z, o[14]); o[15] = fmaf(qd, k3.w, o[15]);
    }
    const float zi = 1.0f / z;
    const size_t ob = ((size_t)(b * Sn + st * 64 + sl)) * Dn + h * DKn + e0;
#pragma unroll
    for (int j = 0; j < 16; j += 2)
        *(__half2*)(g_ath + ob + j) = __floats2half2_rn(zi * o[j], zi * o[j + 1]);
}

// -------------------------- LayerNorm (D=512) ------------------------------
template<bool SPLIT>
__global__ __launch_bounds__(256) void ln_kernel(
    const float* __restrict__ in, const float* __restrict__ gw,
    const float* __restrict__ bw, float* __restrict__ out,
    __half* __restrict__ oh)
{
    const int row = blockIdx.x, t = threadIdx.x;
    const float* rp = in + (size_t)row * Dn;
    const int c = t * 2;
    float2 v = *(const float2*)(rp + c);
    float s1 = v.x + v.y;
    float s2 = v.x * v.x + v.y * v.y;
#pragma unroll
    for (int o = 16; o > 0; o >>= 1) {
        s1 += __shfl_down_sync(0xffffffffu, s1, o);
        s2 += __shfl_down_sync(0xffffffffu, s2, o);
    }
    __shared__ float sh1[8], sh2[8];
    __shared__ float msh, rsh;
    if ((t & 31) == 0) { sh1[t >> 5] = s1; sh2[t >> 5] = s2; }
    __syncthreads();
    if (t == 0) {
        float a = 0.f, q = 0.f;
#pragma unroll
        for (int i = 0; i < 8; i++) { a += sh1[i]; q += sh2[i]; }
        const float m = a * (1.0f / Dn);
        const float var = q * (1.0f / Dn) - m * m;
        msh = m;
        rsh = rsqrtf(var + LNEPS);
    }
    __syncthreads();
    const float m = msh, r = rsh;
    float2 o2;
    o2.x = (v.x - m) * r * gw[c]     + bw[c];
    o2.y = (v.y - m) * r * gw[c + 1] + bw[c + 1];
    *(float2*)(out + (size_t)row * Dn + c) = o2;
    if (SPLIT)
        *(__half2*)(oh + (size_t)row * Dn + c) = __floats2half2_rn(o2.x, o2.y);
}

// ------------------------------- launch ------------------------------------
extern "C" void kernel_launch(void* const* d_in, const int* in_sizes, int n_in,
                              void* d_out, int out_size)
{
    const float* x    = (const float*)d_in[0];
    const float* wq   = (const float*)d_in[1];
    const float* bq   = (const float*)d_in[2];
    const float* wk   = (const float*)d_in[3];
    const float* bk   = (const float*)d_in[4];
    const float* wv   = (const float*)d_in[5];
    const float* bv   = (const float*)d_in[6];
    const float* wo   = (const float*)d_in[7];
    const float* bo   = (const float*)d_in[8];
    const float* qcw  = (const float*)d_in[9];
    const float* qcb  = (const float*)d_in[10];
    const float* kcw  = (const float*)d_in[11];
    const float* kcb  = (const float*)d_in[12];
    const float* vcw  = (const float*)d_in[13];
    const float* vcb  = (const float*)d_in[14];
    const float* w1   = (const float*)d_in[15];
    const float* b1   = (const float*)d_in[16];
    const float* w2   = (const float*)d_in[17];
    const float* b2   = (const float*)d_in[18];
    const float* ln1g = (const float*)d_in[19];
    const float* ln1b = (const float*)d_in[20];
    const float* ln2g = (const float*)d_in[21];
    const float* ln2b = (const float*)d_in[22];
    float* out = (float*)d_out;

    float *pq, *pk, *pv, *py, *px1, *py2;
    cudaGetSymbolAddress((void**)&pq,  g_q);
    cudaGetSymbolAddress((void**)&pk,  g_k);
    cudaGetSymbolAddress((void**)&pv,  g_v);
    cudaGetSymbolAddress((void**)&py,  g_y);
    cudaGetSymbolAddress((void**)&px1, g_x1);
    cudaGetSymbolAddress((void**)&py2, g_y2);

    __half *pxh, *path, *px1h, *phh;
    __half *pwqh, *pwql, *pwkh, *pwkl, *pwvh, *pwvl, *pwoh, *pwol;
    __half *pw1h, *pw1l, *pw2h, *pw2l;
    cudaGetSymbolAddress((void**)&pxh,  g_xh);
    cudaGetSymbolAddress((void**)&path, g_ath);
    cudaGetSymbolAddress((void**)&px1h, g_x1h);
    cudaGetSymbolAddress((void**)&phh,  g_hh);
    cudaGetSymbolAddress((void**)&pwqh, g_wqh); cudaGetSymbolAddress((void**)&pwql, g_wql);
    cudaGetSymbolAddress((void**)&pwkh, g_wkh); cudaGetSymbolAddress((void**)&pwkl, g_wkl);
    cudaGetSymbolAddress((void**)&pwvh, g_wvh); cudaGetSymbolAddress((void**)&pwvl, g_wvl);
    cudaGetSymbolAddress((void**)&pwoh, g_woh); cudaGetSymbolAddress((void**)&pwol, g_wol);
    cudaGetSymbolAddress((void**)&pw1h, g_w1h); cudaGetSymbolAddress((void**)&pw1l, g_w1l);
    cudaGetSymbolAddress((void**)&pw2h, g_w2h); cudaGetSymbolAddress((void**)&pw2l, g_w2l);

    cudaFuncSetAttribute(gemm_mma<0>, cudaFuncAttributeMaxDynamicSharedMemorySize, GSMEM);
    cudaFuncSetAttribute(gemm_mma<1>, cudaFuncAttributeMaxDynamicSharedMemorySize, GSMEM);
    cudaFuncSetAttribute(gemm_mma<2>, cudaFuncAttributeMaxDynamicSharedMemorySize, GSMEM);

    auto cvtw = [](const float* p, __half* h, __half* l, size_t n) {
        int n4 = (int)(n / 4);
        cvt_split_h<<<(n4 + 255) / 256, 256>>>(p, h, l, n4);
    };

    const dim3 gridD(Dn / 256, Mn / 128);    // (2, 256)
    const dim3 gridF(DFFn / 256, Mn / 128);  // (4, 256)

    // Launches 0-4 (so launch #5 — the one ncu profiles — is gemm Q)
    cvt_h<<<(Mn * Dn / 4 + 255) / 256, 256>>>(x, pxh, Mn * Dn / 4);
    cvtw(wq, pwqh, pwql, (size_t)Dn * Dn);
    cvtw(wk, pwkh, pwkl, (size_t)Dn * Dn);
    cvtw(wv, pwvh, pwvl, (size_t)Dn * Dn);
    cvtw(wo, pwoh, pwol, (size_t)Dn * Dn);

    // QKV projections (launch #5 = gemm Q)
    gemm_mma<0><<<gridD, 512, GSMEM>>>(pxh, pwqh, pwql, bq, nullptr,
                                       pq, nullptr, Mn, Dn, Dn);
    gemm_mma<0><<<gridD, 512, GSMEM>>>(pxh, pwkh, pwkl, bk, nullptr,
                                       pk, nullptr, Mn, Dn, Dn);
    gemm_mma<0><<<gridD, 512, GSMEM>>>(pxh, pwvh, pwvl, bv, nullptr,
                                       pv, nullptr, Mn, Dn, Dn);

    // FFN weight splits (independent; overlap with attention phase)
    cvtw(w1, pw1h, pw1l, (size_t)DFFn * Dn);
    cvtw(w2, pw2h, pw2l, (size_t)Dn * DFFn);

    // depthwise conv + elu+1 + partial KV/Ksum
    conv_pre<<<dim3(NCH, Hn, Bn), 256>>>(pq, pk, pv, qcw, qcb, kcw, kcb, vcw, vcb);
    kv_reduce<<<Bn * Hn, 256>>>();
    attn_apply<<<dim3(Sn / 64, Hn, Bn), 256>>>();

    // output projection + residual, then LN1 (LN1 also emits fp16)
    gemm_mma<1><<<gridD, 512, GSMEM>>>(path, pwoh, pwol, bo, x,
                                       py, nullptr, Mn, Dn, Dn);
    ln_kernel<true><<<Mn, 256>>>(py, ln1g, ln1b, px1, px1h);

    // FFN: gelu^2 -> fp16 h; FFN2 consumes it (K=1024)
    gemm_mma<2><<<gridF, 512, GSMEM>>>(px1h, pw1h, pw1l, b1, nullptr,
                                       nullptr, phh, Mn, DFFn, Dn);
    gemm_mma<1><<<gridD, 512, GSMEM>>>(phh, pw2h, pw2l, b2, px1,
                                       py2, nullptr, Mn, Dn, DFFn);
    ln_kernel<false><<<Mn, 256>>>(py2, ln2g, ln2b, out, nullptr);
}

// round 6
// speedup vs baseline: 3.5328x; 1.3363x over previous
#include <cuda_runtime.h>
#include <cuda_fp16.h>
#include <cstdint>

#define Bn 8
#define Sn 4096
#define Dn 512
#define Hn 8
#define DKn 64
#define DFFn 1024
#define Mn (Bn*Sn)          // 32768 rows
#define NCH 16              // seq chunks for partial KV
#define CHROWS 256
#define EPSA 1e-6f
#define LNEPS 1e-5f

// ---------------- scratch (device globals; no allocation allowed) ----------
__device__ float g_q   [(size_t)Mn*Dn];
__device__ float g_k   [(size_t)Mn*Dn];
__device__ float g_v   [(size_t)Mn*Dn];
__device__ float g_q2  [(size_t)Mn*Dn];
__device__ float g_y   [(size_t)Mn*Dn];
__device__ float g_x1  [(size_t)Mn*Dn];
__device__ float g_y2  [(size_t)Mn*Dn];
__device__ float g_kvp [(size_t)Bn*Hn*NCH*DKn*DKn];
__device__ float g_ksp [(size_t)Bn*Hn*NCH*DKn];
__device__ float g_kv  [(size_t)Bn*Hn*DKn*DKn];
__device__ float g_ks  [(size_t)Bn*Hn*DKn];

// fp16 buffers
__device__ __half g_xh [(size_t)Mn*Dn];
__device__ __half g_ath[(size_t)Mn*Dn];
__device__ __half g_x1h[(size_t)Mn*Dn];
__device__ __half g_hh [(size_t)Mn*DFFn];
__device__ __half g_wqh[Dn*Dn];
__device__ __half g_wkh[Dn*Dn];
__device__ __half g_wvh[Dn*Dn];
__device__ __half g_woh[Dn*Dn];
__device__ __half g_w1h[DFFn*Dn];
__device__ __half g_w2h[Dn*DFFn];

// ------------------------- PTX helpers -------------------------------------
__device__ __forceinline__ uint32_t smem_u32(const void* p) {
    uint32_t a;
    asm("{ .reg .u64 t; cvta.to.shared.u64 t, %1; cvt.u32.u64 %0, t; }"
        : "=r"(a) : "l"(p));
    return a;
}

__device__ __forceinline__ void ldm4(uint32_t* r, uint32_t addr) {
    asm volatile("ldmatrix.sync.aligned.m8n8.x4.shared.b16 {%0,%1,%2,%3}, [%4];"
                 : "=r"(r[0]), "=r"(r[1]), "=r"(r[2]), "=r"(r[3]) : "r"(addr));
}

__device__ __forceinline__ void mma16816(float* c, const uint32_t* a,
                                         uint32_t b0, uint32_t b1) {
    asm volatile(
        "mma.sync.aligned.m16n8k16.row.col.f32.f16.f16.f32 "
        "{%0,%1,%2,%3}, {%4,%5,%6,%7}, {%8,%9}, {%0,%1,%2,%3};"
        : "+f"(c[0]), "+f"(c[1]), "+f"(c[2]), "+f"(c[3])
        : "r"(a[0]), "r"(a[1]), "r"(a[2]), "r"(a[3]), "r"(b0), "r"(b1));
}

// ================= HMMA fp16 GEMM: C = A(fp16) @ W(fp16)^T + bias ==========
// EPI: 0 = bias ; 1 = bias+res ; 2 = gelu(x)^2 -> Ch fp16
// CTA tile 128x256, K-chunk 32, 16 warps (4M x 4N), warp tile 32x64, 3 stages.
#define PITCH 80                   // bytes per smem row (32 fp16 + 8 pad)
#define ABYTES (128 * PITCH)       // 10240
#define WBYTES (256 * PITCH)       // 20480
#define STAGE (ABYTES + WBYTES)    // 30720
#define NSTG 3
#define GSMEM (NSTG * STAGE)       // 92160

template<int EPI>
__global__ void __launch_bounds__(512) gemm_mma(
    const __half* __restrict__ A, const __half* __restrict__ W,
    const float* __restrict__ bias, const float* __restrict__ res,
    float* __restrict__ C, __half* __restrict__ Ch,
    int M, int N, int K)
{
    extern __shared__ char smem[];
    const uint32_t sb = smem_u32(smem);
    const int tid  = threadIdx.x;
    const int bn = blockIdx.x * 256, bm = blockIdx.y * 128;
    const int w = tid >> 5, lane = tid & 31;
    const int wm = w & 3, wn = w >> 2;          // warp tile rows wm*32, cols wn*64
    const int mrow = lane >> 3, mr = lane & 7;

    const __half* Ap = A + (size_t)bm * K;
    const __half* Wp = W + (size_t)bn * K;
    const int nch = K >> 5;

    const int lr = tid >> 2, lc = tid & 3;      // loader row 0..127, col 0..3

    auto load_chunk = [&](int kt, int stg) {
        const uint32_t base = sb + stg * STAGE;
        const int off = kt * 32 + lc * 8;
        const uint32_t dA = base + lr * PITCH + lc * 16;
        asm volatile("cp.async.cg.shared.global [%0], [%1], 16;"
                     :: "r"(dA), "l"((const void*)(Ap + (size_t)lr * K + off)));
        const uint32_t dW = base + ABYTES + lr * PITCH + lc * 16;
        asm volatile("cp.async.cg.shared.global [%0], [%1], 16;"
                     :: "r"(dW), "l"((const void*)(Wp + (size_t)lr * K + off)));
        asm volatile("cp.async.cg.shared.global [%0], [%1], 16;"
                     :: "r"(dW + 128 * PITCH), "l"((const void*)(Wp + (size_t)(lr + 128) * K + off)));
        asm volatile("cp.async.commit_group;");
    };

    float acc[2][8][4];
#pragma unroll
    for (int i = 0; i < 2; i++)
#pragma unroll
        for (int j = 0; j < 8; j++)
#pragma unroll
            for (int q = 0; q < 4; q++) acc[i][j][q] = 0.f;

    load_chunk(0, 0);
    load_chunk(1, 1);

    int cs = 0, ls = 2;
    for (int kt = 0; kt < nch; kt++) {
        if (kt == nch - 1) {
            asm volatile("cp.async.wait_group 0;" ::: "memory");
        } else {
            asm volatile("cp.async.wait_group 1;" ::: "memory");
        }
        __syncthreads();   // 3-stage ring: load target is 2 ahead of compute
        if (kt + 2 < nch) {
            load_chunk(kt + 2, ls);
            ls = (ls == 2) ? 0 : ls + 1;
        }

        const uint32_t base = sb + cs * STAGE;
        cs = (cs == 2) ? 0 : cs + 1;
#pragma unroll
        for (int ks = 0; ks < 2; ks++) {
            uint32_t ah[2][4];
#pragma unroll
            for (int i = 0; i < 2; i++) {
                const int rowA = wm * 32 + i * 16 + (mrow & 1) * 8 + mr;
                const uint32_t cA = ks * 32 + (mrow >> 1) * 16;
                ldm4(ah[i], base + rowA * PITCH + cA);
            }
#pragma unroll
            for (int jp = 0; jp < 4; jp++) {
                const int rowB = wn * 64 + jp * 16 + (mrow >> 1) * 8 + mr;
                const uint32_t cB = ks * 32 + (mrow & 1) * 16;
                uint32_t t0[4];
                ldm4(t0, base + ABYTES + rowB * PITCH + cB);
#pragma unroll
                for (int i = 0; i < 2; i++) {
                    mma16816(acc[i][2*jp],     ah[i], t0[0], t0[1]);
                    mma16816(acc[i][2*jp + 1], ah[i], t0[2], t0[3]);
                }
            }
        }
    }
    __syncthreads();

    // ------------------------------ epilogue --------------------------------
    const int tg = lane >> 2, ti = lane & 3;
#pragma unroll
    for (int i = 0; i < 2; i++) {
#pragma unroll
        for (int j = 0; j < 8; j++) {
            const int gr0 = bm + wm * 32 + i * 16 + tg;
            const int gc  = bn + wn * 64 + j * 8 + ti * 2;
            const float b0 = bias[gc], b1 = bias[gc + 1];
#pragma unroll
            for (int hfl = 0; hfl < 2; hfl++) {
                const int gr = gr0 + hfl * 8;
                float v0 = acc[i][j][2*hfl + 0] + b0;
                float v1 = acc[i][j][2*hfl + 1] + b1;
                const size_t off = (size_t)gr * N + gc;
                if (EPI == 1) {
                    float2 rv = *(const float2*)(res + off);
                    v0 += rv.x; v1 += rv.y;
                }
                if (EPI == 2) {
                    float g0 = 0.5f * v0 * (1.0f + erff(v0 * 0.7071067811865476f));
                    float g1 = 0.5f * v1 * (1.0f + erff(v1 * 0.7071067811865476f));
                    v0 = g0 * g0; v1 = g1 * g1;
                    *(__half2*)(Ch + off) = __floats2half2_rn(v0, v1);
                } else {
                    float2 ov; ov.x = v0; ov.y = v1;
                    *(float2*)(C + off) = ov;
                }
            }
        }
    }
}

// ------------------ fp32 -> fp16 convert ------------------------------------
__global__ void cvt_h(const float* __restrict__ in, __half* __restrict__ out, int n4)
{
    const int i = blockIdx.x * 256 + threadIdx.x;
    if (i >= n4) return;
    float4 v = ((const float4*)in)[i];
    ((__half2*)out)[2 * i]     = __floats2half2_rn(v.x, v.y);
    ((__half2*)out)[2 * i + 1] = __floats2half2_rn(v.z, v.w);
}

// ------------- conv(q,k,v) + elu+1(q,k) + partial KV / Ksum ---------------
__global__ __launch_bounds__(256) void conv_pre(
    const float* __restrict__ qb, const float* __restrict__ kb,
    const float* __restrict__ vb,
    const float* __restrict__ qcw, const float* __restrict__ qcb,
    const float* __restrict__ kcw, const float* __restrict__ kcb,
    const float* __restrict__ vcw, const float* __restrict__ vcb)
{
    const int c = blockIdx.x, h = blockIdx.y, b = blockIdx.z;
    const int t  = threadIdx.x;
    const int ch = t & 63, rl = t >> 6;
    const int d0 = (t & 15) * 4, e0 = (t >> 4) * 4;

    __shared__ float k2s[64][68];
    __shared__ float v2s[64][68];

    const float qw0 = qcw[ch*3+0], qw1 = qcw[ch*3+1], qw2 = qcw[ch*3+2], qbv = qcb[ch];
    const float kw0 = kcw[ch*3+0], kw1 = kcw[ch*3+1], kw2 = kcw[ch*3+2], kbv = kcb[ch];
    const float vw0 = vcw[ch*3+0], vw1 = vcw[ch*3+1], vw2 = vcw[ch*3+2], vbv = vcb[ch];

    float acc[4][4];
#pragma unroll
    for (int i = 0; i < 4; i++)
#pragma unroll
        for (int j = 0; j < 4; j++) acc[i][j] = 0.f;
    float ksacc = 0.f;

    for (int sub = 0; sub < 4; sub++) {
        __syncthreads();
        const int s0 = c * CHROWS + sub * 64 + rl * 16;
        const size_t base0 = ((size_t)(b * Sn + s0)) * Dn + h * DKn + ch;
        float qm1 = 0.f, qm2 = 0.f, km1 = 0.f, km2 = 0.f, vm1 = 0.f, vm2 = 0.f;
        if (s0 >= 1) { qm1 = qb[base0 - Dn];   km1 = kb[base0 - Dn];   vm1 = vb[base0 - Dn]; }
        if (s0 >= 2) { qm2 = qb[base0 - 2*Dn]; km2 = kb[base0 - 2*Dn]; vm2 = vb[base0 - 2*Dn]; }
#pragma unroll
        for (int i = 0; i < 16; i++) {
            const int r = rl * 16 + i;
            const size_t base = base0 + (size_t)i * Dn;

            float q0 = qb[base];
            float qc = qw0*qm2 + qw1*qm1 + qw2*q0 + qbv;
            g_q2[base] = qc > 0.f ? qc + 1.f : expf(qc);
            qm2 = qm1; qm1 = q0;

            float k0 = kb[base];
            float kc = kw0*km2 + kw1*km1 + kw2*k0 + kbv;
            k2s[r][ch] = kc > 0.f ? kc + 1.f : expf(kc);
            km2 = km1; km1 = k0;

            float v0 = vb[base];
            v2s[r][ch] = vw0*vm2 + vw1*vm1 + vw2*v0 + vbv;
            vm2 = vm1; vm1 = v0;
        }
        __syncthreads();
        if (t < 64) {
#pragma unroll 8
            for (int r = 0; r < 64; r++) ksacc += k2s[r][t];
        }
#pragma unroll 4
        for (int r = 0; r < 64; r++) {
            float4 kd = *(const float4*)&k2s[r][d0];
            float4 ve = *(const float4*)&v2s[r][e0];
            float kda[4] = {kd.x, kd.y, kd.z, kd.w};
            float vea[4] = {ve.x, ve.y, ve.z, ve.w};
#pragma unroll
            for (int i = 0; i < 4; i++)
#pragma unroll
                for (int j = 0; j < 4; j++)
                    acc[i][j] = fmaf(kda[i], vea[j], acc[i][j]);
        }
    }

    const int bh = b * Hn + h;
    const size_t kvbase = ((size_t)bh * NCH + c) * (DKn * DKn);
#pragma unroll
    for (int i = 0; i < 4; i++)
#pragma unroll
        for (int j = 0; j < 4; j++)
            g_kvp[kvbase + (size_t)(d0 + i) * DKn + (e0 + j)] = acc[i][j];
    if (t < 64)
        g_ksp[((size_t)bh * NCH + c) * DKn + t] = ksacc;
}

// -------------- reduce partial KV / Ksum over chunks ----------------------
__global__ void kv_reduce()
{
    const int bh = blockIdx.x, t = threadIdx.x;
    for (int idx = t; idx < DKn * DKn; idx += 256) {
        float s = 0.f;
#pragma unroll
        for (int c = 0; c < NCH; c++)
            s += g_kvp[((size_t)bh * NCH + c) * (DKn * DKn) + idx];
        g_kv[(size_t)bh * (DKn * DKn) + idx] = s;
    }
    if (t < DKn) {
        float s = 0.f;
#pragma unroll
        for (int c = 0; c < NCH; c++)
            s += g_ksp[((size_t)bh * NCH + c) * DKn + t];
        g_ks[(size_t)bh * DKn + t] = s;
    }
}

// -------------- attn apply: Vn = (Q @ KV) / (Q . (Ksum+eps)) --------------
__global__ __launch_bounds__(256) void attn_apply()
{
    const int st = blockIdx.x, h = blockIdx.y, b = blockIdx.z;
    const int t = threadIdx.x;
    const int bh = b * Hn + h;
    __shared__ float qs [64][68];
    __shared__ float kvs[64][68];
    __shared__ float kss[64];

    for (int idx = t; idx < DKn * DKn; idx += 256) {
        const int r = idx >> 6, chn = idx & 63;
        qs [r][chn] = g_q2[((size_t)(b * Sn + st * 64 + r)) * Dn + h * DKn + chn];
        kvs[r][chn] = g_kv[(size_t)bh * (DKn * DKn) + idx];
    }
    if (t < DKn) kss[t] = g_ks[(size_t)bh * DKn + t] + EPSA;
    __syncthreads();

    const int sl = t >> 2;
    const int e0 = (t & 3) * 16;
    float z = 0.f;
    float o[16];
#pragma unroll
    for (int j = 0; j < 16; j++) o[j] = 0.f;

#pragma unroll 8
    for (int d = 0; d < 64; d++) {
        const float qd = qs[sl][d];
        z = fmaf(qd, kss[d], z);
        const float4* kp = (const float4*)&kvs[d][e0];
        float4 k0 = kp[0], k1 = kp[1], k2 = kp[2], k3 = kp[3];
        o[0]  = fmaf(qd, k0.x, o[0]);  o[1]  = fmaf(qd, k0.y, o[1]);
        o[2]  = fmaf(qd, k0.z, o[2]);  o[3]  = fmaf(qd, k0.w, o[3]);
        o[4]  = fmaf(qd, k1.x, o[4]);  o[5]  = fmaf(qd, k1.y, o[5]);
        o[6]  = fmaf(qd, k1.z, o[6]);  o[7]  = fmaf(qd, k1.w, o[7]);
        o[8]  = fmaf(qd, k2.x, o[8]);  o[9]  = fmaf(qd, k2.y, o[9]);
        o[10] = fmaf(qd, k2.z, o[10]); o[11] = fmaf(qd, k2.w, o[11]);
        o[12] = fmaf(qd, k3.x, o[12]); o[13] = fmaf(qd, k3.y, o[13]);
        o[14] = fmaf(qd, k3.z, o[14]); o[15] = fmaf(qd, k3.w, o[15]);
    }
    const float zi = 1.0f / z;
    const size_t ob = ((size_t)(b * Sn + st * 64 + sl)) * Dn + h * DKn + e0;
#pragma unroll
    for (int j = 0; j < 16; j += 2)
        *(__half2*)(g_ath + ob + j) = __floats2half2_rn(zi * o[j], zi * o[j + 1]);
}

// -------------------------- LayerNorm (D=512) ------------------------------
template<bool SPLIT>
__global__ __launch_bounds__(256) void ln_kernel(
    const float* __restrict__ in, const float* __restrict__ gw,
    const float* __restrict__ bw, float* __restrict__ out,
    __half* __restrict__ oh)
{
    const int row = blockIdx.x, t = threadIdx.x;
    const float* rp = in + (size_t)row * Dn;
    const int c = t * 2;
    float2 v = *(const float2*)(rp + c);
    float s1 = v.x + v.y;
    float s2 = v.x * v.x + v.y * v.y;
#pragma unroll
    for (int o = 16; o > 0; o >>= 1) {
        s1 += __shfl_down_sync(0xffffffffu, s1, o);
        s2 += __shfl_down_sync(0xffffffffu, s2, o);
    }
    __shared__ float sh1[8], sh2[8];
    __shared__ float msh, rsh;
    if ((t & 31) == 0) { sh1[t >> 5] = s1; sh2[t >> 5] = s2; }
    __syncthreads();
    if (t == 0) {
        float a = 0.f, q = 0.f;
#pragma unroll
        for (int i = 0; i < 8; i++) { a += sh1[i]; q += sh2[i]; }
        const float m = a * (1.0f / Dn);
        const float var = q * (1.0f / Dn) - m * m;
        msh = m;
        rsh = rsqrtf(var + LNEPS);
    }
    __syncthreads();
    const float m = msh, r = rsh;
    float2 o2;
    o2.x = (v.x - m) * r * gw[c]     + bw[c];
    o2.y = (v.y - m) * r * gw[c + 1] + bw[c + 1];
    *(float2*)(out + (size_t)row * Dn + c) = o2;
    if (SPLIT)
        *(__half2*)(oh + (size_t)row * Dn + c) = __floats2half2_rn(o2.x, o2.y);
}

// ------------------------------- launch ------------------------------------
extern "C" void kernel_launch(void* const* d_in, const int* in_sizes, int n_in,
                              void* d_out, int out_size)
{
    const float* x    = (const float*)d_in[0];
    const float* wq   = (const float*)d_in[1];
    const float* bq   = (const float*)d_in[2];
    const float* wk   = (const float*)d_in[3];
    const float* bk   = (const float*)d_in[4];
    const float* wv   = (const float*)d_in[5];
    const float* bv   = (const float*)d_in[6];
    const float* wo   = (const float*)d_in[7];
    const float* bo   = (const float*)d_in[8];
    const float* qcw  = (const float*)d_in[9];
    const float* qcb  = (const float*)d_in[10];
    const float* kcw  = (const float*)d_in[11];
    const float* kcb  = (const float*)d_in[12];
    const float* vcw  = (const float*)d_in[13];
    const float* vcb  = (const float*)d_in[14];
    const float* w1   = (const float*)d_in[15];
    const float* b1   = (const float*)d_in[16];
    const float* w2   = (const float*)d_in[17];
    const float* b2   = (const float*)d_in[18];
    const float* ln1g = (const float*)d_in[19];
    const float* ln1b = (const float*)d_in[20];
    const float* ln2g = (const float*)d_in[21];
    const float* ln2b = (const float*)d_in[22];
    float* out = (float*)d_out;

    float *pq, *pk, *pv, *py, *px1, *py2;
    cudaGetSymbolAddress((void**)&pq,  g_q);
    cudaGetSymbolAddress((void**)&pk,  g_k);
    cudaGetSymbolAddress((void**)&pv,  g_v);
    cudaGetSymbolAddress((void**)&py,  g_y);
    cudaGetSymbolAddress((void**)&px1, g_x1);
    cudaGetSymbolAddress((void**)&py2, g_y2);

    __half *pxh, *path, *px1h, *phh;
    __half *pwqh, *pwkh, *pwvh, *pwoh, *pw1h, *pw2h;
    cudaGetSymbolAddress((void**)&pxh,  g_xh);
    cudaGetSymbolAddress((void**)&path, g_ath);
    cudaGetSymbolAddress((void**)&px1h, g_x1h);
    cudaGetSymbolAddress((void**)&phh,  g_hh);
    cudaGetSymbolAddress((void**)&pwqh, g_wqh);
    cudaGetSymbolAddress((void**)&pwkh, g_wkh);
    cudaGetSymbolAddress((void**)&pwvh, g_wvh);
    cudaGetSymbolAddress((void**)&pwoh, g_woh);
    cudaGetSymbolAddress((void**)&pw1h, g_w1h);
    cudaGetSymbolAddress((void**)&pw2h, g_w2h);

    cudaFuncSetAttribute(gemm_mma<0>, cudaFuncAttributeMaxDynamicSharedMemorySize, GSMEM);
    cudaFuncSetAttribute(gemm_mma<1>, cudaFuncAttributeMaxDynamicSharedMemorySize, GSMEM);
    cudaFuncSetAttribute(gemm_mma<2>, cudaFuncAttributeMaxDynamicSharedMemorySize, GSMEM);

    auto cvt = [](const float* p, __half* h, size_t n) {
        int n4 = (int)(n / 4);
        cvt_h<<<(n4 + 255) / 256, 256>>>(p, h, n4);
    };

    const dim3 gridD(Dn / 256, Mn / 128);    // (2, 256)
    const dim3 gridF(DFFn / 256, Mn / 128);  // (4, 256)

    // Launches 0-4 (launch #5, the one ncu profiles, is gemm Q)
    cvt(x,  pxh,  (size_t)Mn * Dn);
    cvt(wq, pwqh, (size_t)Dn * Dn);
    cvt(wk, pwkh, (size_t)Dn * Dn);
    cvt(wv, pwvh, (size_t)Dn * Dn);
    cvt(wo, pwoh, (size_t)Dn * Dn);

    // QKV projections (launch #5 = gemm Q)
    gemm_mma<0><<<gridD, 512, GSMEM>>>(pxh, pwqh, bq, nullptr, pq, nullptr, Mn, Dn, Dn);
    gemm_mma<0><<<gridD, 512, GSMEM>>>(pxh, pwkh, bk, nullptr, pk, nullptr, Mn, Dn, Dn);
    gemm_mma<0><<<gridD, 512, GSMEM>>>(pxh, pwvh, bv, nullptr, pv, nullptr, Mn, Dn, Dn);

    // FFN weight converts (independent; overlap with attention phase)
    cvt(w1, pw1h, (size_t)DFFn * Dn);
    cvt(w2, pw2h, (size_t)Dn * DFFn);

    // depthwise conv + elu+1 + partial KV/Ksum
    conv_pre<<<dim3(NCH, Hn, Bn), 256>>>(pq, pk, pv, qcw, qcb, kcw, kcb, vcw, vcb);
    kv_reduce<<<Bn * Hn, 256>>>();
    attn_apply<<<dim3(Sn / 64, Hn, Bn), 256>>>();

    // output projection + residual, then LN1 (LN1 also emits fp16)
    gemm_mma<1><<<gridD, 512, GSMEM>>>(path, pwoh, bo, x, py, nullptr, Mn, Dn, Dn);
    ln_kernel<true><<<Mn, 256>>>(py, ln1g, ln1b, px1, px1h);

    // FFN: gelu^2 -> fp16 h; FFN2 consumes it (K=1024)
    gemm_mma<2><<<gridF, 512, GSMEM>>>(px1h, pw1h, b1, nullptr, nullptr, phh, Mn, DFFn, Dn);
    gemm_mma<1><<<gridD, 512, GSMEM>>>(phh, pw2h, b2, px1, py2, nullptr, Mn, Dn, DFFn);
    ln_kernel<false><<<Mn, 256>>>(py2, ln2g, ln2b, out, nullptr);
}

// round 7
// speedup vs baseline: 4.1442x; 1.1731x over previous
#include <cuda_runtime.h>
#include <cuda_fp16.h>
#include <cstdint>

#define Bn 8
#define Sn 4096
#define Dn 512
#define Hn 8
#define DKn 64
#define DFFn 1024
#define Mn (Bn*Sn)          // 32768 rows
#define NCH 16              // seq chunks for partial KV
#define CHROWS 256
#define EPSA 1e-6f
#define LNEPS 1e-5f
#define D3 (3*Dn)           // 1536

// ---------------- scratch (device globals; no allocation allowed) ----------
__device__ float g_qkv [(size_t)Mn*D3];    // merged q|k|v projections
__device__ float g_q2  [(size_t)Mn*Dn];
__device__ float g_y   [(size_t)Mn*Dn];
__device__ float g_x1  [(size_t)Mn*Dn];
__device__ float g_y2  [(size_t)Mn*Dn];
__device__ float g_kvp [(size_t)Bn*Hn*NCH*DKn*DKn];
__device__ float g_ksp [(size_t)Bn*Hn*NCH*DKn];
__device__ float g_kv  [(size_t)Bn*Hn*DKn*DKn];
__device__ float g_ks  [(size_t)Bn*Hn*DKn];
__device__ float g_bqkv[D3];

// fp16 buffers
__device__ __half g_xh   [(size_t)Mn*Dn];
__device__ __half g_ath  [(size_t)Mn*Dn];
__device__ __half g_x1h  [(size_t)Mn*Dn];
__device__ __half g_hh   [(size_t)Mn*DFFn];
__device__ __half g_wqkvh[(size_t)D3*Dn];   // wq|wk|wv rows concatenated
__device__ __half g_woh  [Dn*Dn];
__device__ __half g_w1h  [DFFn*Dn];
__device__ __half g_w2h  [Dn*DFFn];

// ------------------------- PTX helpers -------------------------------------
__device__ __forceinline__ uint32_t smem_u32(const void* p) {
    uint32_t a;
    asm("{ .reg .u64 t; cvta.to.shared.u64 t, %1; cvt.u32.u64 %0, t; }"
        : "=r"(a) : "l"(p));
    return a;
}

__device__ __forceinline__ void ldm4(uint32_t* r, uint32_t addr) {
    asm volatile("ldmatrix.sync.aligned.m8n8.x4.shared.b16 {%0,%1,%2,%3}, [%4];"
                 : "=r"(r[0]), "=r"(r[1]), "=r"(r[2]), "=r"(r[3]) : "r"(addr));
}

__device__ __forceinline__ void mma16816(float* c, const uint32_t* a,
                                         uint32_t b0, uint32_t b1) {
    asm volatile(
        "mma.sync.aligned.m16n8k16.row.col.f32.f16.f16.f32 "
        "{%0,%1,%2,%3}, {%4,%5,%6,%7}, {%8,%9}, {%0,%1,%2,%3};"
        : "+f"(c[0]), "+f"(c[1]), "+f"(c[2]), "+f"(c[3])
        : "r"(a[0]), "r"(a[1]), "r"(a[2]), "r"(a[3]), "r"(b0), "r"(b1));
}

// ================= HMMA fp16 GEMM: C = A(fp16) @ W(fp16)^T + bias ==========
// EPI: 0 = bias ; 1 = bias+res ; 2 = gelu(x)^2 -> Ch fp16
// CTA tile 128x256, K-chunk 32, 16 warps (4M x 4N), warp tile 32x64, 3 stages.
#define PITCH 80
#define ABYTES (128 * PITCH)
#define WBYTES (256 * PITCH)
#define STAGE (ABYTES + WBYTES)
#define NSTG 3
#define GSMEM (NSTG * STAGE)

template<int EPI>
__global__ void __launch_bounds__(512) gemm_mma(
    const __half* __restrict__ A, const __half* __restrict__ W,
    const float* __restrict__ bias, const float* __restrict__ res,
    float* __restrict__ C, __half* __restrict__ Ch,
    int M, int N, int K)
{
    extern __shared__ char smem[];
    const uint32_t sb = smem_u32(smem);
    const int tid  = threadIdx.x;
    const int bn = blockIdx.x * 256, bm = blockIdx.y * 128;
    const int w = tid >> 5, lane = tid & 31;
    const int wm = w & 3, wn = w >> 2;
    const int mrow = lane >> 3, mr = lane & 7;

    const __half* Ap = A + (size_t)bm * K;
    const __half* Wp = W + (size_t)bn * K;
    const int nch = K >> 5;

    const int lr = tid >> 2, lc = tid & 3;

    auto load_chunk = [&](int kt, int stg) {
        const uint32_t base = sb + stg * STAGE;
        const int off = kt * 32 + lc * 8;
        const uint32_t dA = base + lr * PITCH + lc * 16;
        asm volatile("cp.async.cg.shared.global [%0], [%1], 16;"
                     :: "r"(dA), "l"((const void*)(Ap + (size_t)lr * K + off)));
        const uint32_t dW = base + ABYTES + lr * PITCH + lc * 16;
        asm volatile("cp.async.cg.shared.global [%0], [%1], 16;"
                     :: "r"(dW), "l"((const void*)(Wp + (size_t)lr * K + off)));
        asm volatile("cp.async.cg.shared.global [%0], [%1], 16;"
                     :: "r"(dW + 128 * PITCH), "l"((const void*)(Wp + (size_t)(lr + 128) * K + off)));
        asm volatile("cp.async.commit_group;");
    };

    float acc[2][8][4];
#pragma unroll
    for (int i = 0; i < 2; i++)
#pragma unroll
        for (int j = 0; j < 8; j++)
#pragma unroll
            for (int q = 0; q < 4; q++) acc[i][j][q] = 0.f;

    load_chunk(0, 0);
    load_chunk(1, 1);

    int cs = 0, ls = 2;
    for (int kt = 0; kt < nch; kt++) {
        if (kt == nch - 1) {
            asm volatile("cp.async.wait_group 0;" ::: "memory");
        } else {
            asm volatile("cp.async.wait_group 1;" ::: "memory");
        }
        __syncthreads();
        if (kt + 2 < nch) {
            load_chunk(kt + 2, ls);
            ls = (ls == 2) ? 0 : ls + 1;
        }

        const uint32_t base = sb + cs * STAGE;
        cs = (cs == 2) ? 0 : cs + 1;
#pragma unroll
        for (int ks = 0; ks < 2; ks++) {
            uint32_t ah[2][4];
#pragma unroll
            for (int i = 0; i < 2; i++) {
                const int rowA = wm * 32 + i * 16 + (mrow & 1) * 8 + mr;
                const uint32_t cA = ks * 32 + (mrow >> 1) * 16;
                ldm4(ah[i], base + rowA * PITCH + cA);
            }
#pragma unroll
            for (int jp = 0; jp < 4; jp++) {
                const int rowB = wn * 64 + jp * 16 + (mrow >> 1) * 8 + mr;
                const uint32_t cB = ks * 32 + (mrow & 1) * 16;
                uint32_t t0[4];
                ldm4(t0, base + ABYTES + rowB * PITCH + cB);
#pragma unroll
                for (int i = 0; i < 2; i++) {
                    mma16816(acc[i][2*jp],     ah[i], t0[0], t0[1]);
                    mma16816(acc[i][2*jp + 1], ah[i], t0[2], t0[3]);
                }
            }
        }
    }
    __syncthreads();

    // ------------------------------ epilogue --------------------------------
    const int tg = lane >> 2, ti = lane & 3;
#pragma unroll
    for (int i = 0; i < 2; i++) {
#pragma unroll
        for (int j = 0; j < 8; j++) {
            const int gr0 = bm + wm * 32 + i * 16 + tg;
            const int gc  = bn + wn * 64 + j * 8 + ti * 2;
            const float b0 = bias[gc], b1 = bias[gc + 1];
#pragma unroll
            for (int hfl = 0; hfl < 2; hfl++) {
                const int gr = gr0 + hfl * 8;
                float v0 = acc[i][j][2*hfl + 0] + b0;
                float v1 = acc[i][j][2*hfl + 1] + b1;
                const size_t off = (size_t)gr * N + gc;
                if (EPI == 1) {
                    float2 rv = *(const float2*)(res + off);
                    v0 += rv.x; v1 += rv.y;
                }
                if (EPI == 2) {
                    float g0 = 0.5f * v0 * (1.0f + erff(v0 * 0.7071067811865476f));
                    float g1 = 0.5f * v1 * (1.0f + erff(v1 * 0.7071067811865476f));
                    v0 = g0 * g0; v1 = g1 * g1;
                    *(__half2*)(Ch + off) = __floats2half2_rn(v0, v1);
                } else {
                    float2 ov; ov.x = v0; ov.y = v1;
                    *(float2*)(C + off) = ov;
                }
            }
        }
    }
}

// ------------------ fp32 -> fp16 convert ------------------------------------
__global__ void cvt_h(const float* __restrict__ in, __half* __restrict__ out, int n4)
{
    const int i = blockIdx.x * 256 + threadIdx.x;
    if (i >= n4) return;
    float4 v = ((const float4*)in)[i];
    ((__half2*)out)[2 * i]     = __floats2half2_rn(v.x, v.y);
    ((__half2*)out)[2 * i + 1] = __floats2half2_rn(v.z, v.w);
}

// ------------------ pack 3 bias vectors into one ----------------------------
__global__ void pack3(const float* __restrict__ a, const float* __restrict__ b,
                      const float* __restrict__ c, float* __restrict__ o)
{
    const int i = blockIdx.x * 256 + threadIdx.x;
    if (i < Dn)            o[i] = a[i];
    else if (i < 2 * Dn)   o[i] = b[i - Dn];
    else if (i < 3 * Dn)   o[i] = c[i - 2 * Dn];
}

// ------------- conv(q,k,v) + elu+1(q,k) + partial KV / Ksum ---------------
// Reads merged g_qkv [M, 1536]; register-carried causal taps.
__global__ __launch_bounds__(256) void conv_pre(
    const float* __restrict__ qkv,
    const float* __restrict__ qcw, const float* __restrict__ qcb,
    const float* __restrict__ kcw, const float* __restrict__ kcb,
    const float* __restrict__ vcw, const float* __restrict__ vcb)
{
    const int c = blockIdx.x, h = blockIdx.y, b = blockIdx.z;
    const int t  = threadIdx.x;
    const int ch = t & 63, rl = t >> 6;
    const int d0 = (t & 15) * 4, e0 = (t >> 4) * 4;

    __shared__ float k2s[64][68];
    __shared__ float v2s[64][68];

    const float qw0 = qcw[ch*3+0], qw1 = qcw[ch*3+1], qw2 = qcw[ch*3+2], qbv = qcb[ch];
    const float kw0 = kcw[ch*3+0], kw1 = kcw[ch*3+1], kw2 = kcw[ch*3+2], kbv = kcb[ch];
    const float vw0 = vcw[ch*3+0], vw1 = vcw[ch*3+1], vw2 = vcw[ch*3+2], vbv = vcb[ch];

    float acc[4][4];
#pragma unroll
    for (int i = 0; i < 4; i++)
#pragma unroll
        for (int j = 0; j < 4; j++) acc[i][j] = 0.f;
    float ksacc = 0.f;

    for (int sub = 0; sub < 4; sub++) {
        __syncthreads();
        const int s0 = c * CHROWS + sub * 64 + rl * 16;
        const size_t qb0 = ((size_t)(b * Sn + s0)) * D3 + h * DKn + ch;   // q col
        const size_t q2b0 = ((size_t)(b * Sn + s0)) * Dn + h * DKn + ch;  // out
        float qm1 = 0.f, qm2 = 0.f, km1 = 0.f, km2 = 0.f, vm1 = 0.f, vm2 = 0.f;
        if (s0 >= 1) {
            qm1 = qkv[qb0 - D3];
            km1 = qkv[qb0 - D3 + Dn];
            vm1 = qkv[qb0 - D3 + 2 * Dn];
        }
        if (s0 >= 2) {
            qm2 = qkv[qb0 - 2 * D3];
            km2 = qkv[qb0 - 2 * D3 + Dn];
            vm2 = qkv[qb0 - 2 * D3 + 2 * Dn];
        }
#pragma unroll
        for (int i = 0; i < 16; i++) {
            const int r = rl * 16 + i;
            const size_t base = qb0 + (size_t)i * D3;

            float q0 = qkv[base];
            float qc = qw0*qm2 + qw1*qm1 + qw2*q0 + qbv;
            g_q2[q2b0 + (size_t)i * Dn] = qc > 0.f ? qc + 1.f : expf(qc);
            qm2 = qm1; qm1 = q0;

            float k0 = qkv[base + Dn];
            float kc = kw0*km2 + kw1*km1 + kw2*k0 + kbv;
            k2s[r][ch] = kc > 0.f ? kc + 1.f : expf(kc);
            km2 = km1; km1 = k0;

            float v0 = qkv[base + 2 * Dn];
            v2s[r][ch] = vw0*vm2 + vw1*vm1 + vw2*v0 + vbv;
            vm2 = vm1; vm1 = v0;
        }
        __syncthreads();
        if (t < 64) {
#pragma unroll 8
            for (int r = 0; r < 64; r++) ksacc += k2s[r][t];
        }
#pragma unroll 4
        for (int r = 0; r < 64; r++) {
            float4 kd = *(const float4*)&k2s[r][d0];
            float4 ve = *(const float4*)&v2s[r][e0];
            float kda[4] = {kd.x, kd.y, kd.z, kd.w};
            float vea[4] = {ve.x, ve.y, ve.z, ve.w};
#pragma unroll
            for (int i = 0; i < 4; i++)
#pragma unroll
                for (int j = 0; j < 4; j++)
                    acc[i][j] = fmaf(kda[i], vea[j], acc[i][j]);
        }
    }

    const int bh = b * Hn + h;
    const size_t kvbase = ((size_t)bh * NCH + c) * (DKn * DKn);
#pragma unroll
    for (int i = 0; i < 4; i++)
#pragma unroll
        for (int j = 0; j < 4; j++)
            g_kvp[kvbase + (size_t)(d0 + i) * DKn + (e0 + j)] = acc[i][j];
    if (t < 64)
        g_ksp[((size_t)bh * NCH + c) * DKn + t] = ksacc;
}

// -------------- reduce partial KV / Ksum over chunks ----------------------
__global__ void kv_reduce()
{
    const int bh = blockIdx.x, t = threadIdx.x;
    for (int idx = t; idx < DKn * DKn; idx += 256) {
        float s = 0.f;
#pragma unroll
        for (int c = 0; c < NCH; c++)
            s += g_kvp[((size_t)bh * NCH + c) * (DKn * DKn) + idx];
        g_kv[(size_t)bh * (DKn * DKn) + idx] = s;
    }
    if (t < DKn) {
        float s = 0.f;
#pragma unroll
        for (int c = 0; c < NCH; c++)
            s += g_ksp[((size_t)bh * NCH + c) * DKn + t];
        g_ks[(size_t)bh * DKn + t] = s;
    }
}

// -------------- attn apply: Vn = (Q @ KV) / (Q . (Ksum+eps)) --------------
// 2-row blocking: thread = (row r & r+32, 8-col group); halves kv LDS.128.
__global__ __launch_bounds__(256) void attn_apply()
{
    const int st = blockIdx.x, h = blockIdx.y, b = blockIdx.z;
    const int t = threadIdx.x;
    const int bh = b * Hn + h;
    __shared__ float qs [64][68];
    __shared__ float kvs[64][68];
    __shared__ float kss[64];

    for (int idx = t; idx < DKn * DKn; idx += 256) {
        const int r = idx >> 6, chn = idx & 63;
        qs [r][chn] = g_q2[((size_t)(b * Sn + st * 64 + r)) * Dn + h * DKn + chn];
        kvs[r][chn] = g_kv[(size_t)bh * (DKn * DKn) + idx];
    }
    if (t < DKn) kss[t] = g_ks[(size_t)bh * DKn + t] + EPSA;
    __syncthreads();

    const int r  = t & 31;            // rows r and r+32
    const int e0 = (t >> 5) * 8;      // 8-col group
    float z0 = 0.f, z1 = 0.f;
    float o0[8], o1[8];
#pragma unroll
    for (int j = 0; j < 8; j++) { o0[j] = 0.f; o1[j] = 0.f; }

#pragma unroll 8
    for (int d = 0; d < 64; d++) {
        const float q0 = qs[r][d];
        const float q1 = qs[r + 32][d];
        z0 = fmaf(q0, kss[d], z0);
        z1 = fmaf(q1, kss[d], z1);
        const float4* kp = (const float4*)&kvs[d][e0];
        float4 ka = kp[0], kb = kp[1];
        o0[0] = fmaf(q0, ka.x, o0[0]); o0[1] = fmaf(q0, ka.y, o0[1]);
        o0[2] = fmaf(q0, ka.z, o0[2]); o0[3] = fmaf(q0, ka.w, o0[3]);
        o0[4] = fmaf(q0, kb.x, o0[4]); o0[5] = fmaf(q0, kb.y, o0[5]);
        o0[6] = fmaf(q0, kb.z, o0[6]); o0[7] = fmaf(q0, kb.w, o0[7]);
        o1[0] = fmaf(q1, ka.x, o1[0]); o1[1] = fmaf(q1, ka.y, o1[1]);
        o1[2] = fmaf(q1, ka.z, o1[2]); o1[3] = fmaf(q1, ka.w, o1[3]);
        o1[4] = fmaf(q1, kb.x, o1[4]); o1[5] = fmaf(q1, kb.y, o1[5]);
        o1[6] = fmaf(q1, kb.z, o1[6]); o1[7] = fmaf(q1, kb.w, o1[7]);
    }
    const float zi0 = 1.0f / z0;
    const float zi1 = 1.0f / z1;
    const size_t ob0 = ((size_t)(b * Sn + st * 64 + r)) * Dn + h * DKn + e0;
    const size_t ob1 = ob0 + (size_t)32 * Dn;
#pragma unroll
    for (int j = 0; j < 8; j += 2) {
        *(__half2*)(g_ath + ob0 + j) = __floats2half2_rn(zi0 * o0[j], zi0 * o0[j + 1]);
        *(__half2*)(g_ath + ob1 + j) = __floats2half2_rn(zi1 * o1[j], zi1 * o1[j + 1]);
    }
}

// -------------------- LayerNorm (D=512), warp per row ----------------------
template<bool SPLIT>
__global__ __launch_bounds__(256) void ln_kernel(
    const float* __restrict__ in, const float* __restrict__ gw,
    const float* __restrict__ bw, float* __restrict__ out,
    __half* __restrict__ oh)
{
    const int warp = threadIdx.x >> 5, lane = threadIdx.x & 31;
    const int row = blockIdx.x * 8 + warp;
    const float4* rp = (const float4*)(in + (size_t)row * Dn);

    float4 v[4];
    float s1 = 0.f, s2 = 0.f;
#pragma unroll
    for (int i = 0; i < 4; i++) {
        v[i] = rp[lane + i * 32];
        s1 += v[i].x + v[i].y + v[i].z + v[i].w;
        s2 += v[i].x * v[i].x + v[i].y * v[i].y + v[i].z * v[i].z + v[i].w * v[i].w;
    }
#pragma unroll
    for (int o = 16; o > 0; o >>= 1) {
        s1 += __shfl_xor_sync(0xffffffffu, s1, o);
        s2 += __shfl_xor_sync(0xffffffffu, s2, o);
    }
    const float m = s1 * (1.0f / Dn);
    const float rr = rsqrtf(s2 * (1.0f / Dn) - m * m + LNEPS);

    float4* op = (float4*)(out + (size_t)row * Dn);
    const float4* gp = (const float4*)gw;
    const float4* bp = (const float4*)bw;
#pragma unroll
    for (int i = 0; i < 4; i++) {
        const float4 g4 = gp[lane + i * 32];
        const float4 b4 = bp[lane + i * 32];
        float4 o4;
        o4.x = (v[i].x - m) * rr * g4.x + b4.x;
        o4.y = (v[i].y - m) * rr * g4.y + b4.y;
        o4.z = (v[i].z - m) * rr * g4.z + b4.z;
        o4.w = (v[i].w - m) * rr * g4.w + b4.w;
        op[lane + i * 32] = o4;
        if (SPLIT) {
            __half2* hp = (__half2*)(oh + (size_t)row * Dn) + 2 * (lane + i * 32);
            hp[0] = __floats2half2_rn(o4.x, o4.y);
            hp[1] = __floats2half2_rn(o4.z, o4.w);
        }
    }
}

// ------------------------------- launch ------------------------------------
extern "C" void kernel_launch(void* const* d_in, const int* in_sizes, int n_in,
                              void* d_out, int out_size)
{
    const float* x    = (const float*)d_in[0];
    const float* wq   = (const float*)d_in[1];
    const float* bq   = (const float*)d_in[2];
    const float* wk   = (const float*)d_in[3];
    const float* bk   = (const float*)d_in[4];
    const float* wv   = (const float*)d_in[5];
    const float* bv   = (const float*)d_in[6];
    const float* wo   = (const float*)d_in[7];
    const float* bo   = (const float*)d_in[8];
    const float* qcw  = (const float*)d_in[9];
    const float* qcb  = (const float*)d_in[10];
    const float* kcw  = (const float*)d_in[11];
    const float* kcb  = (const float*)d_in[12];
    const float* vcw  = (const float*)d_in[13];
    const float* vcb  = (const float*)d_in[14];
    const float* w1   = (const float*)d_in[15];
    const float* b1   = (const float*)d_in[16];
    const float* w2   = (const float*)d_in[17];
    const float* b2   = (const float*)d_in[18];
    const float* ln1g = (const float*)d_in[19];
    const float* ln1b = (const float*)d_in[20];
    const float* ln2g = (const float*)d_in[21];
    const float* ln2b = (const float*)d_in[22];
    float* out = (float*)d_out;

    float *pqkv, *py, *px1, *py2, *pbqkv;
    cudaGetSymbolAddress((void**)&pqkv, g_qkv);
    cudaGetSymbolAddress((void**)&py,   g_y);
    cudaGetSymbolAddress((void**)&px1,  g_x1);
    cudaGetSymbolAddress((void**)&py2,  g_y2);
    cudaGetSymbolAddress((void**)&pbqkv, g_bqkv);

    __half *pxh, *path, *px1h, *phh;
    __half *pwqkvh, *pwoh, *pw1h, *pw2h;
    cudaGetSymbolAddress((void**)&pxh,    g_xh);
    cudaGetSymbolAddress((void**)&path,   g_ath);
    cudaGetSymbolAddress((void**)&px1h,   g_x1h);
    cudaGetSymbolAddress((void**)&phh,    g_hh);
    cudaGetSymbolAddress((void**)&pwqkvh, g_wqkvh);
    cudaGetSymbolAddress((void**)&pwoh,   g_woh);
    cudaGetSymbolAddress((void**)&pw1h,   g_w1h);
    cudaGetSymbolAddress((void**)&pw2h,   g_w2h);

    cudaFuncSetAttribute(gemm_mma<0>, cudaFuncAttributeMaxDynamicSharedMemorySize, GSMEM);
    cudaFuncSetAttribute(gemm_mma<1>, cudaFuncAttributeMaxDynamicSharedMemorySize, GSMEM);
    cudaFuncSetAttribute(gemm_mma<2>, cudaFuncAttributeMaxDynamicSharedMemorySize, GSMEM);

    auto cvt = [](const float* p, __half* h, size_t n) {
        int n4 = (int)(n / 4);
        cvt_h<<<(n4 + 255) / 256, 256>>>(p, h, n4);
    };

    const dim3 gridQKV(D3 / 256, Mn / 128);   // (6, 256) = 1536 CTAs
    const dim3 gridD(Dn / 256, Mn / 128);     // (2, 256)
    const dim3 gridF(DFFn / 256, Mn / 128);   // (4, 256)

    // Launches 0-4 (launch #5, the ncu-profiled one, is the merged QKV GEMM)
    cvt(x,  pxh, (size_t)Mn * Dn);
    cvt(wq, pwqkvh,                 (size_t)Dn * Dn);
    cvt(wk, pwqkvh + (size_t)Dn * Dn,     (size_t)Dn * Dn);
    cvt(wv, pwqkvh + (size_t)2 * Dn * Dn, (size_t)Dn * Dn);
    pack3<<<(D3 + 255) / 256, 256>>>(bq, bk, bv, pbqkv);

    // merged QKV projection (launch #5)
    gemm_mma<0><<<gridQKV, 512, GSMEM>>>(pxh, pwqkvh, pbqkv, nullptr,
                                         pqkv, nullptr, Mn, D3, Dn);

    // remaining weight converts (overlap with attention phase)
    cvt(wo, pwoh, (size_t)Dn * Dn);
    cvt(w1, pw1h, (size_t)DFFn * Dn);
    cvt(w2, pw2h, (size_t)Dn * DFFn);

    // depthwise conv + elu+1 + partial KV/Ksum
    conv_pre<<<dim3(NCH, Hn, Bn), 256>>>(pqkv, qcw, qcb, kcw, kcb, vcw, vcb);
    kv_reduce<<<Bn * Hn, 256>>>();
    attn_apply<<<dim3(Sn / 64, Hn, Bn), 256>>>();

    // output projection + residual, then LN1 (LN1 also emits fp16)
    gemm_mma<1><<<gridD, 512, GSMEM>>>(path, pwoh, bo, x, py, nullptr, Mn, Dn, Dn);
    ln_kernel<true><<<Mn / 8, 256>>>(py, ln1g, ln1b, px1, px1h);

    // FFN: gelu^2 -> fp16 h; FFN2 consumes it (K=1024)
    gemm_mma<2><<<gridF, 512, GSMEM>>>(px1h, pw1h, b1, nullptr, nullptr, phh, Mn, DFFn, Dn);
    gemm_mma<1><<<gridD, 512, GSMEM>>>(phh, pw2h, b2, px1, py2, nullptr, Mn, Dn, DFFn);
    ln_kernel<false><<<Mn / 8, 256>>>(py2, ln2g, ln2b, out, nullptr);
}

// round 8
// speedup vs baseline: 4.2088x; 1.0156x over previous
#include <cuda_runtime.h>
#include <cuda_fp16.h>
#include <cstdint>

#define Bn 8
#define Sn 4096
#define Dn 512
#define Hn 8
#define DKn 64
#define DFFn 1024
#define Mn (Bn*Sn)          // 32768 rows
#define NCH 16              // seq chunks for partial KV
#define CHROWS 256
#define EPSA 1e-6f
#define LNEPS 1e-5f
#define D3 (3*Dn)           // 1536

// ---------------- scratch (device globals; no allocation allowed) ----------
__device__ float g_y   [(size_t)Mn*Dn];
__device__ float g_x1  [(size_t)Mn*Dn];
__device__ float g_y2  [(size_t)Mn*Dn];
__device__ float g_kvp [(size_t)Bn*Hn*NCH*DKn*DKn];
__device__ float g_ksp [(size_t)Bn*Hn*NCH*DKn];
__device__ float g_kv  [(size_t)Bn*Hn*DKn*DKn];
__device__ float g_ks  [(size_t)Bn*Hn*DKn];
__device__ float g_bqkv[D3];

// fp16 buffers
__device__ __half g_qkvh[(size_t)Mn*D3];    // merged q|k|v projections (fp16)
__device__ __half g_q2h [(size_t)Mn*Dn];    // elu(conv(q))+1 (fp16)
__device__ __half g_xh  [(size_t)Mn*Dn];
__device__ __half g_ath [(size_t)Mn*Dn];
__device__ __half g_x1h [(size_t)Mn*Dn];
__device__ __half g_hh  [(size_t)Mn*DFFn];
__device__ __half g_wqkvh[(size_t)D3*Dn];   // wq|wk|wv rows concatenated
__device__ __half g_woh [Dn*Dn];
__device__ __half g_w1h [DFFn*Dn];
__device__ __half g_w2h [Dn*DFFn];

// ------------------------- PTX helpers -------------------------------------
__device__ __forceinline__ uint32_t smem_u32(const void* p) {
    uint32_t a;
    asm("{ .reg .u64 t; cvta.to.shared.u64 t, %1; cvt.u32.u64 %0, t; }"
        : "=r"(a) : "l"(p));
    return a;
}

__device__ __forceinline__ void ldm4(uint32_t* r, uint32_t addr) {
    asm volatile("ldmatrix.sync.aligned.m8n8.x4.shared.b16 {%0,%1,%2,%3}, [%4];"
                 : "=r"(r[0]), "=r"(r[1]), "=r"(r[2]), "=r"(r[3]) : "r"(addr));
}

__device__ __forceinline__ void mma16816(float* c, const uint32_t* a,
                                         uint32_t b0, uint32_t b1) {
    asm volatile(
        "mma.sync.aligned.m16n8k16.row.col.f32.f16.f16.f32 "
        "{%0,%1,%2,%3}, {%4,%5,%6,%7}, {%8,%9}, {%0,%1,%2,%3};"
        : "+f"(c[0]), "+f"(c[1]), "+f"(c[2]), "+f"(c[3])
        : "r"(a[0]), "r"(a[1]), "r"(a[2]), "r"(a[3]), "r"(b0), "r"(b1));
}

// ================= HMMA fp16 GEMM: C = A(fp16) @ W(fp16)^T + bias ==========
// EPI: 0 = bias->fp32 ; 1 = bias+res->fp32 ; 2 = gelu(x)^2->fp16 ; 3 = bias->fp16
// CTA tile 128x256, K-chunk 32, 16 warps (4M x 4N), warp tile 32x64, 3 stages.
#define PITCH 80
#define ABYTES (128 * PITCH)
#define WBYTES (256 * PITCH)
#define STAGE (ABYTES + WBYTES)
#define NSTG 3
#define GSMEM (NSTG * STAGE)

template<int EPI>
__global__ void __launch_bounds__(512) gemm_mma(
    const __half* __restrict__ A, const __half* __restrict__ W,
    const float* __restrict__ bias, const float* __restrict__ res,
    float* __restrict__ C, __half* __restrict__ Ch,
    int M, int N, int K)
{
    extern __shared__ char smem[];
    const uint32_t sb = smem_u32(smem);
    const int tid  = threadIdx.x;
    const int bn = blockIdx.x * 256, bm = blockIdx.y * 128;
    const int w = tid >> 5, lane = tid & 31;
    const int wm = w & 3, wn = w >> 2;
    const int mrow = lane >> 3, mr = lane & 7;

    const __half* Ap = A + (size_t)bm * K;
    const __half* Wp = W + (size_t)bn * K;
    const int nch = K >> 5;

    const int lr = tid >> 2, lc = tid & 3;

    auto load_chunk = [&](int kt, int stg) {
        const uint32_t base = sb + stg * STAGE;
        const int off = kt * 32 + lc * 8;
        const uint32_t dA = base + lr * PITCH + lc * 16;
        asm volatile("cp.async.cg.shared.global [%0], [%1], 16;"
                     :: "r"(dA), "l"((const void*)(Ap + (size_t)lr * K + off)));
        const uint32_t dW = base + ABYTES + lr * PITCH + lc * 16;
        asm volatile("cp.async.cg.shared.global [%0], [%1], 16;"
                     :: "r"(dW), "l"((const void*)(Wp + (size_t)lr * K + off)));
        asm volatile("cp.async.cg.shared.global [%0], [%1], 16;"
                     :: "r"(dW + 128 * PITCH), "l"((const void*)(Wp + (size_t)(lr + 128) * K + off)));
        asm volatile("cp.async.commit_group;");
    };

    float acc[2][8][4];
#pragma unroll
    for (int i = 0; i < 2; i++)
#pragma unroll
        for (int j = 0; j < 8; j++)
#pragma unroll
            for (int q = 0; q < 4; q++) acc[i][j][q] = 0.f;

    load_chunk(0, 0);
    load_chunk(1, 1);

    int cs = 0, ls = 2;
    for (int kt = 0; kt < nch; kt++) {
        if (kt == nch - 1) {
            asm volatile("cp.async.wait_group 0;" ::: "memory");
        } else {
            asm volatile("cp.async.wait_group 1;" ::: "memory");
        }
        __syncthreads();
        if (kt + 2 < nch) {
            load_chunk(kt + 2, ls);
            ls = (ls == 2) ? 0 : ls + 1;
        }

        const uint32_t base = sb + cs * STAGE;
        cs = (cs == 2) ? 0 : cs + 1;
#pragma unroll
        for (int ks = 0; ks < 2; ks++) {
            uint32_t ah[2][4];
#pragma unroll
            for (int i = 0; i < 2; i++) {
                const int rowA = wm * 32 + i * 16 + (mrow & 1) * 8 + mr;
                const uint32_t cA = ks * 32 + (mrow >> 1) * 16;
                ldm4(ah[i], base + rowA * PITCH + cA);
            }
#pragma unroll
            for (int jp = 0; jp < 4; jp++) {
                const int rowB = wn * 64 + jp * 16 + (mrow >> 1) * 8 + mr;
                const uint32_t cB = ks * 32 + (mrow & 1) * 16;
                uint32_t t0[4];
                ldm4(t0, base + ABYTES + rowB * PITCH + cB);
#pragma unroll
                for (int i = 0; i < 2; i++) {
                    mma16816(acc[i][2*jp],     ah[i], t0[0], t0[1]);
                    mma16816(acc[i][2*jp + 1], ah[i], t0[2], t0[3]);
                }
            }
        }
    }
    __syncthreads();

    // ------------------------------ epilogue --------------------------------
    const int tg = lane >> 2, ti = lane & 3;
#pragma unroll
    for (int i = 0; i < 2; i++) {
#pragma unroll
        for (int j = 0; j < 8; j++) {
            const int gr0 = bm + wm * 32 + i * 16 + tg;
            const int gc  = bn + wn * 64 + j * 8 + ti * 2;
            const float b0 = bias[gc], b1 = bias[gc + 1];
#pragma unroll
            for (int hfl = 0; hfl < 2; hfl++) {
                const int gr = gr0 + hfl * 8;
                float v0 = acc[i][j][2*hfl + 0] + b0;
                float v1 = acc[i][j][2*hfl + 1] + b1;
                const size_t off = (size_t)gr * N + gc;
                if (EPI == 1) {
                    float2 rv = *(const float2*)(res + off);
                    v0 += rv.x; v1 += rv.y;
                }
                if (EPI == 2) {
                    float g0 = 0.5f * v0 * (1.0f + erff(v0 * 0.7071067811865476f));
                    float g1 = 0.5f * v1 * (1.0f + erff(v1 * 0.7071067811865476f));
                    v0 = g0 * g0; v1 = g1 * g1;
                }
                if (EPI == 2 || EPI == 3) {
                    *(__half2*)(Ch + off) = __floats2half2_rn(v0, v1);
                } else {
                    float2 ov; ov.x = v0; ov.y = v1;
                    *(float2*)(C + off) = ov;
                }
            }
        }
    }
}

// ------------------ fp32 -> fp16 convert ------------------------------------
__global__ void cvt_h(const float* __restrict__ in, __half* __restrict__ out, int n4)
{
    const int i = blockIdx.x * 256 + threadIdx.x;
    if (i >= n4) return;
    float4 v = ((const float4*)in)[i];
    ((__half2*)out)[2 * i]     = __floats2half2_rn(v.x, v.y);
    ((__half2*)out)[2 * i + 1] = __floats2half2_rn(v.z, v.w);
}

// ------------------ pack 3 bias vectors into one ----------------------------
__global__ void pack3(const float* __restrict__ a, const float* __restrict__ b,
                      const float* __restrict__ c, float* __restrict__ o)
{
    const int i = blockIdx.x * 256 + threadIdx.x;
    if (i < Dn)            o[i] = a[i];
    else if (i < 2 * Dn)   o[i] = b[i - Dn];
    else if (i < 3 * Dn)   o[i] = c[i - 2 * Dn];
}

// ------------- conv(q,k,v) + elu+1(q,k) + partial KV / Ksum ---------------
// Reads merged fp16 g_qkvh [M, 1536]; register-carried causal taps.
__global__ __launch_bounds__(256) void conv_pre(
    const __half* __restrict__ qkv,
    const float* __restrict__ qcw, const float* __restrict__ qcb,
    const float* __restrict__ kcw, const float* __restrict__ kcb,
    const float* __restrict__ vcw, const float* __restrict__ vcb)
{
    const int c = blockIdx.x, h = blockIdx.y, b = blockIdx.z;
    const int t  = threadIdx.x;
    const int ch = t & 63, rl = t >> 6;
    const int d0 = (t & 15) * 4, e0 = (t >> 4) * 4;

    __shared__ float k2s[64][68];
    __shared__ float v2s[64][68];

    const float qw0 = qcw[ch*3+0], qw1 = qcw[ch*3+1], qw2 = qcw[ch*3+2], qbv = qcb[ch];
    const float kw0 = kcw[ch*3+0], kw1 = kcw[ch*3+1], kw2 = kcw[ch*3+2], kbv = kcb[ch];
    const float vw0 = vcw[ch*3+0], vw1 = vcw[ch*3+1], vw2 = vcw[ch*3+2], vbv = vcb[ch];

    float acc[4][4];
#pragma unroll
    for (int i = 0; i < 4; i++)
#pragma unroll
        for (int j = 0; j < 4; j++) acc[i][j] = 0.f;
    float ksacc = 0.f;

    for (int sub = 0; sub < 4; sub++) {
        __syncthreads();
        const int s0 = c * CHROWS + sub * 64 + rl * 16;
        const size_t qb0 = ((size_t)(b * Sn + s0)) * D3 + h * DKn + ch;
        const size_t q2b0 = ((size_t)(b * Sn + s0)) * Dn + h * DKn + ch;
        float qm1 = 0.f, qm2 = 0.f, km1 = 0.f, km2 = 0.f, vm1 = 0.f, vm2 = 0.f;
        if (s0 >= 1) {
            qm1 = __half2float(qkv[qb0 - D3]);
            km1 = __half2float(qkv[qb0 - D3 + Dn]);
            vm1 = __half2float(qkv[qb0 - D3 + 2 * Dn]);
        }
        if (s0 >= 2) {
            qm2 = __half2float(qkv[qb0 - 2 * D3]);
            km2 = __half2float(qkv[qb0 - 2 * D3 + Dn]);
            vm2 = __half2float(qkv[qb0 - 2 * D3 + 2 * Dn]);
        }
#pragma unroll
        for (int i = 0; i < 16; i++) {
            const int r = rl * 16 + i;
            const size_t base = qb0 + (size_t)i * D3;

            float q0 = __half2float(qkv[base]);
            float qc = qw0*qm2 + qw1*qm1 + qw2*q0 + qbv;
            g_q2h[q2b0 + (size_t)i * Dn] =
                __float2half_rn(qc > 0.f ? qc + 1.f : expf(qc));
            qm2 = qm1; qm1 = q0;

            float k0 = __half2float(qkv[base + Dn]);
            float kc = kw0*km2 + kw1*km1 + kw2*k0 + kbv;
            k2s[r][ch] = kc > 0.f ? kc + 1.f : expf(kc);
            km2 = km1; km1 = k0;

            float v0 = __half2float(qkv[base + 2 * Dn]);
            v2s[r][ch] = vw0*vm2 + vw1*vm1 + vw2*v0 + vbv;
            vm2 = vm1; vm1 = v0;
        }
        __syncthreads();
        if (t < 64) {
#pragma unroll 8
            for (int r = 0; r < 64; r++) ksacc += k2s[r][t];
        }
#pragma unroll 4
        for (int r = 0; r < 64; r++) {
            float4 kd = *(const float4*)&k2s[r][d0];
            float4 ve = *(const float4*)&v2s[r][e0];
            float kda[4] = {kd.x, kd.y, kd.z, kd.w};
            float vea[4] = {ve.x, ve.y, ve.z, ve.w};
#pragma unroll
            for (int i = 0; i < 4; i++)
#pragma unroll
                for (int j = 0; j < 4; j++)
                    acc[i][j] = fmaf(kda[i], vea[j], acc[i][j]);
        }
    }

    const int bh = b * Hn + h;
    const size_t kvbase = ((size_t)bh * NCH + c) * (DKn * DKn);
#pragma unroll
    for (int i = 0; i < 4; i++)
#pragma unroll
        for (int j = 0; j < 4; j++)
            g_kvp[kvbase + (size_t)(d0 + i) * DKn + (e0 + j)] = acc[i][j];
    if (t < 64)
        g_ksp[((size_t)bh * NCH + c) * DKn + t] = ksacc;
}

// -------------- reduce partial KV / Ksum over chunks ----------------------
__global__ void kv_reduce()
{
    const int bh = blockIdx.x, t = threadIdx.x;
    for (int idx = t; idx < DKn * DKn; idx += 256) {
        float s = 0.f;
#pragma unroll
        for (int c = 0; c < NCH; c++)
            s += g_kvp[((size_t)bh * NCH + c) * (DKn * DKn) + idx];
        g_kv[(size_t)bh * (DKn * DKn) + idx] = s;
    }
    if (t < DKn) {
        float s = 0.f;
#pragma unroll
        for (int c = 0; c < NCH; c++)
            s += g_ksp[((size_t)bh * NCH + c) * DKn + t];
        g_ks[(size_t)bh * DKn + t] = s;
    }
}

// -------------- attn apply: Vn = (Q @ KV) / (Q . (Ksum+eps)) --------------
// 2-row blocking; fp16 q input, fp16 attn output.
__global__ __launch_bounds__(256) void attn_apply()
{
    const int st = blockIdx.x, h = blockIdx.y, b = blockIdx.z;
    const int t = threadIdx.x;
    const int bh = b * Hn + h;
    __shared__ float qs [64][68];
    __shared__ float kvs[64][68];
    __shared__ float kss[64];

    for (int idx = t; idx < DKn * DKn; idx += 256) {
        const int r = idx >> 6, chn = idx & 63;
        qs [r][chn] = __half2float(
            g_q2h[((size_t)(b * Sn + st * 64 + r)) * Dn + h * DKn + chn]);
        kvs[r][chn] = g_kv[(size_t)bh * (DKn * DKn) + idx];
    }
    if (t < DKn) kss[t] = g_ks[(size_t)bh * DKn + t] + EPSA;
    __syncthreads();

    const int r  = t & 31;
    const int e0 = (t >> 5) * 8;
    float z0 = 0.f, z1 = 0.f;
    float o0[8], o1[8];
#pragma unroll
    for (int j = 0; j < 8; j++) { o0[j] = 0.f; o1[j] = 0.f; }

#pragma unroll 8
    for (int d = 0; d < 64; d++) {
        const float q0 = qs[r][d];
        const float q1 = qs[r + 32][d];
        z0 = fmaf(q0, kss[d], z0);
        z1 = fmaf(q1, kss[d], z1);
        const float4* kp = (const float4*)&kvs[d][e0];
        float4 ka = kp[0], kb = kp[1];
        o0[0] = fmaf(q0, ka.x, o0[0]); o0[1] = fmaf(q0, ka.y, o0[1]);
        o0[2] = fmaf(q0, ka.z, o0[2]); o0[3] = fmaf(q0, ka.w, o0[3]);
        o0[4] = fmaf(q0, kb.x, o0[4]); o0[5] = fmaf(q0, kb.y, o0[5]);
        o0[6] = fmaf(q0, kb.z, o0[6]); o0[7] = fmaf(q0, kb.w, o0[7]);
        o1[0] = fmaf(q1, ka.x, o1[0]); o1[1] = fmaf(q1, ka.y, o1[1]);
        o1[2] = fmaf(q1, ka.z, o1[2]); o1[3] = fmaf(q1, ka.w, o1[3]);
        o1[4] = fmaf(q1, kb.x, o1[4]); o1[5] = fmaf(q1, kb.y, o1[5]);
        o1[6] = fmaf(q1, kb.z, o1[6]); o1[7] = fmaf(q1, kb.w, o1[7]);
    }
    const float zi0 = 1.0f / z0;
    const float zi1 = 1.0f / z1;
    const size_t ob0 = ((size_t)(b * Sn + st * 64 + r)) * Dn + h * DKn + e0;
    const size_t ob1 = ob0 + (size_t)32 * Dn;
#pragma unroll
    for (int j = 0; j < 8; j += 2) {
        *(__half2*)(g_ath + ob0 + j) = __floats2half2_rn(zi0 * o0[j], zi0 * o0[j + 1]);
        *(__half2*)(g_ath + ob1 + j) = __floats2half2_rn(zi1 * o1[j], zi1 * o1[j + 1]);
    }
}

// -------------------- LayerNorm (D=512), warp per row ----------------------
template<bool SPLIT>
__global__ __launch_bounds__(256) void ln_kernel(
    const float* __restrict__ in, const float* __restrict__ gw,
    const float* __restrict__ bw, float* __restrict__ out,
    __half* __restrict__ oh)
{
    const int warp = threadIdx.x >> 5, lane = threadIdx.x & 31;
    const int row = blockIdx.x * 8 + warp;
    const float4* rp = (const float4*)(in + (size_t)row * Dn);

    float4 v[4];
    float s1 = 0.f, s2 = 0.f;
#pragma unroll
    for (int i = 0; i < 4; i++) {
        v[i] = rp[lane + i * 32];
        s1 += v[i].x + v[i].y + v[i].z + v[i].w;
        s2 += v[i].x * v[i].x + v[i].y * v[i].y + v[i].z * v[i].z + v[i].w * v[i].w;
    }
#pragma unroll
    for (int o = 16; o > 0; o >>= 1) {
        s1 += __shfl_xor_sync(0xffffffffu, s1, o);
        s2 += __shfl_xor_sync(0xffffffffu, s2, o);
    }
    const float m = s1 * (1.0f / Dn);
    const float rr = rsqrtf(s2 * (1.0f / Dn) - m * m + LNEPS);

    float4* op = (float4*)(out + (size_t)row * Dn);
    const float4* gp = (const float4*)gw;
    const float4* bp = (const float4*)bw;
#pragma unroll
    for (int i = 0; i < 4; i++) {
        const float4 g4 = gp[lane + i * 32];
        const float4 b4 = bp[lane + i * 32];
        float4 o4;
        o4.x = (v[i].x - m) * rr * g4.x + b4.x;
        o4.y = (v[i].y - m) * rr * g4.y + b4.y;
        o4.z = (v[i].z - m) * rr * g4.z + b4.z;
        o4.w = (v[i].w - m) * rr * g4.w + b4.w;
        op[lane + i * 32] = o4;
        if (SPLIT) {
            __half2* hp = (__half2*)(oh + (size_t)row * Dn) + 2 * (lane + i * 32);
            hp[0] = __floats2half2_rn(o4.x, o4.y);
            hp[1] = __floats2half2_rn(o4.z, o4.w);
        }
    }
}

// ------------------------------- launch ------------------------------------
extern "C" void kernel_launch(void* const* d_in, const int* in_sizes, int n_in,
                              void* d_out, int out_size)
{
    const float* x    = (const float*)d_in[0];
    const float* wq   = (const float*)d_in[1];
    const float* bq   = (const float*)d_in[2];
    const float* wk   = (const float*)d_in[3];
    const float* bk   = (const float*)d_in[4];
    const float* wv   = (const float*)d_in[5];
    const float* bv   = (const float*)d_in[6];
    const float* wo   = (const float*)d_in[7];
    const float* bo   = (const float*)d_in[8];
    const float* qcw  = (const float*)d_in[9];
    const float* qcb  = (const float*)d_in[10];
    const float* kcw  = (const float*)d_in[11];
    const float* kcb  = (const float*)d_in[12];
    const float* vcw  = (const float*)d_in[13];
    const float* vcb  = (const float*)d_in[14];
    const float* w1   = (const float*)d_in[15];
    const float* b1   = (const float*)d_in[16];
    const float* w2   = (const float*)d_in[17];
    const float* b2   = (const float*)d_in[18];
    const float* ln1g = (const float*)d_in[19];
    const float* ln1b = (const float*)d_in[20];
    const float* ln2g = (const float*)d_in[21];
    const float* ln2b = (const float*)d_in[22];
    float* out = (float*)d_out;

    float *py, *px1, *py2, *pbqkv;
    cudaGetSymbolAddress((void**)&py,    g_y);
    cudaGetSymbolAddress((void**)&px1,   g_x1);
    cudaGetSymbolAddress((void**)&py2,   g_y2);
    cudaGetSymbolAddress((void**)&pbqkv, g_bqkv);

    __half *pqkvh, *pxh, *path, *px1h, *phh;
    __half *pwqkvh, *pwoh, *pw1h, *pw2h;
    cudaGetSymbolAddress((void**)&pqkvh,  g_qkvh);
    cudaGetSymbolAddress((void**)&pxh,    g_xh);
    cudaGetSymbolAddress((void**)&path,   g_ath);
    cudaGetSymbolAddress((void**)&px1h,   g_x1h);
    cudaGetSymbolAddress((void**)&phh,    g_hh);
    cudaGetSymbolAddress((void**)&pwqkvh, g_wqkvh);
    cudaGetSymbolAddress((void**)&pwoh,   g_woh);
    cudaGetSymbolAddress((void**)&pw1h,   g_w1h);
    cudaGetSymbolAddress((void**)&pw2h,   g_w2h);

    cudaFuncSetAttribute(gemm_mma<0>, cudaFuncAttributeMaxDynamicSharedMemorySize, GSMEM);
    cudaFuncSetAttribute(gemm_mma<1>, cudaFuncAttributeMaxDynamicSharedMemorySize, GSMEM);
    cudaFuncSetAttribute(gemm_mma<2>, cudaFuncAttributeMaxDynamicSharedMemorySize, GSMEM);
    cudaFuncSetAttribute(gemm_mma<3>, cudaFuncAttributeMaxDynamicSharedMemorySize, GSMEM);

    auto cvt = [](const float* p, __half* h, size_t n) {
        int n4 = (int)(n / 4);
        cvt_h<<<(n4 + 255) / 256, 256>>>(p, h, n4);
    };

    const dim3 gridQKV(D3 / 256, Mn / 128);   // (6, 256) = 1536 CTAs
    const dim3 gridD(Dn / 256, Mn / 128);     // (2, 256)
    const dim3 gridF(DFFn / 256, Mn / 128);   // (4, 256)

    // Launches 0-4 (launch #5, the ncu-profiled one, is the merged QKV GEMM)
    cvt(x,  pxh, (size_t)Mn * Dn);
    cvt(wq, pwqkvh,                       (size_t)Dn * Dn);
    cvt(wk, pwqkvh + (size_t)Dn * Dn,     (size_t)Dn * Dn);
    cvt(wv, pwqkvh + (size_t)2 * Dn * Dn, (size_t)Dn * Dn);
    pack3<<<(D3 + 255) / 256, 256>>>(bq, bk, bv, pbqkv);

    // merged QKV projection -> fp16 (launch #5)
    gemm_mma<3><<<gridQKV, 512, GSMEM>>>(pxh, pwqkvh, pbqkv, nullptr,
                                         nullptr, pqkvh, Mn, D3, Dn);

    // remaining weight converts (overlap with attention phase)
    cvt(wo, pwoh, (size_t)Dn * Dn);
    cvt(w1, pw1h, (size_t)DFFn * Dn);
    cvt(w2, pw2h, (size_t)Dn * DFFn);

    // depthwise conv + elu+1 + partial KV/Ksum (fp16 in/out)
    conv_pre<<<dim3(NCH, Hn, Bn), 256>>>(pqkvh, qcw, qcb, kcw, kcb, vcw, vcb);
    kv_reduce<<<Bn * Hn, 256>>>();
    attn_apply<<<dim3(Sn / 64, Hn, Bn), 256>>>();

    // output projection + residual, then LN1 (LN1 also emits fp16)
    gemm_mma<1><<<gridD, 512, GSMEM>>>(path, pwoh, bo, x, py, nullptr, Mn, Dn, Dn);
    ln_kernel<true><<<Mn / 8, 256>>>(py, ln1g, ln1b, px1, px1h);

    // FFN: gelu^2 -> fp16 h; FFN2 consumes it (K=1024)
    gemm_mma<2><<<gridF, 512, GSMEM>>>(px1h, pw1h, b1, nullptr, nullptr, phh, Mn, DFFn, Dn);
    gemm_mma<1><<<gridD, 512, GSMEM>>>(phh, pw2h, b2, px1, py2, nullptr, Mn, Dn, DFFn);
    ln_kernel<false><<<Mn / 8, 256>>>(py2, ln2g, ln2b, out, nullptr);
}

// round 9
// speedup vs baseline: 4.4199x; 1.0502x over previous
#include <cuda_runtime.h>
#include <cuda_fp16.h>
#include <cstdint>

#define Bn 8
#define Sn 4096
#define Dn 512
#define Hn 8
#define DKn 64
#define DFFn 1024
#define Mn (Bn*Sn)          // 32768 rows
#define NCH 16              // seq chunks for partial KV
#define CHROWS 256
#define EPSA 1e-6f
#define LNEPS 1e-5f
#define D3 (3*Dn)           // 1536

// ---------------- scratch (device globals; no allocation allowed) ----------
__device__ float g_y   [(size_t)Mn*Dn];
__device__ float g_x1  [(size_t)Mn*Dn];
__device__ float g_y2  [(size_t)Mn*Dn];
__device__ float g_kvp [(size_t)Bn*Hn*NCH*DKn*DKn];
__device__ float g_ksp [(size_t)Bn*Hn*NCH*DKn];
__device__ float g_ks  [(size_t)Bn*Hn*DKn];
__device__ float g_bqkv[D3];

// fp16 buffers
__device__ __half g_qkvh[(size_t)Mn*D3];        // merged q|k|v projections
__device__ __half g_q2h [(size_t)Mn*Dn];        // elu(conv(q))+1
__device__ __half g_kvhT[(size_t)Bn*Hn*DKn*DKn];// KV transposed [bh][e][d]
__device__ __half g_xh  [(size_t)Mn*Dn];
__device__ __half g_ath [(size_t)Mn*Dn];
__device__ __half g_x1h [(size_t)Mn*Dn];
__device__ __half g_hh  [(size_t)Mn*DFFn];
__device__ __half g_wqkvh[(size_t)D3*Dn];
__device__ __half g_woh [Dn*Dn];
__device__ __half g_w1h [DFFn*Dn];
__device__ __half g_w2h [Dn*DFFn];

// ------------------------- PTX helpers -------------------------------------
__device__ __forceinline__ uint32_t smem_u32(const void* p) {
    uint32_t a;
    asm("{ .reg .u64 t; cvta.to.shared.u64 t, %1; cvt.u32.u64 %0, t; }"
        : "=r"(a) : "l"(p));
    return a;
}

__device__ __forceinline__ void ldm4(uint32_t* r, uint32_t addr) {
    asm volatile("ldmatrix.sync.aligned.m8n8.x4.shared.b16 {%0,%1,%2,%3}, [%4];"
                 : "=r"(r[0]), "=r"(r[1]), "=r"(r[2]), "=r"(r[3]) : "r"(addr));
}

__device__ __forceinline__ void mma16816(float* c, const uint32_t* a,
                                         uint32_t b0, uint32_t b1) {
    asm volatile(
        "mma.sync.aligned.m16n8k16.row.col.f32.f16.f16.f32 "
        "{%0,%1,%2,%3}, {%4,%5,%6,%7}, {%8,%9}, {%0,%1,%2,%3};"
        : "+f"(c[0]), "+f"(c[1]), "+f"(c[2]), "+f"(c[3])
        : "r"(a[0]), "r"(a[1]), "r"(a[2]), "r"(a[3]), "r"(b0), "r"(b1));
}

// ================= HMMA fp16 GEMM: C = A(fp16) @ W(fp16)^T + bias ==========
// EPI: 0 = bias->fp32 ; 1 = bias+res->fp32 ; 2 = gelu(x)^2->fp16 ; 3 = bias->fp16
#define PITCH 80
#define ABYTES (128 * PITCH)
#define WBYTES (256 * PITCH)
#define STAGE (ABYTES + WBYTES)
#define NSTG 3
#define GSMEM (NSTG * STAGE)

template<int EPI>
__global__ void __launch_bounds__(512) gemm_mma(
    const __half* __restrict__ A, const __half* __restrict__ W,
    const float* __restrict__ bias, const float* __restrict__ res,
    float* __restrict__ C, __half* __restrict__ Ch,
    int M, int N, int K)
{
    extern __shared__ char smem[];
    const uint32_t sb = smem_u32(smem);
    const int tid  = threadIdx.x;
    const int bn = blockIdx.x * 256, bm = blockIdx.y * 128;
    const int w = tid >> 5, lane = tid & 31;
    const int wm = w & 3, wn = w >> 2;
    const int mrow = lane >> 3, mr = lane & 7;

    const __half* Ap = A + (size_t)bm * K;
    const __half* Wp = W + (size_t)bn * K;
    const int nch = K >> 5;

    const int lr = tid >> 2, lc = tid & 3;

    auto load_chunk = [&](int kt, int stg) {
        const uint32_t base = sb + stg * STAGE;
        const int off = kt * 32 + lc * 8;
        const uint32_t dA = base + lr * PITCH + lc * 16;
        asm volatile("cp.async.cg.shared.global [%0], [%1], 16;"
                     :: "r"(dA), "l"((const void*)(Ap + (size_t)lr * K + off)));
        const uint32_t dW = base + ABYTES + lr * PITCH + lc * 16;
        asm volatile("cp.async.cg.shared.global [%0], [%1], 16;"
                     :: "r"(dW), "l"((const void*)(Wp + (size_t)lr * K + off)));
        asm volatile("cp.async.cg.shared.global [%0], [%1], 16;"
                     :: "r"(dW + 128 * PITCH), "l"((const void*)(Wp + (size_t)(lr + 128) * K + off)));
        asm volatile("cp.async.commit_group;");
    };

    float acc[2][8][4];
#pragma unroll
    for (int i = 0; i < 2; i++)
#pragma unroll
        for (int j = 0; j < 8; j++)
#pragma unroll
            for (int q = 0; q < 4; q++) acc[i][j][q] = 0.f;

    load_chunk(0, 0);
    load_chunk(1, 1);

    int cs = 0, ls = 2;
    for (int kt = 0; kt < nch; kt++) {
        if (kt == nch - 1) {
            asm volatile("cp.async.wait_group 0;" ::: "memory");
        } else {
            asm volatile("cp.async.wait_group 1;" ::: "memory");
        }
        __syncthreads();
        if (kt + 2 < nch) {
            load_chunk(kt + 2, ls);
            ls = (ls == 2) ? 0 : ls + 1;
        }

        const uint32_t base = sb + cs * STAGE;
        cs = (cs == 2) ? 0 : cs + 1;
#pragma unroll
        for (int ks = 0; ks < 2; ks++) {
            uint32_t ah[2][4];
#pragma unroll
            for (int i = 0; i < 2; i++) {
                const int rowA = wm * 32 + i * 16 + (mrow & 1) * 8 + mr;
                const uint32_t cA = ks * 32 + (mrow >> 1) * 16;
                ldm4(ah[i], base + rowA * PITCH + cA);
            }
#pragma unroll
            for (int jp = 0; jp < 4; jp++) {
                const int rowB = wn * 64 + jp * 16 + (mrow >> 1) * 8 + mr;
                const uint32_t cB = ks * 32 + (mrow & 1) * 16;
                uint32_t t0[4];
                ldm4(t0, base + ABYTES + rowB * PITCH + cB);
#pragma unroll
                for (int i = 0; i < 2; i++) {
                    mma16816(acc[i][2*jp],     ah[i], t0[0], t0[1]);
                    mma16816(acc[i][2*jp + 1], ah[i], t0[2], t0[3]);
                }
            }
        }
    }
    __syncthreads();

    const int tg = lane >> 2, ti = lane & 3;
#pragma unroll
    for (int i = 0; i < 2; i++) {
#pragma unroll
        for (int j = 0; j < 8; j++) {
            const int gr0 = bm + wm * 32 + i * 16 + tg;
            const int gc  = bn + wn * 64 + j * 8 + ti * 2;
            const float b0 = bias[gc], b1 = bias[gc + 1];
#pragma unroll
            for (int hfl = 0; hfl < 2; hfl++) {
                const int gr = gr0 + hfl * 8;
                float v0 = acc[i][j][2*hfl + 0] + b0;
                float v1 = acc[i][j][2*hfl + 1] + b1;
                const size_t off = (size_t)gr * N + gc;
                if (EPI == 1) {
                    float2 rv = *(const float2*)(res + off);
                    v0 += rv.x; v1 += rv.y;
                }
                if (EPI == 2) {
                    float g0 = 0.5f * v0 * (1.0f + erff(v0 * 0.7071067811865476f));
                    float g1 = 0.5f * v1 * (1.0f + erff(v1 * 0.7071067811865476f));
                    v0 = g0 * g0; v1 = g1 * g1;
                }
                if (EPI == 2 || EPI == 3) {
                    *(__half2*)(Ch + off) = __floats2half2_rn(v0, v1);
                } else {
                    float2 ov; ov.x = v0; ov.y = v1;
                    *(float2*)(C + off) = ov;
                }
            }
        }
    }
}

// ------------------ fp32 -> fp16 convert ------------------------------------
__global__ void cvt_h(const float* __restrict__ in, __half* __restrict__ out, int n4)
{
    const int i = blockIdx.x * 256 + threadIdx.x;
    if (i >= n4) return;
    float4 v = ((const float4*)in)[i];
    ((__half2*)out)[2 * i]     = __floats2half2_rn(v.x, v.y);
    ((__half2*)out)[2 * i + 1] = __floats2half2_rn(v.z, v.w);
}

// ------------------ pack 3 bias vectors into one ----------------------------
__global__ void pack3(const float* __restrict__ a, const float* __restrict__ b,
                      const float* __restrict__ c, float* __restrict__ o)
{
    const int i = blockIdx.x * 256 + threadIdx.x;
    if (i < Dn)            o[i] = a[i];
    else if (i < 2 * Dn)   o[i] = b[i - Dn];
    else if (i < 3 * Dn)   o[i] = c[i - 2 * Dn];
}

// ------------- conv(q,k,v) + elu+1(q,k) + partial KV / Ksum ---------------
// half2-vectorized: thread = (channel pair, 8 rows); register-carried taps.
__global__ __launch_bounds__(256) void conv_pre(
    const __half* __restrict__ qkv,
    const float* __restrict__ qcw, const float* __restrict__ qcb,
    const float* __restrict__ kcw, const float* __restrict__ kcb,
    const float* __restrict__ vcw, const float* __restrict__ vcb)
{
    const int c = blockIdx.x, h = blockIdx.y, b = blockIdx.z;
    const int t  = threadIdx.x;
    const int p  = t & 31;           // channel pair -> channels 2p, 2p+1
    const int rl = t >> 5;           // 0..7, 8 rows each
    const int ch = 2 * p;
    const int d0 = (t & 15) * 4, e0 = (t >> 4) * 4;

    __shared__ float k2s[64][68];
    __shared__ float v2s[64][68];

    const float qw0a = qcw[ch*3+0], qw1a = qcw[ch*3+1], qw2a = qcw[ch*3+2], qba = qcb[ch];
    const float qw0b = qcw[ch*3+3], qw1b = qcw[ch*3+4], qw2b = qcw[ch*3+5], qbb = qcb[ch+1];
    const float kw0a = kcw[ch*3+0], kw1a = kcw[ch*3+1], kw2a = kcw[ch*3+2], kba = kcb[ch];
    const float kw0b = kcw[ch*3+3], kw1b = kcw[ch*3+4], kw2b = kcw[ch*3+5], kbb = kcb[ch+1];
    const float vw0a = vcw[ch*3+0], vw1a = vcw[ch*3+1], vw2a = vcw[ch*3+2], vba = vcb[ch];
    const float vw0b = vcw[ch*3+3], vw1b = vcw[ch*3+4], vw2b = vcw[ch*3+5], vbb = vcb[ch+1];

    float acc[4][4];
#pragma unroll
    for (int i = 0; i < 4; i++)
#pragma unroll
        for (int j = 0; j < 4; j++) acc[i][j] = 0.f;
    float ksacc = 0.f;

    for (int sub = 0; sub < 4; sub++) {
        __syncthreads();
        const int s0 = c * CHROWS + sub * 64 + rl * 8;
        const size_t qb0  = ((size_t)(b * Sn + s0)) * D3 + h * DKn + ch;
        const size_t q2b0 = ((size_t)(b * Sn + s0)) * Dn + h * DKn + ch;
        float2 qm1 = {0.f,0.f}, qm2 = {0.f,0.f};
        float2 km1 = {0.f,0.f}, km2 = {0.f,0.f};
        float2 vm1 = {0.f,0.f}, vm2 = {0.f,0.f};
        if (s0 >= 1) {
            qm1 = __half22float2(*(const __half2*)(qkv + qb0 - D3));
            km1 = __half22float2(*(const __half2*)(qkv + qb0 - D3 + Dn));
            vm1 = __half22float2(*(const __half2*)(qkv + qb0 - D3 + 2 * Dn));
        }
        if (s0 >= 2) {
            qm2 = __half22float2(*(const __half2*)(qkv + qb0 - 2 * D3));
            km2 = __half22float2(*(const __half2*)(qkv + qb0 - 2 * D3 + Dn));
            vm2 = __half22float2(*(const __half2*)(qkv + qb0 - 2 * D3 + 2 * Dn));
        }
#pragma unroll
        for (int i = 0; i < 8; i++) {
            const int r = rl * 8 + i;
            const size_t base = qb0 + (size_t)i * D3;

            float2 q0 = __half22float2(*(const __half2*)(qkv + base));
            float qcx = qw0a*qm2.x + qw1a*qm1.x + qw2a*q0.x + qba;
            float qcy = qw0b*qm2.y + qw1b*qm1.y + qw2b*q0.y + qbb;
            qcx = qcx > 0.f ? qcx + 1.f : expf(qcx);
            qcy = qcy > 0.f ? qcy + 1.f : expf(qcy);
            *(__half2*)(g_q2h + q2b0 + (size_t)i * Dn) = __floats2half2_rn(qcx, qcy);
            qm2 = qm1; qm1 = q0;

            float2 k0 = __half22float2(*(const __half2*)(qkv + base + Dn));
            float kcx = kw0a*km2.x + kw1a*km1.x + kw2a*k0.x + kba;
            float kcy = kw0b*km2.y + kw1b*km1.y + kw2b*k0.y + kbb;
            kcx = kcx > 0.f ? kcx + 1.f : expf(kcx);
            kcy = kcy > 0.f ? kcy + 1.f : expf(kcy);
            float2 kst; kst.x = kcx; kst.y = kcy;
            *(float2*)&k2s[r][ch] = kst;
            km2 = km1; km1 = k0;

            float2 v0 = __half22float2(*(const __half2*)(qkv + base + 2 * Dn));
            float2 vst;
            vst.x = vw0a*vm2.x + vw1a*vm1.x + vw2a*v0.x + vba;
            vst.y = vw0b*vm2.y + vw1b*vm1.y + vw2b*v0.y + vbb;
            *(float2*)&v2s[r][ch] = vst;
            vm2 = vm1; vm1 = v0;
        }
        __syncthreads();
        if (t < 64) {
#pragma unroll 8
            for (int r = 0; r < 64; r++) ksacc += k2s[r][t];
        }
#pragma unroll 4
        for (int r = 0; r < 64; r++) {
            float4 kd = *(const float4*)&k2s[r][d0];
            float4 ve = *(const float4*)&v2s[r][e0];
            float kda[4] = {kd.x, kd.y, kd.z, kd.w};
            float vea[4] = {ve.x, ve.y, ve.z, ve.w};
#pragma unroll
            for (int i = 0; i < 4; i++)
#pragma unroll
                for (int j = 0; j < 4; j++)
                    acc[i][j] = fmaf(kda[i], vea[j], acc[i][j]);
        }
    }

    const int bh = b * Hn + h;
    const size_t kvbase = ((size_t)bh * NCH + c) * (DKn * DKn);
#pragma unroll
    for (int i = 0; i < 4; i++)
#pragma unroll
        for (int j = 0; j < 4; j++)
            g_kvp[kvbase + (size_t)(d0 + i) * DKn + (e0 + j)] = acc[i][j];
    if (t < 64)
        g_ksp[((size_t)bh * NCH + c) * DKn + t] = ksacc;
}

// ---- reduce partial KV (-> fp16 transposed) / Ksum over chunks ------------
__global__ void kv_reduce()
{
    const int bh = blockIdx.x, t = threadIdx.x;
    for (int idx = t; idx < DKn * DKn; idx += 256) {
        float s = 0.f;
#pragma unroll
        for (int c = 0; c < NCH; c++)
            s += g_kvp[((size_t)bh * NCH + c) * (DKn * DKn) + idx];
        const int d = idx >> 6, e = idx & 63;
        g_kvhT[(size_t)bh * (DKn * DKn) + e * DKn + d] = __float2half_rn(s);
    }
    if (t < DKn) {
        float s = 0.f;
#pragma unroll
        for (int c = 0; c < NCH; c++)
            s += g_ksp[((size_t)bh * NCH + c) * DKn + t];
        g_ks[(size_t)bh * DKn + t] = s;
    }
}

// -------------- attn apply via HMMA: Vn = (Q @ KV) / (Q.(Ksum+eps)) --------
// Per block: one (b,h,64-row tile). A = Q [64,64] fp16, B = KV^T [64,64] fp16.
#define APITCH 144
__global__ __launch_bounds__(128) void attn_apply()
{
    const int st = blockIdx.x, h = blockIdx.y, b = blockIdx.z;
    const int t = threadIdx.x;
    const int bh = b * Hn + h;
    const int w = t >> 5, lane = t & 31;
    const int mrow = lane >> 3, mr = lane & 7;

    __shared__ __align__(16) char qsmem[64 * APITCH];
    __shared__ __align__(16) char ksmem[64 * APITCH];
    __shared__ float kss[64];
    __shared__ float zinv[64];

    const uint32_t qb = smem_u32(qsmem);
    const uint32_t kb = smem_u32(ksmem);

    // fill (coalesced half2)
    for (int idx = t; idx < 2048; idx += 128) {
        const int r = idx >> 5, c2 = idx & 31;
        *(__half2*)(qsmem + r * APITCH + c2 * 4) =
            *(const __half2*)(g_q2h + ((size_t)(b * Sn + st * 64 + r)) * Dn
                              + h * DKn + c2 * 2);
        *(__half2*)(ksmem + r * APITCH + c2 * 4) =
            *(const __half2*)(g_kvhT + (size_t)bh * (DKn * DKn) + r * DKn + c2 * 2);
    }
    if (t < DKn) kss[t] = g_ks[(size_t)bh * DKn + t] + EPSA;
    __syncthreads();

    // z = Q . kss  (threads t, t^1 split the 64-d dot)
    {
        const int s = t >> 1, part = t & 1;
        float z = 0.f;
        const char* rp = qsmem + s * APITCH + part * 64;
#pragma unroll
        for (int d = 0; d < 32; d++)
            z += __half2float(*(const __half*)(rp + d * 2)) * kss[part * 32 + d];
        z += __shfl_xor_sync(0xffffffffu, z, 1);
        if (part == 0) zinv[s] = 1.0f / z;
    }

    // MMA: warp w -> rows 16w..16w+15, all 64 cols
    float acc[8][4];
#pragma unroll
    for (int j = 0; j < 8; j++)
#pragma unroll
        for (int q = 0; q < 4; q++) acc[j][q] = 0.f;

#pragma unroll
    for (int ks = 0; ks < 4; ks++) {
        uint32_t ah[4];
        const int rowA = w * 16 + (mrow & 1) * 8 + mr;
        ldm4(ah, qb + rowA * APITCH + ks * 32 + (mrow >> 1) * 16);
#pragma unroll
        for (int jp = 0; jp < 4; jp++) {
            const int rowB = jp * 16 + (mrow >> 1) * 8 + mr;
            uint32_t t0[4];
            ldm4(t0, kb + rowB * APITCH + ks * 32 + (mrow & 1) * 16);
            mma16816(acc[2*jp],     ah, t0[0], t0[1]);
            mma16816(acc[2*jp + 1], ah, t0[2], t0[3]);
        }
    }
    __syncthreads();   // zinv visible to all

    // epilogue: scale by zinv, write fp16
    const int tg = lane >> 2, ti = lane & 3;
#pragma unroll
    for (int j = 0; j < 8; j++) {
        const int col = j * 8 + ti * 2;
#pragma unroll
        for (int hfl = 0; hfl < 2; hfl++) {
            const int row = w * 16 + hfl * 8 + tg;
            const float zi = zinv[row];
            const size_t off = ((size_t)(b * Sn + st * 64 + row)) * Dn
                               + h * DKn + col;
            *(__half2*)(g_ath + off) =
                __floats2half2_rn(zi * acc[j][2*hfl], zi * acc[j][2*hfl + 1]);
        }
    }
}

// -------------------- LayerNorm (D=512), warp per row ----------------------
template<bool SPLIT>
__global__ __launch_bounds__(256) void ln_kernel(
    const float* __restrict__ in, const float* __restrict__ gw,
    const float* __restrict__ bw, float* __restrict__ out,
    __half* __restrict__ oh)
{
    const int warp = threadIdx.x >> 5, lane = threadIdx.x & 31;
    const int row = blockIdx.x * 8 + warp;
    const float4* rp = (const float4*)(in + (size_t)row * Dn);

    float4 v[4];
    float s1 = 0.f, s2 = 0.f;
#pragma unroll
    for (int i = 0; i < 4; i++) {
        v[i] = rp[lane + i * 32];
        s1 += v[i].x + v[i].y + v[i].z + v[i].w;
        s2 += v[i].x * v[i].x + v[i].y * v[i].y + v[i].z * v[i].z + v[i].w * v[i].w;
    }
#pragma unroll
    for (int o = 16; o > 0; o >>= 1) {
        s1 += __shfl_xor_sync(0xffffffffu, s1, o);
        s2 += __shfl_xor_sync(0xffffffffu, s2, o);
    }
    const float m = s1 * (1.0f / Dn);
    const float rr = rsqrtf(s2 * (1.0f / Dn) - m * m + LNEPS);

    float4* op = (float4*)(out + (size_t)row * Dn);
    const float4* gp = (const float4*)gw;
    const float4* bp = (const float4*)bw;
#pragma unroll
    for (int i = 0; i < 4; i++) {
        const float4 g4 = gp[lane + i * 32];
        const float4 b4 = bp[lane + i * 32];
        float4 o4;
        o4.x = (v[i].x - m) * rr * g4.x + b4.x;
        o4.y = (v[i].y - m) * rr * g4.y + b4.y;
        o4.z = (v[i].z - m) * rr * g4.z + b4.z;
        o4.w = (v[i].w - m) * rr * g4.w + b4.w;
        op[lane + i * 32] = o4;
        if (SPLIT) {
            __half2* hp = (__half2*)(oh + (size_t)row * Dn) + 2 * (lane + i * 32);
            hp[0] = __floats2half2_rn(o4.x, o4.y);
            hp[1] = __floats2half2_rn(o4.z, o4.w);
        }
    }
}

// ------------------------------- launch ------------------------------------
extern "C" void kernel_launch(void* const* d_in, const int* in_sizes, int n_in,
                              void* d_out, int out_size)
{
    const float* x    = (const float*)d_in[0];
    const float* wq   = (const float*)d_in[1];
    const float* bq   = (const float*)d_in[2];
    const float* wk   = (const float*)d_in[3];
    const float* bk   = (const float*)d_in[4];
    const float* wv   = (const float*)d_in[5];
    const float* bv   = (const float*)d_in[6];
    const float* wo   = (const float*)d_in[7];
    const float* bo   = (const float*)d_in[8];
    const float* qcw  = (const float*)d_in[9];
    const float* qcb  = (const float*)d_in[10];
    const float* kcw  = (const float*)d_in[11];
    const float* kcb  = (const float*)d_in[12];
    const float* vcw  = (const float*)d_in[13];
    const float* vcb  = (const float*)d_in[14];
    const float* w1   = (const float*)d_in[15];
    const float* b1   = (const float*)d_in[16];
    const float* w2   = (const float*)d_in[17];
    const float* b2   = (const float*)d_in[18];
    const float* ln1g = (const float*)d_in[19];
    const float* ln1b = (const float*)d_in[20];
    const float* ln2g = (const float*)d_in[21];
    const float* ln2b = (const float*)d_in[22];
    float* out = (float*)d_out;

    float *py, *px1, *py2, *pbqkv;
    cudaGetSymbolAddress((void**)&py,    g_y);
    cudaGetSymbolAddress((void**)&px1,   g_x1);
    cudaGetSymbolAddress((void**)&py2,   g_y2);
    cudaGetSymbolAddress((void**)&pbqkv, g_bqkv);

    __half *pqkvh, *pxh, *path, *px1h, *phh;
    __half *pwqkvh, *pwoh, *pw1h, *pw2h;
    cudaGetSymbolAddress((void**)&pqkvh,  g_qkvh);
    cudaGetSymbolAddress((void**)&pxh,    g_xh);
    cudaGetSymbolAddress((void**)&path,   g_ath);
    cudaGetSymbolAddress((void**)&px1h,   g_x1h);
    cudaGetSymbolAddress((void**)&phh,    g_hh);
    cudaGetSymbolAddress((void**)&pwqkvh, g_wqkvh);
    cudaGetSymbolAddress((void**)&pwoh,   g_woh);
    cudaGetSymbolAddress((void**)&pw1h,   g_w1h);
    cudaGetSymbolAddress((void**)&pw2h,   g_w2h);

    cudaFuncSetAttribute(gemm_mma<0>, cudaFuncAttributeMaxDynamicSharedMemorySize, GSMEM);
    cudaFuncSetAttribute(gemm_mma<1>, cudaFuncAttributeMaxDynamicSharedMemorySize, GSMEM);
    cudaFuncSetAttribute(gemm_mma<2>, cudaFuncAttributeMaxDynamicSharedMemorySize, GSMEM);
    cudaFuncSetAttribute(gemm_mma<3>, cudaFuncAttributeMaxDynamicSharedMemorySize, GSMEM);

    auto cvt = [](const float* p, __half* h, size_t n) {
        int n4 = (int)(n / 4);
        cvt_h<<<(n4 + 255) / 256, 256>>>(p, h, n4);
    };

    const dim3 gridQKV(D3 / 256, Mn / 128);   // (6, 256)
    const dim3 gridD(Dn / 256, Mn / 128);     // (2, 256)
    const dim3 gridF(DFFn / 256, Mn / 128);   // (4, 256)

    // Launches 0-4 (launch #5, the ncu-profiled one, is the merged QKV GEMM)
    cvt(x,  pxh, (size_t)Mn * Dn);
    cvt(wq, pwqkvh,                       (size_t)Dn * Dn);
    cvt(wk, pwqkvh + (size_t)Dn * Dn,     (size_t)Dn * Dn);
    cvt(wv, pwqkvh + (size_t)2 * Dn * Dn, (size_t)Dn * Dn);
    pack3<<<(D3 + 255) / 256, 256>>>(bq, bk, bv, pbqkv);

    // merged QKV projection -> fp16 (launch #5)
    gemm_mma<3><<<gridQKV, 512, GSMEM>>>(pxh, pwqkvh, pbqkv, nullptr,
                                         nullptr, pqkvh, Mn, D3, Dn);

    // remaining weight converts (overlap with attention phase)
    cvt(wo, pwoh, (size_t)Dn * Dn);
    cvt(w1, pw1h, (size_t)DFFn * Dn);
    cvt(w2, pw2h, (size_t)Dn * DFFn);

    // depthwise conv + elu+1 + partial KV/Ksum (fp16 in/out)
    conv_pre<<<dim3(NCH, Hn, Bn), 256>>>(pqkvh, qcw, qcb, kcw, kcb, vcw, vcb);
    kv_reduce<<<Bn * Hn, 256>>>();
    attn_apply<<<dim3(Sn / 64, Hn, Bn), 128>>>();

    // output projection + residual, then LN1 (LN1 also emits fp16)
    gemm_mma<1><<<gridD, 512, GSMEM>>>(path, pwoh, bo, x, py, nullptr, Mn, Dn, Dn);
    ln_kernel<true><<<Mn / 8, 256>>>(py, ln1g, ln1b, px1, px1h);

    // FFN: gelu^2 -> fp16 h; FFN2 consumes it (K=1024)
    gemm_mma<2><<<gridF, 512, GSMEM>>>(px1h, pw1h, b1, nullptr, nullptr, phh, Mn, DFFn, Dn);
    gemm_mma<1><<<gridD, 512, GSMEM>>>(phh, pw2h, b2, px1, py2, nullptr, Mn, Dn, DFFn);
    ln_kernel<false><<<Mn / 8, 256>>>(py2, ln2g, ln2b, out, nullptr);
}

// round 10
// speedup vs baseline: 4.5698x; 1.0339x over previous
#include <cuda_runtime.h>
#include <cuda_fp16.h>
#include <cstdint>

#define Bn 8
#define Sn 4096
#define Dn 512
#define Hn 8
#define DKn 64
#define DFFn 1024
#define Mn (Bn*Sn)          // 32768 rows
#define NCH 16              // seq chunks for partial KV
#define CHROWS 256
#define EPSA 1e-6f
#define LNEPS 1e-5f
#define D3 (3*Dn)           // 1536

// ---------------- scratch (device globals; no allocation allowed) ----------
__device__ float g_y   [(size_t)Mn*Dn];
__device__ float g_x1  [(size_t)Mn*Dn];
__device__ float g_y2  [(size_t)Mn*Dn];
__device__ float g_kvp [(size_t)Bn*Hn*NCH*DKn*DKn];
__device__ float g_ksp [(size_t)Bn*Hn*NCH*DKn];
__device__ float g_ks  [(size_t)Bn*Hn*DKn];
__device__ float g_bqkv[D3];

// fp16 buffers
__device__ __half g_qkvh[(size_t)Mn*D3];        // merged q|k|v projections
__device__ __half g_q2h [(size_t)Mn*Dn];        // elu(conv(q))+1
__device__ __half g_kvhT[(size_t)Bn*Hn*DKn*DKn];// KV transposed [bh][e][d]
__device__ __half g_xh  [(size_t)Mn*Dn];
__device__ __half g_ath [(size_t)Mn*Dn];
__device__ __half g_x1h [(size_t)Mn*Dn];
__device__ __half g_hh  [(size_t)Mn*DFFn];
__device__ __half g_wqkvh[(size_t)D3*Dn];
__device__ __half g_woh [Dn*Dn];
__device__ __half g_w1h [DFFn*Dn];
__device__ __half g_w2h [Dn*DFFn];

// ------------------------- PTX helpers -------------------------------------
__device__ __forceinline__ uint32_t smem_u32(const void* p) {
    uint32_t a;
    asm("{ .reg .u64 t; cvta.to.shared.u64 t, %1; cvt.u32.u64 %0, t; }"
        : "=r"(a) : "l"(p));
    return a;
}

__device__ __forceinline__ void ldm4(uint32_t* r, uint32_t addr) {
    asm volatile("ldmatrix.sync.aligned.m8n8.x4.shared.b16 {%0,%1,%2,%3}, [%4];"
                 : "=r"(r[0]), "=r"(r[1]), "=r"(r[2]), "=r"(r[3]) : "r"(addr));
}

__device__ __forceinline__ void ldm4t(uint32_t* r, uint32_t addr) {
    asm volatile("ldmatrix.sync.aligned.m8n8.x4.trans.shared.b16 {%0,%1,%2,%3}, [%4];"
                 : "=r"(r[0]), "=r"(r[1]), "=r"(r[2]), "=r"(r[3]) : "r"(addr));
}

__device__ __forceinline__ void mma16816(float* c, const uint32_t* a,
                                         uint32_t b0, uint32_t b1) {
    asm volatile(
        "mma.sync.aligned.m16n8k16.row.col.f32.f16.f16.f32 "
        "{%0,%1,%2,%3}, {%4,%5,%6,%7}, {%8,%9}, {%0,%1,%2,%3};"
        : "+f"(c[0]), "+f"(c[1]), "+f"(c[2]), "+f"(c[3])
        : "r"(a[0]), "r"(a[1]), "r"(a[2]), "r"(a[3]), "r"(b0), "r"(b1));
}

// ================= HMMA fp16 GEMM: C = A(fp16) @ W(fp16)^T + bias ==========
// EPI: 0 = bias->fp32 ; 1 = bias+res->fp32 ; 2 = gelu(x)^2->fp16 ; 3 = bias->fp16
#define PITCH 80
#define ABYTES (128 * PITCH)
#define WBYTES (256 * PITCH)
#define STAGE (ABYTES + WBYTES)
#define NSTG 3
#define GSMEM (NSTG * STAGE)

template<int EPI>
__global__ void __launch_bounds__(512) gemm_mma(
    const __half* __restrict__ A, const __half* __restrict__ W,
    const float* __restrict__ bias, const float* __restrict__ res,
    float* __restrict__ C, __half* __restrict__ Ch,
    int M, int N, int K)
{
    extern __shared__ char smem[];
    const uint32_t sb = smem_u32(smem);
    const int tid  = threadIdx.x;
    const int bn = blockIdx.x * 256, bm = blockIdx.y * 128;
    const int w = tid >> 5, lane = tid & 31;
    const int wm = w & 3, wn = w >> 2;
    const int mrow = lane >> 3, mr = lane & 7;

    const __half* Ap = A + (size_t)bm * K;
    const __half* Wp = W + (size_t)bn * K;
    const int nch = K >> 5;

    const int lr = tid >> 2, lc = tid & 3;

    auto load_chunk = [&](int kt, int stg) {
        const uint32_t base = sb + stg * STAGE;
        const int off = kt * 32 + lc * 8;
        const uint32_t dA = base + lr * PITCH + lc * 16;
        asm volatile("cp.async.cg.shared.global [%0], [%1], 16;"
                     :: "r"(dA), "l"((const void*)(Ap + (size_t)lr * K + off)));
        const uint32_t dW = base + ABYTES + lr * PITCH + lc * 16;
        asm volatile("cp.async.cg.shared.global [%0], [%1], 16;"
                     :: "r"(dW), "l"((const void*)(Wp + (size_t)lr * K + off)));
        asm volatile("cp.async.cg.shared.global [%0], [%1], 16;"
                     :: "r"(dW + 128 * PITCH), "l"((const void*)(Wp + (size_t)(lr + 128) * K + off)));
        asm volatile("cp.async.commit_group;");
    };

    float acc[2][8][4];
#pragma unroll
    for (int i = 0; i < 2; i++)
#pragma unroll
        for (int j = 0; j < 8; j++)
#pragma unroll
            for (int q = 0; q < 4; q++) acc[i][j][q] = 0.f;

    load_chunk(0, 0);
    load_chunk(1, 1);

    int cs = 0, ls = 2;
    for (int kt = 0; kt < nch; kt++) {
        if (kt == nch - 1) {
            asm volatile("cp.async.wait_group 0;" ::: "memory");
        } else {
            asm volatile("cp.async.wait_group 1;" ::: "memory");
        }
        __syncthreads();
        if (kt + 2 < nch) {
            load_chunk(kt + 2, ls);
            ls = (ls == 2) ? 0 : ls + 1;
        }

        const uint32_t base = sb + cs * STAGE;
        cs = (cs == 2) ? 0 : cs + 1;
#pragma unroll
        for (int ks = 0; ks < 2; ks++) {
            uint32_t ah[2][4];
#pragma unroll
            for (int i = 0; i < 2; i++) {
                const int rowA = wm * 32 + i * 16 + (mrow & 1) * 8 + mr;
                const uint32_t cA = ks * 32 + (mrow >> 1) * 16;
                ldm4(ah[i], base + rowA * PITCH + cA);
            }
#pragma unroll
            for (int jp = 0; jp < 4; jp++) {
                const int rowB = wn * 64 + jp * 16 + (mrow >> 1) * 8 + mr;
                const uint32_t cB = ks * 32 + (mrow & 1) * 16;
                uint32_t t0[4];
                ldm4(t0, base + ABYTES + rowB * PITCH + cB);
#pragma unroll
                for (int i = 0; i < 2; i++) {
                    mma16816(acc[i][2*jp],     ah[i], t0[0], t0[1]);
                    mma16816(acc[i][2*jp + 1], ah[i], t0[2], t0[3]);
                }
            }
        }
    }
    __syncthreads();

    const int tg = lane >> 2, ti = lane & 3;
#pragma unroll
    for (int i = 0; i < 2; i++) {
#pragma unroll
        for (int j = 0; j < 8; j++) {
            const int gr0 = bm + wm * 32 + i * 16 + tg;
            const int gc  = bn + wn * 64 + j * 8 + ti * 2;
            const float b0 = bias[gc], b1 = bias[gc + 1];
#pragma unroll
            for (int hfl = 0; hfl < 2; hfl++) {
                const int gr = gr0 + hfl * 8;
                float v0 = acc[i][j][2*hfl + 0] + b0;
                float v1 = acc[i][j][2*hfl + 1] + b1;
                const size_t off = (size_t)gr * N + gc;
                if (EPI == 1) {
                    float2 rv = *(const float2*)(res + off);
                    v0 += rv.x; v1 += rv.y;
                }
                if (EPI == 2) {
                    float g0 = 0.5f * v0 * (1.0f + erff(v0 * 0.7071067811865476f));
                    float g1 = 0.5f * v1 * (1.0f + erff(v1 * 0.7071067811865476f));
                    v0 = g0 * g0; v1 = g1 * g1;
                }
                if (EPI == 2 || EPI == 3) {
                    *(__half2*)(Ch + off) = __floats2half2_rn(v0, v1);
                } else {
                    float2 ov; ov.x = v0; ov.y = v1;
                    *(float2*)(C + off) = ov;
                }
            }
        }
    }
}

// ------------------ fp32 -> fp16 convert ------------------------------------
__global__ void cvt_h(const float* __restrict__ in, __half* __restrict__ out, int n4)
{
    const int i = blockIdx.x * 256 + threadIdx.x;
    if (i >= n4) return;
    float4 v = ((const float4*)in)[i];
    ((__half2*)out)[2 * i]     = __floats2half2_rn(v.x, v.y);
    ((__half2*)out)[2 * i + 1] = __floats2half2_rn(v.z, v.w);
}

// ------------------ pack 3 bias vectors into one ----------------------------
__global__ void pack3(const float* __restrict__ a, const float* __restrict__ b,
                      const float* __restrict__ c, float* __restrict__ o)
{
    const int i = blockIdx.x * 256 + threadIdx.x;
    if (i < Dn)            o[i] = a[i];
    else if (i < 2 * Dn)   o[i] = b[i - Dn];
    else if (i < 3 * Dn)   o[i] = c[i - 2 * Dn];
}

// ------------- conv(q,k,v) + elu+1(q,k) + partial KV (HMMA) / Ksum ---------
// half2-vectorized conv; KV = K^T V via ldmatrix.trans + mma (fp16 in, fp32 acc).
#define CPITCH 144   // bytes per smem row: 72 halves (64 + 8 pad)
__global__ __launch_bounds__(256) void conv_pre(
    const __half* __restrict__ qkv,
    const float* __restrict__ qcw, const float* __restrict__ qcb,
    const float* __restrict__ kcw, const float* __restrict__ kcb,
    const float* __restrict__ vcw, const float* __restrict__ vcb)
{
    const int c = blockIdx.x, h = blockIdx.y, b = blockIdx.z;
    const int t  = threadIdx.x;
    const int p  = t & 31;           // channel pair -> channels 2p, 2p+1
    const int rl = t >> 5;           // 0..7, 8 rows each
    const int ch = 2 * p;
    const int w = t >> 5, lane = t & 31;
    const int mrow = lane >> 3, mr = lane & 7;
    const int dbase = (w & 3) * 16, ebase = (w >> 2) * 32;

    __shared__ __align__(16) char k2s[64 * CPITCH];
    __shared__ __align__(16) char v2s[64 * CPITCH];
    const uint32_t kbse = smem_u32(k2s);
    const uint32_t vbse = smem_u32(v2s);

    const float qw0a = qcw[ch*3+0], qw1a = qcw[ch*3+1], qw2a = qcw[ch*3+2], qba = qcb[ch];
    const float qw0b = qcw[ch*3+3], qw1b = qcw[ch*3+4], qw2b = qcw[ch*3+5], qbb = qcb[ch+1];
    const float kw0a = kcw[ch*3+0], kw1a = kcw[ch*3+1], kw2a = kcw[ch*3+2], kba = kcb[ch];
    const float kw0b = kcw[ch*3+3], kw1b = kcw[ch*3+4], kw2b = kcw[ch*3+5], kbb = kcb[ch+1];
    const float vw0a = vcw[ch*3+0], vw1a = vcw[ch*3+1], vw2a = vcw[ch*3+2], vba = vcb[ch];
    const float vw0b = vcw[ch*3+3], vw1b = vcw[ch*3+4], vw2b = vcw[ch*3+5], vbb = vcb[ch+1];

    float accm[4][4];
#pragma unroll
    for (int i = 0; i < 4; i++)
#pragma unroll
        for (int j = 0; j < 4; j++) accm[i][j] = 0.f;
    float ksacc = 0.f;

    for (int sub = 0; sub < 4; sub++) {
        __syncthreads();
        const int s0 = c * CHROWS + sub * 64 + rl * 8;
        const size_t qb0  = ((size_t)(b * Sn + s0)) * D3 + h * DKn + ch;
        const size_t q2b0 = ((size_t)(b * Sn + s0)) * Dn + h * DKn + ch;
        float2 qm1 = {0.f,0.f}, qm2 = {0.f,0.f};
        float2 km1 = {0.f,0.f}, km2 = {0.f,0.f};
        float2 vm1 = {0.f,0.f}, vm2 = {0.f,0.f};
        if (s0 >= 1) {
            qm1 = __half22float2(*(const __half2*)(qkv + qb0 - D3));
            km1 = __half22float2(*(const __half2*)(qkv + qb0 - D3 + Dn));
            vm1 = __half22float2(*(const __half2*)(qkv + qb0 - D3 + 2 * Dn));
        }
        if (s0 >= 2) {
            qm2 = __half22float2(*(const __half2*)(qkv + qb0 - 2 * D3));
            km2 = __half22float2(*(const __half2*)(qkv + qb0 - 2 * D3 + Dn));
            vm2 = __half22float2(*(const __half2*)(qkv + qb0 - 2 * D3 + 2 * Dn));
        }
#pragma unroll
        for (int i = 0; i < 8; i++) {
            const int r = rl * 8 + i;
            const size_t base = qb0 + (size_t)i * D3;

            float2 q0 = __half22float2(*(const __half2*)(qkv + base));
            float qcx = qw0a*qm2.x + qw1a*qm1.x + qw2a*q0.x + qba;
            float qcy = qw0b*qm2.y + qw1b*qm1.y + qw2b*q0.y + qbb;
            qcx = qcx > 0.f ? qcx + 1.f : expf(qcx);
            qcy = qcy > 0.f ? qcy + 1.f : expf(qcy);
            *(__half2*)(g_q2h + q2b0 + (size_t)i * Dn) = __floats2half2_rn(qcx, qcy);
            qm2 = qm1; qm1 = q0;

            float2 k0 = __half22float2(*(const __half2*)(qkv + base + Dn));
            float kcx = kw0a*km2.x + kw1a*km1.x + kw2a*k0.x + kba;
            float kcy = kw0b*km2.y + kw1b*km1.y + kw2b*k0.y + kbb;
            kcx = kcx > 0.f ? kcx + 1.f : expf(kcx);
            kcy = kcy > 0.f ? kcy + 1.f : expf(kcy);
            *(__half2*)(k2s + r * CPITCH + ch * 2) = __floats2half2_rn(kcx, kcy);
            km2 = km1; km1 = k0;

            float2 v0 = __half22float2(*(const __half2*)(qkv + base + 2 * Dn));
            float vcx = vw0a*vm2.x + vw1a*vm1.x + vw2a*v0.x + vba;
            float vcy = vw0b*vm2.y + vw1b*vm1.y + vw2b*v0.y + vbb;
            *(__half2*)(v2s + r * CPITCH + ch * 2) = __floats2half2_rn(vcx, vcy);
            vm2 = vm1; vm1 = v0;
        }
        __syncthreads();
        if (t < 64) {
#pragma unroll 8
            for (int r = 0; r < 64; r++)
                ksacc += __half2float(*(const __half*)(k2s + r * CPITCH + t * 2));
        }
        // KV += K^T V : M=64(d) x N=64(e) x K=64(s), warp = 16d x 32e
#pragma unroll
        for (int ksb = 0; ksb < 4; ksb++) {
            uint32_t a[4];
            // A = K^T tile: trans load from k2s[s][d]
            ldm4t(a, kbse + (ksb * 16 + (mrow >> 1) * 8 + mr) * CPITCH
                      + dbase * 2 + (mrow & 1) * 16);
#pragma unroll
            for (int jb = 0; jb < 2; jb++) {
                uint32_t t4[4];
                // B = V^T tile: trans load from v2s[s][e]
                ldm4t(t4, vbse + (ksb * 16 + (mrow & 1) * 8 + mr) * CPITCH
                          + (ebase + jb * 16) * 2 + (mrow >> 1) * 16);
                mma16816(accm[2*jb],     a, t4[0], t4[1]);
                mma16816(accm[2*jb + 1], a, t4[2], t4[3]);
            }
        }
    }

    const int bh = b * Hn + h;
    const size_t kvbase = ((size_t)bh * NCH + c) * (DKn * DKn);
    const int tg = lane >> 2, ti = lane & 3;
#pragma unroll
    for (int jn = 0; jn < 4; jn++) {
#pragma unroll
        for (int hfl = 0; hfl < 2; hfl++) {
            const int d = dbase + hfl * 8 + tg;
            const int e = ebase + jn * 8 + ti * 2;
            g_kvp[kvbase + (size_t)d * DKn + e]     = accm[jn][2*hfl];
            g_kvp[kvbase + (size_t)d * DKn + e + 1] = accm[jn][2*hfl + 1];
        }
    }
    if (t < 64)
        g_ksp[((size_t)bh * NCH + c) * DKn + t] = ksacc;
}

// ---- reduce partial KV (-> fp16 transposed) / Ksum over chunks ------------
__global__ void kv_reduce()
{
    const int bh = blockIdx.x, t = threadIdx.x;
    for (int idx = t; idx < DKn * DKn; idx += 256) {
        float s = 0.f;
#pragma unroll
        for (int c = 0; c < NCH; c++)
            s += g_kvp[((size_t)bh * NCH + c) * (DKn * DKn) + idx];
        const int d = idx >> 6, e = idx & 63;
        g_kvhT[(size_t)bh * (DKn * DKn) + e * DKn + d] = __float2half_rn(s);
    }
    if (t < DKn) {
        float s = 0.f;
#pragma unroll
        for (int c = 0; c < NCH; c++)
            s += g_ksp[((size_t)bh * NCH + c) * DKn + t];
        g_ks[(size_t)bh * DKn + t] = s;
    }
}

// -------------- attn apply via HMMA: Vn = (Q @ KV) / (Q.(Ksum+eps)) --------
#define APITCH 144
__global__ __launch_bounds__(128) void attn_apply()
{
    const int st = blockIdx.x, h = blockIdx.y, b = blockIdx.z;
    const int t = threadIdx.x;
    const int bh = b * Hn + h;
    const int w = t >> 5, lane = t & 31;
    const int mrow = lane >> 3, mr = lane & 7;

    __shared__ __align__(16) char qsmem[64 * APITCH];
    __shared__ __align__(16) char ksmem[64 * APITCH];
    __shared__ float kss[64];
    __shared__ float zinv[64];

    const uint32_t qb = smem_u32(qsmem);
    const uint32_t kb = smem_u32(ksmem);

    for (int idx = t; idx < 2048; idx += 128) {
        const int r = idx >> 5, c2 = idx & 31;
        *(__half2*)(qsmem + r * APITCH + c2 * 4) =
            *(const __half2*)(g_q2h + ((size_t)(b * Sn + st * 64 + r)) * Dn
                              + h * DKn + c2 * 2);
        *(__half2*)(ksmem + r * APITCH + c2 * 4) =
            *(const __half2*)(g_kvhT + (size_t)bh * (DKn * DKn) + r * DKn + c2 * 2);
    }
    if (t < DKn) kss[t] = g_ks[(size_t)bh * DKn + t] + EPSA;
    __syncthreads();

    {
        const int s = t >> 1, part = t & 1;
        float z = 0.f;
        const char* rp = qsmem + s * APITCH + part * 64;
#pragma unroll
        for (int d = 0; d < 32; d++)
            z += __half2float(*(const __half*)(rp + d * 2)) * kss[part * 32 + d];
        z += __shfl_xor_sync(0xffffffffu, z, 1);
        if (part == 0) zinv[s] = 1.0f / z;
    }

    float acc[8][4];
#pragma unroll
    for (int j = 0; j < 8; j++)
#pragma unroll
        for (int q = 0; q < 4; q++) acc[j][q] = 0.f;

#pragma unroll
    for (int ks = 0; ks < 4; ks++) {
        uint32_t ah[4];
        const int rowA = w * 16 + (mrow & 1) * 8 + mr;
        ldm4(ah, qb + rowA * APITCH + ks * 32 + (mrow >> 1) * 16);
#pragma unroll
        for (int jp = 0; jp < 4; jp++) {
            const int rowB = jp * 16 + (mrow >> 1) * 8 + mr;
            uint32_t t0[4];
            ldm4(t0, kb + rowB * APITCH + ks * 32 + (mrow & 1) * 16);
            mma16816(acc[2*jp],     ah, t0[0], t0[1]);
            mma16816(acc[2*jp + 1], ah, t0[2], t0[3]);
        }
    }
    __syncthreads();

    const int tg = lane >> 2, ti = lane & 3;
#pragma unroll
    for (int j = 0; j < 8; j++) {
        const int col = j * 8 + ti * 2;
#pragma unroll
        for (int hfl = 0; hfl < 2; hfl++) {
            const int row = w * 16 + hfl * 8 + tg;
            const float zi = zinv[row];
            const size_t off = ((size_t)(b * Sn + st * 64 + row)) * Dn
                               + h * DKn + col;
            *(__half2*)(g_ath + off) =
                __floats2half2_rn(zi * acc[j][2*hfl], zi * acc[j][2*hfl + 1]);
        }
    }
}

// -------------------- LayerNorm (D=512), warp per row ----------------------
template<bool SPLIT>
__global__ __launch_bounds__(256) void ln_kernel(
    const float* __restrict__ in, const float* __restrict__ gw,
    const float* __restrict__ bw, float* __restrict__ out,
    __half* __restrict__ oh)
{
    const int warp = threadIdx.x >> 5, lane = threadIdx.x & 31;
    const int row = blockIdx.x * 8 + warp;
    const float4* rp = (const float4*)(in + (size_t)row * Dn);

    float4 v[4];
    float s1 = 0.f, s2 = 0.f;
#pragma unroll
    for (int i = 0; i < 4; i++) {
        v[i] = rp[lane + i * 32];
        s1 += v[i].x + v[i].y + v[i].z + v[i].w;
        s2 += v[i].x * v[i].x + v[i].y * v[i].y + v[i].z * v[i].z + v[i].w * v[i].w;
    }
#pragma unroll
    for (int o = 16; o > 0; o >>= 1) {
        s1 += __shfl_xor_sync(0xffffffffu, s1, o);
        s2 += __shfl_xor_sync(0xffffffffu, s2, o);
    }
    const float m = s1 * (1.0f / Dn);
    const float rr = rsqrtf(s2 * (1.0f / Dn) - m * m + LNEPS);

    float4* op = (float4*)(out + (size_t)row * Dn);
    const float4* gp = (const float4*)gw;
    const float4* bp = (const float4*)bw;
#pragma unroll
    for (int i = 0; i < 4; i++) {
        const float4 g4 = gp[lane + i * 32];
        const float4 b4 = bp[lane + i * 32];
        float4 o4;
        o4.x = (v[i].x - m) * rr * g4.x + b4.x;
        o4.y = (v[i].y - m) * rr * g4.y + b4.y;
        o4.z = (v[i].z - m) * rr * g4.z + b4.z;
        o4.w = (v[i].w - m) * rr * g4.w + b4.w;
        op[lane + i * 32] = o4;
        if (SPLIT) {
            __half2* hp = (__half2*)(oh + (size_t)row * Dn) + 2 * (lane + i * 32);
            hp[0] = __floats2half2_rn(o4.x, o4.y);
            hp[1] = __floats2half2_rn(o4.z, o4.w);
        }
    }
}

// ------------------------------- launch ------------------------------------
extern "C" void kernel_launch(void* const* d_in, const int* in_sizes, int n_in,
                              void* d_out, int out_size)
{
    const float* x    = (const float*)d_in[0];
    const float* wq   = (const float*)d_in[1];
    const float* bq   = (const float*)d_in[2];
    const float* wk   = (const float*)d_in[3];
    const float* bk   = (const float*)d_in[4];
    const float* wv   = (const float*)d_in[5];
    const float* bv   = (const float*)d_in[6];
    const float* wo   = (const float*)d_in[7];
    const float* bo   = (const float*)d_in[8];
    const float* qcw  = (const float*)d_in[9];
    const float* qcb  = (const float*)d_in[10];
    const float* kcw  = (const float*)d_in[11];
    const float* kcb  = (const float*)d_in[12];
    const float* vcw  = (const float*)d_in[13];
    const float* vcb  = (const float*)d_in[14];
    const float* w1   = (const float*)d_in[15];
    const float* b1   = (const float*)d_in[16];
    const float* w2   = (const float*)d_in[17];
    const float* b2   = (const float*)d_in[18];
    const float* ln1g = (const float*)d_in[19];
    const float* ln1b = (const float*)d_in[20];
    const float* ln2g = (const float*)d_in[21];
    const float* ln2b = (const float*)d_in[22];
    float* out = (float*)d_out;

    float *py, *px1, *py2, *pbqkv;
    cudaGetSymbolAddress((void**)&py,    g_y);
    cudaGetSymbolAddress((void**)&px1,   g_x1);
    cudaGetSymbolAddress((void**)&py2,   g_y2);
    cudaGetSymbolAddress((void**)&pbqkv, g_bqkv);

    __half *pqkvh, *pxh, *path, *px1h, *phh;
    __half *pwqkvh, *pwoh, *pw1h, *pw2h;
    cudaGetSymbolAddress((void**)&pqkvh,  g_qkvh);
    cudaGetSymbolAddress((void**)&pxh,    g_xh);
    cudaGetSymbolAddress((void**)&path,   g_ath);
    cudaGetSymbolAddress((void**)&px1h,   g_x1h);
    cudaGetSymbolAddress((void**)&phh,    g_hh);
    cudaGetSymbolAddress((void**)&pwqkvh, g_wqkvh);
    cudaGetSymbolAddress((void**)&pwoh,   g_woh);
    cudaGetSymbolAddress((void**)&pw1h,   g_w1h);
    cudaGetSymbolAddress((void**)&pw2h,   g_w2h);

    cudaFuncSetAttribute(gemm_mma<0>, cudaFuncAttributeMaxDynamicSharedMemorySize, GSMEM);
    cudaFuncSetAttribute(gemm_mma<1>, cudaFuncAttributeMaxDynamicSharedMemorySize, GSMEM);
    cudaFuncSetAttribute(gemm_mma<2>, cudaFuncAttributeMaxDynamicSharedMemorySize, GSMEM);
    cudaFuncSetAttribute(gemm_mma<3>, cudaFuncAttributeMaxDynamicSharedMemorySize, GSMEM);

    auto cvt = [](const float* p, __half* h, size_t n) {
        int n4 = (int)(n / 4);
        cvt_h<<<(n4 + 255) / 256, 256>>>(p, h, n4);
    };

    const dim3 gridQKV(D3 / 256, Mn / 128);   // (6, 256)
    const dim3 gridD(Dn / 256, Mn / 128);     // (2, 256)
    const dim3 gridF(DFFn / 256, Mn / 128);   // (4, 256)

    // Launches 0-4 (launch #5, the ncu-profiled one, is the merged QKV GEMM)
    cvt(x,  pxh, (size_t)Mn * Dn);
    cvt(wq, pwqkvh,                       (size_t)Dn * Dn);
    cvt(wk, pwqkvh + (size_t)Dn * Dn,     (size_t)Dn * Dn);
    cvt(wv, pwqkvh + (size_t)2 * Dn * Dn, (size_t)Dn * Dn);
    pack3<<<(D3 + 255) / 256, 256>>>(bq, bk, bv, pbqkv);

    // merged QKV projection -> fp16 (launch #5)
    gemm_mma<3><<<gridQKV, 512, GSMEM>>>(pxh, pwqkvh, pbqkv, nullptr,
                                         nullptr, pqkvh, Mn, D3, Dn);

    // remaining weight converts
    cvt(wo, pwoh, (size_t)Dn * Dn);
    cvt(w1, pw1h, (size_t)DFFn * Dn);
    cvt(w2, pw2h, (size_t)Dn * DFFn);

    // depthwise conv + elu+1 + partial KV (HMMA) / Ksum
    conv_pre<<<dim3(NCH, Hn, Bn), 256>>>(pqkvh, qcw, qcb, kcw, kcb, vcw, vcb);
    kv_reduce<<<Bn * Hn, 256>>>();
    attn_apply<<<dim3(Sn / 64, Hn, Bn), 128>>>();

    // output projection + residual, then LN1 (LN1 also emits fp16)
    gemm_mma<1><<<gridD, 512, GSMEM>>>(path, pwoh, bo, x, py, nullptr, Mn, Dn, Dn);
    ln_kernel<true><<<Mn / 8, 256>>>(py, ln1g, ln1b, px1, px1h);

    // FFN: gelu^2 -> fp16 h; FFN2 consumes it (K=1024)
    gemm_mma<2><<<gridF, 512, GSMEM>>>(px1h, pw1h, b1, nullptr, nullptr, phh, Mn, DFFn, Dn);
    gemm_mma<1><<<gridD, 512, GSMEM>>>(phh, pw2h, b2, px1, py2, nullptr, Mn, Dn, DFFn);
    ln_kernel<false><<<Mn / 8, 256>>>(py2, ln2g, ln2b, out, nullptr);
}

// round 11
// speedup vs baseline: 4.6507x; 1.0177x over previous
#include <cuda_runtime.h>
#include <cuda_fp16.h>
#include <cstdint>

#define Bn 8
#define Sn 4096
#define Dn 512
#define Hn 8
#define DKn 64
#define DFFn 1024
#define Mn (Bn*Sn)          // 32768 rows
#define NCH 16              // seq chunks for partial KV
#define CHROWS 256
#define EPSA 1e-6f
#define LNEPS 1e-5f
#define D3 (3*Dn)           // 1536

// ---------------- scratch (device globals; no allocation allowed) ----------
__device__ float g_kvp [(size_t)Bn*Hn*NCH*DKn*DKn];
__device__ float g_ksp [(size_t)Bn*Hn*NCH*DKn];
__device__ float g_ks  [(size_t)Bn*Hn*DKn];
__device__ float g_bqkv[D3];

// fp16 buffers
__device__ __half g_qkvh[(size_t)Mn*D3];        // merged q|k|v projections
__device__ __half g_q2h [(size_t)Mn*Dn];        // elu(conv(q))+1
__device__ __half g_kvhT[(size_t)Bn*Hn*DKn*DKn];// KV transposed [bh][e][d]
__device__ __half g_xh  [(size_t)Mn*Dn];
__device__ __half g_ath [(size_t)Mn*Dn];
__device__ __half g_yh  [(size_t)Mn*Dn];        // O-proj + residual (fp16)
__device__ __half g_x1h [(size_t)Mn*Dn];        // LN1 output (fp16)
__device__ __half g_hh  [(size_t)Mn*DFFn];
__device__ __half g_y2h [(size_t)Mn*Dn];        // FFN2 + residual (fp16)
__device__ __half g_wqkvh[(size_t)D3*Dn];
__device__ __half g_woh [Dn*Dn];
__device__ __half g_w1h [DFFn*Dn];
__device__ __half g_w2h [Dn*DFFn];

// ------------------------- PTX helpers -------------------------------------
__device__ __forceinline__ uint32_t smem_u32(const void* p) {
    uint32_t a;
    asm("{ .reg .u64 t; cvta.to.shared.u64 t, %1; cvt.u32.u64 %0, t; }"
        : "=r"(a) : "l"(p));
    return a;
}

__device__ __forceinline__ void ldm4(uint32_t* r, uint32_t addr) {
    asm volatile("ldmatrix.sync.aligned.m8n8.x4.shared.b16 {%0,%1,%2,%3}, [%4];"
                 : "=r"(r[0]), "=r"(r[1]), "=r"(r[2]), "=r"(r[3]) : "r"(addr));
}

__device__ __forceinline__ void ldm4t(uint32_t* r, uint32_t addr) {
    asm volatile("ldmatrix.sync.aligned.m8n8.x4.trans.shared.b16 {%0,%1,%2,%3}, [%4];"
                 : "=r"(r[0]), "=r"(r[1]), "=r"(r[2]), "=r"(r[3]) : "r"(addr));
}

__device__ __forceinline__ void mma16816(float* c, const uint32_t* a,
                                         uint32_t b0, uint32_t b1) {
    asm volatile(
        "mma.sync.aligned.m16n8k16.row.col.f32.f16.f16.f32 "
        "{%0,%1,%2,%3}, {%4,%5,%6,%7}, {%8,%9}, {%0,%1,%2,%3};"
        : "+f"(c[0]), "+f"(c[1]), "+f"(c[2]), "+f"(c[3])
        : "r"(a[0]), "r"(a[1]), "r"(a[2]), "r"(a[3]), "r"(b0), "r"(b1));
}

// ================= HMMA fp16 GEMM: C = A(fp16) @ W(fp16)^T + bias ==========
// EPI: 1 = bias + fp32 res -> fp16 ; 2 = gelu(x)^2 -> fp16 ;
//      3 = bias -> fp16      ; 4 = bias + fp16 res -> fp16
#define PITCH 80
#define ABYTES (128 * PITCH)
#define WBYTES (256 * PITCH)
#define STAGE (ABYTES + WBYTES)
#define NSTG 3
#define GSMEM (NSTG * STAGE)

template<int EPI>
__global__ void __launch_bounds__(512) gemm_mma(
    const __half* __restrict__ A, const __half* __restrict__ W,
    const float* __restrict__ bias, const float* __restrict__ res,
    const __half* __restrict__ resh, __half* __restrict__ Ch,
    int M, int N, int K)
{
    extern __shared__ char smem[];
    const uint32_t sb = smem_u32(smem);
    const int tid  = threadIdx.x;
    const int bn = blockIdx.x * 256, bm = blockIdx.y * 128;
    const int w = tid >> 5, lane = tid & 31;
    const int wm = w & 3, wn = w >> 2;
    const int mrow = lane >> 3, mr = lane & 7;

    const __half* Ap = A + (size_t)bm * K;
    const __half* Wp = W + (size_t)bn * K;
    const int nch = K >> 5;

    const int lr = tid >> 2, lc = tid & 3;

    auto load_chunk = [&](int kt, int stg) {
        const uint32_t base = sb + stg * STAGE;
        const int off = kt * 32 + lc * 8;
        const uint32_t dA = base + lr * PITCH + lc * 16;
        asm volatile("cp.async.cg.shared.global [%0], [%1], 16;"
                     :: "r"(dA), "l"((const void*)(Ap + (size_t)lr * K + off)));
        const uint32_t dW = base + ABYTES + lr * PITCH + lc * 16;
        asm volatile("cp.async.cg.shared.global [%0], [%1], 16;"
                     :: "r"(dW), "l"((const void*)(Wp + (size_t)lr * K + off)));
        asm volatile("cp.async.cg.shared.global [%0], [%1], 16;"
                     :: "r"(dW + 128 * PITCH), "l"((const void*)(Wp + (size_t)(lr + 128) * K + off)));
        asm volatile("cp.async.commit_group;");
    };

    float acc[2][8][4];
#pragma unroll
    for (int i = 0; i < 2; i++)
#pragma unroll
        for (int j = 0; j < 8; j++)
#pragma unroll
            for (int q = 0; q < 4; q++) acc[i][j][q] = 0.f;

    load_chunk(0, 0);
    load_chunk(1, 1);

    int cs = 0, ls = 2;
    for (int kt = 0; kt < nch; kt++) {
        if (kt == nch - 1) {
            asm volatile("cp.async.wait_group 0;" ::: "memory");
        } else {
            asm volatile("cp.async.wait_group 1;" ::: "memory");
        }
        __syncthreads();
        if (kt + 2 < nch) {
            load_chunk(kt + 2, ls);
            ls = (ls == 2) ? 0 : ls + 1;
        }

        const uint32_t base = sb + cs * STAGE;
        cs = (cs == 2) ? 0 : cs + 1;
#pragma unroll
        for (int ks = 0; ks < 2; ks++) {
            uint32_t ah[2][4];
#pragma unroll
            for (int i = 0; i < 2; i++) {
                const int rowA = wm * 32 + i * 16 + (mrow & 1) * 8 + mr;
                const uint32_t cA = ks * 32 + (mrow >> 1) * 16;
                ldm4(ah[i], base + rowA * PITCH + cA);
            }
#pragma unroll
            for (int jp = 0; jp < 4; jp++) {
                const int rowB = wn * 64 + jp * 16 + (mrow >> 1) * 8 + mr;
                const uint32_t cB = ks * 32 + (mrow & 1) * 16;
                uint32_t t0[4];
                ldm4(t0, base + ABYTES + rowB * PITCH + cB);
#pragma unroll
                for (int i = 0; i < 2; i++) {
                    mma16816(acc[i][2*jp],     ah[i], t0[0], t0[1]);
                    mma16816(acc[i][2*jp + 1], ah[i], t0[2], t0[3]);
                }
            }
        }
    }
    __syncthreads();

    const int tg = lane >> 2, ti = lane & 3;
#pragma unroll
    for (int i = 0; i < 2; i++) {
#pragma unroll
        for (int j = 0; j < 8; j++) {
            const int gr0 = bm + wm * 32 + i * 16 + tg;
            const int gc  = bn + wn * 64 + j * 8 + ti * 2;
            const float b0 = bias[gc], b1 = bias[gc + 1];
#pragma unroll
            for (int hfl = 0; hfl < 2; hfl++) {
                const int gr = gr0 + hfl * 8;
                float v0 = acc[i][j][2*hfl + 0] + b0;
                float v1 = acc[i][j][2*hfl + 1] + b1;
                const size_t off = (size_t)gr * N + gc;
                if (EPI == 1) {
                    float2 rv = *(const float2*)(res + off);
                    v0 += rv.x; v1 += rv.y;
                }
                if (EPI == 4) {
                    float2 rv = __half22float2(*(const __half2*)(resh + off));
                    v0 += rv.x; v1 += rv.y;
                }
                if (EPI == 2) {
                    float g0 = 0.5f * v0 * (1.0f + erff(v0 * 0.7071067811865476f));
                    float g1 = 0.5f * v1 * (1.0f + erff(v1 * 0.7071067811865476f));
                    v0 = g0 * g0; v1 = g1 * g1;
                }
                *(__half2*)(Ch + off) = __floats2half2_rn(v0, v1);
            }
        }
    }
}

// ------------------ fp32 -> fp16 convert ------------------------------------
__global__ void cvt_h(const float* __restrict__ in, __half* __restrict__ out, int n4)
{
    const int i = blockIdx.x * 256 + threadIdx.x;
    if (i >= n4) return;
    float4 v = ((const float4*)in)[i];
    ((__half2*)out)[2 * i]     = __floats2half2_rn(v.x, v.y);
    ((__half2*)out)[2 * i + 1] = __floats2half2_rn(v.z, v.w);
}

// ------------------ pack 3 bias vectors into one ----------------------------
__global__ void pack3(const float* __restrict__ a, const float* __restrict__ b,
                      const float* __restrict__ c, float* __restrict__ o)
{
    const int i = blockIdx.x * 256 + threadIdx.x;
    if (i < Dn)            o[i] = a[i];
    else if (i < 2 * Dn)   o[i] = b[i - Dn];
    else if (i < 3 * Dn)   o[i] = c[i - 2 * Dn];
}

// ------------- conv(q,k,v) + elu+1(q,k) + partial KV (HMMA) / Ksum ---------
#define CPITCH 144
__global__ __launch_bounds__(256) void conv_pre(
    const __half* __restrict__ qkv,
    const float* __restrict__ qcw, const float* __restrict__ qcb,
    const float* __restrict__ kcw, const float* __restrict__ kcb,
    const float* __restrict__ vcw, const float* __restrict__ vcb)
{
    const int c = blockIdx.x, h = blockIdx.y, b = blockIdx.z;
    const int t  = threadIdx.x;
    const int p  = t & 31;
    const int rl = t >> 5;
    const int ch = 2 * p;
    const int w = t >> 5, lane = t & 31;
    const int mrow = lane >> 3, mr = lane & 7;
    const int dbase = (w & 3) * 16, ebase = (w >> 2) * 32;

    __shared__ __align__(16) char k2s[64 * CPITCH];
    __shared__ __align__(16) char v2s[64 * CPITCH];
    const uint32_t kbse = smem_u32(k2s);
    const uint32_t vbse = smem_u32(v2s);

    const float qw0a = qcw[ch*3+0], qw1a = qcw[ch*3+1], qw2a = qcw[ch*3+2], qba = qcb[ch];
    const float qw0b = qcw[ch*3+3], qw1b = qcw[ch*3+4], qw2b = qcw[ch*3+5], qbb = qcb[ch+1];
    const float kw0a = kcw[ch*3+0], kw1a = kcw[ch*3+1], kw2a = kcw[ch*3+2], kba = kcb[ch];
    const float kw0b = kcw[ch*3+3], kw1b = kcw[ch*3+4], kw2b = kcw[ch*3+5], kbb = kcb[ch+1];
    const float vw0a = vcw[ch*3+0], vw1a = vcw[ch*3+1], vw2a = vcw[ch*3+2], vba = vcb[ch];
    const float vw0b = vcw[ch*3+3], vw1b = vcw[ch*3+4], vw2b = vcw[ch*3+5], vbb = vcb[ch+1];

    float accm[4][4];
#pragma unroll
    for (int i = 0; i < 4; i++)
#pragma unroll
        for (int j = 0; j < 4; j++) accm[i][j] = 0.f;
    float ksacc = 0.f;

    for (int sub = 0; sub < 4; sub++) {
        __syncthreads();
        const int s0 = c * CHROWS + sub * 64 + rl * 8;
        const size_t qb0  = ((size_t)(b * Sn + s0)) * D3 + h * DKn + ch;
        const size_t q2b0 = ((size_t)(b * Sn + s0)) * Dn + h * DKn + ch;
        float2 qm1 = {0.f,0.f}, qm2 = {0.f,0.f};
        float2 km1 = {0.f,0.f}, km2 = {0.f,0.f};
        float2 vm1 = {0.f,0.f}, vm2 = {0.f,0.f};
        if (s0 >= 1) {
            qm1 = __half22float2(*(const __half2*)(qkv + qb0 - D3));
            km1 = __half22float2(*(const __half2*)(qkv + qb0 - D3 + Dn));
            vm1 = __half22float2(*(const __half2*)(qkv + qb0 - D3 + 2 * Dn));
        }
        if (s0 >= 2) {
            qm2 = __half22float2(*(const __half2*)(qkv + qb0 - 2 * D3));
            km2 = __half22float2(*(const __half2*)(qkv + qb0 - 2 * D3 + Dn));
            vm2 = __half22float2(*(const __half2*)(qkv + qb0 - 2 * D3 + 2 * Dn));
        }
#pragma unroll
        for (int i = 0; i < 8; i++) {
            const int r = rl * 8 + i;
            const size_t base = qb0 + (size_t)i * D3;

            float2 q0 = __half22float2(*(const __half2*)(qkv + base));
            float qcx = qw0a*qm2.x + qw1a*qm1.x + qw2a*q0.x + qba;
            float qcy = qw0b*qm2.y + qw1b*qm1.y + qw2b*q0.y + qbb;
            qcx = qcx > 0.f ? qcx + 1.f : expf(qcx);
            qcy = qcy > 0.f ? qcy + 1.f : expf(qcy);
            *(__half2*)(g_q2h + q2b0 + (size_t)i * Dn) = __floats2half2_rn(qcx, qcy);
            qm2 = qm1; qm1 = q0;

            float2 k0 = __half22float2(*(const __half2*)(qkv + base + Dn));
            float kcx = kw0a*km2.x + kw1a*km1.x + kw2a*k0.x + kba;
            float kcy = kw0b*km2.y + kw1b*km1.y + kw2b*k0.y + kbb;
            kcx = kcx > 0.f ? kcx + 1.f : expf(kcx);
            kcy = kcy > 0.f ? kcy + 1.f : expf(kcy);
            *(__half2*)(k2s + r * CPITCH + ch * 2) = __floats2half2_rn(kcx, kcy);
            km2 = km1; km1 = k0;

            float2 v0 = __half22float2(*(const __half2*)(qkv + base + 2 * Dn));
            float vcx = vw0a*vm2.x + vw1a*vm1.x + vw2a*v0.x + vba;
            float vcy = vw0b*vm2.y + vw1b*vm1.y + vw2b*v0.y + vbb;
            *(__half2*)(v2s + r * CPITCH + ch * 2) = __floats2half2_rn(vcx, vcy);
            vm2 = vm1; vm1 = v0;
        }
        __syncthreads();
        if (t < 64) {
#pragma unroll 8
            for (int r = 0; r < 64; r++)
                ksacc += __half2float(*(const __half*)(k2s + r * CPITCH + t * 2));
        }
#pragma unroll
        for (int ksb = 0; ksb < 4; ksb++) {
            uint32_t a[4];
            ldm4t(a, kbse + (ksb * 16 + (mrow >> 1) * 8 + mr) * CPITCH
                      + dbase * 2 + (mrow & 1) * 16);
#pragma unroll
            for (int jb = 0; jb < 2; jb++) {
                uint32_t t4[4];
                ldm4t(t4, vbse + (ksb * 16 + (mrow & 1) * 8 + mr) * CPITCH
                          + (ebase + jb * 16) * 2 + (mrow >> 1) * 16);
                mma16816(accm[2*jb],     a, t4[0], t4[1]);
                mma16816(accm[2*jb + 1], a, t4[2], t4[3]);
            }
        }
    }

    const int bh = b * Hn + h;
    const size_t kvbase = ((size_t)bh * NCH + c) * (DKn * DKn);
    const int tg = lane >> 2, ti = lane & 3;
#pragma unroll
    for (int jn = 0; jn < 4; jn++) {
#pragma unroll
        for (int hfl = 0; hfl < 2; hfl++) {
            const int d = dbase + hfl * 8 + tg;
            const int e = ebase + jn * 8 + ti * 2;
            g_kvp[kvbase + (size_t)d * DKn + e]     = accm[jn][2*hfl];
            g_kvp[kvbase + (size_t)d * DKn + e + 1] = accm[jn][2*hfl + 1];
        }
    }
    if (t < 64)
        g_ksp[((size_t)bh * NCH + c) * DKn + t] = ksacc;
}

// ---- reduce partial KV (-> fp16 transposed) / Ksum over chunks ------------
__global__ void kv_reduce()
{
    const int bh = blockIdx.x, t = threadIdx.x;
    for (int idx = t; idx < DKn * DKn; idx += 256) {
        float s = 0.f;
#pragma unroll
        for (int c = 0; c < NCH; c++)
            s += g_kvp[((size_t)bh * NCH + c) * (DKn * DKn) + idx];
        const int d = idx >> 6, e = idx & 63;
        g_kvhT[(size_t)bh * (DKn * DKn) + e * DKn + d] = __float2half_rn(s);
    }
    if (t < DKn) {
        float s = 0.f;
#pragma unroll
        for (int c = 0; c < NCH; c++)
            s += g_ksp[((size_t)bh * NCH + c) * DKn + t];
        g_ks[(size_t)bh * DKn + t] = s;
    }
}

// -------------- attn apply via HMMA: Vn = (Q @ KV) / (Q.(Ksum+eps)) --------
#define APITCH 144
__global__ __launch_bounds__(128) void attn_apply()
{
    const int st = blockIdx.x, h = blockIdx.y, b = blockIdx.z;
    const int t = threadIdx.x;
    const int bh = b * Hn + h;
    const int w = t >> 5, lane = t & 31;
    const int mrow = lane >> 3, mr = lane & 7;

    __shared__ __align__(16) char qsmem[64 * APITCH];
    __shared__ __align__(16) char ksmem[64 * APITCH];
    __shared__ float kss[64];
    __shared__ float zinv[64];

    const uint32_t qb = smem_u32(qsmem);
    const uint32_t kb = smem_u32(ksmem);

    for (int idx = t; idx < 2048; idx += 128) {
        const int r = idx >> 5, c2 = idx & 31;
        *(__half2*)(qsmem + r * APITCH + c2 * 4) =
            *(const __half2*)(g_q2h + ((size_t)(b * Sn + st * 64 + r)) * Dn
                              + h * DKn + c2 * 2);
        *(__half2*)(ksmem + r * APITCH + c2 * 4) =
            *(const __half2*)(g_kvhT + (size_t)bh * (DKn * DKn) + r * DKn + c2 * 2);
    }
    if (t < DKn) kss[t] = g_ks[(size_t)bh * DKn + t] + EPSA;
    __syncthreads();

    {
        const int s = t >> 1, part = t & 1;
        float z = 0.f;
        const char* rp = qsmem + s * APITCH + part * 64;
#pragma unroll
        for (int d = 0; d < 32; d++)
            z += __half2float(*(const __half*)(rp + d * 2)) * kss[part * 32 + d];
        z += __shfl_xor_sync(0xffffffffu, z, 1);
        if (part == 0) zinv[s] = 1.0f / z;
    }

    float acc[8][4];
#pragma unroll
    for (int j = 0; j < 8; j++)
#pragma unroll
        for (int q = 0; q < 4; q++) acc[j][q] = 0.f;

#pragma unroll
    for (int ks = 0; ks < 4; ks++) {
        uint32_t ah[4];
        const int rowA = w * 16 + (mrow & 1) * 8 + mr;
        ldm4(ah, qb + rowA * APITCH + ks * 32 + (mrow >> 1) * 16);
#pragma unroll
        for (int jp = 0; jp < 4; jp++) {
            const int rowB = jp * 16 + (mrow >> 1) * 8 + mr;
            uint32_t t0[4];
            ldm4(t0, kb + rowB * APITCH + ks * 32 + (mrow & 1) * 16);
            mma16816(acc[2*jp],     ah, t0[0], t0[1]);
            mma16816(acc[2*jp + 1], ah, t0[2], t0[3]);
        }
    }
    __syncthreads();

    const int tg = lane >> 2, ti = lane & 3;
#pragma unroll
    for (int j = 0; j < 8; j++) {
        const int col = j * 8 + ti * 2;
#pragma unroll
        for (int hfl = 0; hfl < 2; hfl++) {
            const int row = w * 16 + hfl * 8 + tg;
            const float zi = zinv[row];
            const size_t off = ((size_t)(b * Sn + st * 64 + row)) * Dn
                               + h * DKn + col;
            *(__half2*)(g_ath + off) =
                __floats2half2_rn(zi * acc[j][2*hfl], zi * acc[j][2*hfl + 1]);
        }
    }
}

// -------------------- LayerNorm (D=512), warp per row, fp16 in -------------
// OUTF32: true -> fp32 out (final output); false -> fp16 oh only
template<bool OUTF32>
__global__ __launch_bounds__(256) void ln_kernel(
    const __half* __restrict__ in, const float* __restrict__ gw,
    const float* __restrict__ bw, float* __restrict__ out,
    __half* __restrict__ oh)
{
    const int warp = threadIdx.x >> 5, lane = threadIdx.x & 31;
    const int row = blockIdx.x * 8 + warp;
    const uint4* rp = (const uint4*)(in + (size_t)row * Dn);

    float vals[16];
    float s1 = 0.f, s2 = 0.f;
#pragma unroll
    for (int i = 0; i < 2; i++) {
        uint4 raw = rp[lane + i * 32];
        const uint32_t u[4] = {raw.x, raw.y, raw.z, raw.w};
#pragma unroll
        for (int k = 0; k < 4; k++) {
            float2 f = __half22float2(*(const __half2*)&u[k]);
            vals[i * 8 + 2 * k]     = f.x;
            vals[i * 8 + 2 * k + 1] = f.y;
            s1 += f.x + f.y;
            s2 += f.x * f.x + f.y * f.y;
        }
    }
#pragma unroll
    for (int o = 16; o > 0; o >>= 1) {
        s1 += __shfl_xor_sync(0xffffffffu, s1, o);
        s2 += __shfl_xor_sync(0xffffffffu, s2, o);
    }
    const float m = s1 * (1.0f / Dn);
    const float rr = rsqrtf(s2 * (1.0f / Dn) - m * m + LNEPS);

#pragma unroll
    for (int i = 0; i < 2; i++) {
        const int c0 = (lane + i * 32) * 8;
        float o8[8];
#pragma unroll
        for (int k = 0; k < 2; k++) {
            const float4 g4 = *(const float4*)(gw + c0 + k * 4);
            const float4 b4 = *(const float4*)(bw + c0 + k * 4);
            o8[k*4+0] = (vals[i*8 + k*4 + 0] - m) * rr * g4.x + b4.x;
            o8[k*4+1] = (vals[i*8 + k*4 + 1] - m) * rr * g4.y + b4.y;
            o8[k*4+2] = (vals[i*8 + k*4 + 2] - m) * rr * g4.z + b4.z;
            o8[k*4+3] = (vals[i*8 + k*4 + 3] - m) * rr * g4.w + b4.w;
        }
        if (OUTF32) {
#pragma unroll
            for (int k = 0; k < 2; k++) {
                float4 o4; o4.x = o8[k*4]; o4.y = o8[k*4+1];
                o4.z = o8[k*4+2]; o4.w = o8[k*4+3];
                *(float4*)(out + (size_t)row * Dn + c0 + k * 4) = o4;
            }
        } else {
            uint4 packed;
            __half2 p0 = __floats2half2_rn(o8[0], o8[1]);
            __half2 p1 = __floats2half2_rn(o8[2], o8[3]);
            __half2 p2 = __floats2half2_rn(o8[4], o8[5]);
            __half2 p3 = __floats2half2_rn(o8[6], o8[7]);
            packed.x = *(uint32_t*)&p0; packed.y = *(uint32_t*)&p1;
            packed.z = *(uint32_t*)&p2; packed.w = *(uint32_t*)&p3;
            *(uint4*)(oh + (size_t)row * Dn + c0) = packed;
        }
    }
}

// ------------------------------- launch ------------------------------------
extern "C" void kernel_launch(void* const* d_in, const int* in_sizes, int n_in,
                              void* d_out, int out_size)
{
    const float* x    = (const float*)d_in[0];
    const float* wq   = (const float*)d_in[1];
    const float* bq   = (const float*)d_in[2];
    const float* wk   = (const float*)d_in[3];
    const float* bk   = (const float*)d_in[4];
    const float* wv   = (const float*)d_in[5];
    const float* bv   = (const float*)d_in[6];
    const float* wo   = (const float*)d_in[7];
    const float* bo   = (const float*)d_in[8];
    const float* qcw  = (const float*)d_in[9];
    const float* qcb  = (const float*)d_in[10];
    const float* kcw  = (const float*)d_in[11];
    const float* kcb  = (const float*)d_in[12];
    const float* vcw  = (const float*)d_in[13];
    const float* vcb  = (const float*)d_in[14];
    const float* w1   = (const float*)d_in[15];
    const float* b1   = (const float*)d_in[16];
    const float* w2   = (const float*)d_in[17];
    const float* b2   = (const float*)d_in[18];
    const float* ln1g = (const float*)d_in[19];
    const float* ln1b = (const float*)d_in[20];
    const float* ln2g = (const float*)d_in[21];
    const float* ln2b = (const float*)d_in[22];
    float* out = (float*)d_out;

    float* pbqkv;
    cudaGetSymbolAddress((void**)&pbqkv, g_bqkv);

    __half *pqkvh, *pxh, *path, *pyh, *px1h, *phh, *py2h;
    __half *pwqkvh, *pwoh, *pw1h, *pw2h;
    cudaGetSymbolAddress((void**)&pqkvh,  g_qkvh);
    cudaGetSymbolAddress((void**)&pxh,    g_xh);
    cudaGetSymbolAddress((void**)&path,   g_ath);
    cudaGetSymbolAddress((void**)&pyh,    g_yh);
    cudaGetSymbolAddress((void**)&px1h,   g_x1h);
    cudaGetSymbolAddress((void**)&phh,    g_hh);
    cudaGetSymbolAddress((void**)&py2h,   g_y2h);
    cudaGetSymbolAddress((void**)&pwqkvh, g_wqkvh);
    cudaGetSymbolAddress((void**)&pwoh,   g_woh);
    cudaGetSymbolAddress((void**)&pw1h,   g_w1h);
    cudaGetSymbolAddress((void**)&pw2h,   g_w2h);

    cudaFuncSetAttribute(gemm_mma<1>, cudaFuncAttributeMaxDynamicSharedMemorySize, GSMEM);
    cudaFuncSetAttribute(gemm_mma<2>, cudaFuncAttributeMaxDynamicSharedMemorySize, GSMEM);
    cudaFuncSetAttribute(gemm_mma<3>, cudaFuncAttributeMaxDynamicSharedMemorySize, GSMEM);
    cudaFuncSetAttribute(gemm_mma<4>, cudaFuncAttributeMaxDynamicSharedMemorySize, GSMEM);

    auto cvt = [](const float* p, __half* h, size_t n) {
        int n4 = (int)(n / 4);
        cvt_h<<<(n4 + 255) / 256, 256>>>(p, h, n4);
    };

    const dim3 gridQKV(D3 / 256, Mn / 128);   // (6, 256)
    const dim3 gridD(Dn / 256, Mn / 128);     // (2, 256)
    const dim3 gridF(DFFn / 256, Mn / 128);   // (4, 256)

    // Launches 0-4 (launch #5, the ncu-profiled one, is the merged QKV GEMM)
    cvt(x,  pxh, (size_t)Mn * Dn);
    cvt(wq, pwqkvh,                       (size_t)Dn * Dn);
    cvt(wk, pwqkvh + (size_t)Dn * Dn,     (size_t)Dn * Dn);
    cvt(wv, pwqkvh + (size_t)2 * Dn * Dn, (size_t)Dn * Dn);
    pack3<<<(D3 + 255) / 256, 256>>>(bq, bk, bv, pbqkv);

    // merged QKV projection -> fp16 (launch #5)
    gemm_mma<3><<<gridQKV, 512, GSMEM>>>(pxh, pwqkvh, pbqkv, nullptr, nullptr,
                                         pqkvh, Mn, D3, Dn);

    // remaining weight converts
    cvt(wo, pwoh, (size_t)Dn * Dn);
    cvt(w1, pw1h, (size_t)DFFn * Dn);
    cvt(w2, pw2h, (size_t)Dn * DFFn);

    // depthwise conv + elu+1 + partial KV (HMMA) / Ksum
    conv_pre<<<dim3(NCH, Hn, Bn), 256>>>(pqkvh, qcw, qcb, kcw, kcb, vcw, vcb);
    kv_reduce<<<Bn * Hn, 256>>>();
    attn_apply<<<dim3(Sn / 64, Hn, Bn), 128>>>();

    // O-proj + residual(x fp32) -> fp16 y; LN1 fp16->fp16
    gemm_mma<1><<<gridD, 512, GSMEM>>>(path, pwoh, bo, x, nullptr,
                                       pyh, Mn, Dn, Dn);
    ln_kernel<false><<<Mn / 8, 256>>>(pyh, ln1g, ln1b, nullptr, px1h);

    // FFN1 gelu^2 -> fp16; FFN2 + residual(x1h fp16) -> fp16; LN2 -> fp32 out
    gemm_mma<2><<<gridF, 512, GSMEM>>>(px1h, pw1h, b1, nullptr, nullptr,
                                       phh, Mn, DFFn, Dn);
    gemm_mma<4><<<gridD, 512, GSMEM>>>(phh, pw2h, b2, nullptr, px1h,
                                       py2h, Mn, Dn, DFFn);
    ln_kernel<true><<<Mn / 8, 256>>>(py2h, ln2g, ln2b, out, nullptr);
}

// round 12
// speedup vs baseline: 5.5036x; 1.1834x over previous
#include <cuda_runtime.h>
#include <cuda_fp16.h>
#include <cstdint>

#define Bn 8
#define Sn 4096
#define Dn 512
#define Hn 8
#define DKn 64
#define DFFn 1024
#define Mn (Bn*Sn)          // 32768 rows
#define NCH 16              // seq chunks for partial KV
#define CHROWS 256
#define EPSA 1e-6f
#define LNEPS 1e-5f
#define D3 (3*Dn)           // 1536

// ---------------- scratch (device globals; no allocation allowed) ----------
__device__ float g_kvp [(size_t)Bn*Hn*NCH*DKn*DKn];
__device__ float g_ksp [(size_t)Bn*Hn*NCH*DKn];
__device__ float g_ks  [(size_t)Bn*Hn*DKn];
__device__ float g_bqkv[D3];

// fp16 buffers
__device__ __half g_qkvh[(size_t)Mn*D3];
__device__ __half g_q2h [(size_t)Mn*Dn];
__device__ __half g_kvhT[(size_t)Bn*Hn*DKn*DKn];
__device__ __half g_xh  [(size_t)Mn*Dn];
__device__ __half g_ath [(size_t)Mn*Dn];
__device__ __half g_yh  [(size_t)Mn*Dn];
__device__ __half g_x1h [(size_t)Mn*Dn];
__device__ __half g_hh  [(size_t)Mn*DFFn];
__device__ __half g_y2h [(size_t)Mn*Dn];
__device__ __half g_wqkvh[(size_t)D3*Dn];
__device__ __half g_woh [Dn*Dn];
__device__ __half g_w1h [DFFn*Dn];
__device__ __half g_w2h [Dn*DFFn];

// ------------------------- PTX helpers -------------------------------------
__device__ __forceinline__ uint32_t smem_u32(const void* p) {
    uint32_t a;
    asm("{ .reg .u64 t; cvta.to.shared.u64 t, %1; cvt.u32.u64 %0, t; }"
        : "=r"(a) : "l"(p));
    return a;
}

__device__ __forceinline__ void ldm4(uint32_t* r, uint32_t addr) {
    asm volatile("ldmatrix.sync.aligned.m8n8.x4.shared.b16 {%0,%1,%2,%3}, [%4];"
                 : "=r"(r[0]), "=r"(r[1]), "=r"(r[2]), "=r"(r[3]) : "r"(addr));
}

__device__ __forceinline__ void ldm4t(uint32_t* r, uint32_t addr) {
    asm volatile("ldmatrix.sync.aligned.m8n8.x4.trans.shared.b16 {%0,%1,%2,%3}, [%4];"
                 : "=r"(r[0]), "=r"(r[1]), "=r"(r[2]), "=r"(r[3]) : "r"(addr));
}

__device__ __forceinline__ void mma16816(float* c, const uint32_t* a,
                                         uint32_t b0, uint32_t b1) {
    asm volatile(
        "mma.sync.aligned.m16n8k16.row.col.f32.f16.f16.f32 "
        "{%0,%1,%2,%3}, {%4,%5,%6,%7}, {%8,%9}, {%0,%1,%2,%3};"
        : "+f"(c[0]), "+f"(c[1]), "+f"(c[2]), "+f"(c[3])
        : "r"(a[0]), "r"(a[1]), "r"(a[2]), "r"(a[3]), "r"(b0), "r"(b1));
}

// ================= HMMA fp16 GEMM: C = A(fp16) @ W(fp16)^T + bias ==========
// EPI: 1 = bias + fp32 res -> fp16 ; 2 = gelu(x)^2 -> fp16 ;
//      3 = bias -> fp16      ; 4 = bias + fp16 res -> fp16
// CTA tile 128x256, K-chunk 64, 16 warps, 3 stages.
#define PITCH 144                  // 64 halves + 8 pad (conflict-free ldsm)
#define ABYTES (128 * PITCH)       // 18432
#define WBYTES (256 * PITCH)       // 36864
#define STAGE (ABYTES + WBYTES)    // 55296
#define NSTG 3
#define GSMEM (NSTG * STAGE)       // 165888

template<int EPI>
__global__ void __launch_bounds__(512) gemm_mma(
    const __half* __restrict__ A, const __half* __restrict__ W,
    const float* __restrict__ bias, const float* __restrict__ res,
    const __half* __restrict__ resh, __half* __restrict__ Ch,
    int M, int N, int K)
{
    extern __shared__ char smem[];
    const uint32_t sb = smem_u32(smem);
    const int tid  = threadIdx.x;
    const int bn = blockIdx.x * 256, bm = blockIdx.y * 128;
    const int w = tid >> 5, lane = tid & 31;
    const int wm = w & 3, wn = w >> 2;
    const int mrow = lane >> 3, mr = lane & 7;

    const __half* Ap = A + (size_t)bm * K;
    const __half* Wp = W + (size_t)bn * K;
    const int nch = K >> 6;

    const int lr8 = tid >> 3, lc8 = tid & 7;   // loader: row 0..63, 16B col 0..7

    auto load_chunk = [&](int kt, int stg) {
        const uint32_t base = sb + stg * STAGE;
        const int off = kt * 64 + lc8 * 8;
        const uint32_t dA = base + lr8 * PITCH + lc8 * 16;
        asm volatile("cp.async.cg.shared.global [%0], [%1], 16;"
                     :: "r"(dA), "l"((const void*)(Ap + (size_t)lr8 * K + off)));
        asm volatile("cp.async.cg.shared.global [%0], [%1], 16;"
                     :: "r"(dA + 64 * PITCH),
                        "l"((const void*)(Ap + (size_t)(lr8 + 64) * K + off)));
        const uint32_t dW = base + ABYTES + lr8 * PITCH + lc8 * 16;
#pragma unroll
        for (int i = 0; i < 4; i++) {
            asm volatile("cp.async.cg.shared.global [%0], [%1], 16;"
                         :: "r"(dW + i * 64 * PITCH),
                            "l"((const void*)(Wp + (size_t)(lr8 + i * 64) * K + off)));
        }
        asm volatile("cp.async.commit_group;");
    };

    float acc[2][8][4];
#pragma unroll
    for (int i = 0; i < 2; i++)
#pragma unroll
        for (int j = 0; j < 8; j++)
#pragma unroll
            for (int q = 0; q < 4; q++) acc[i][j][q] = 0.f;

    load_chunk(0, 0);
    load_chunk(1, 1);

    int cs = 0, ls = 2;
    for (int kt = 0; kt < nch; kt++) {
        if (kt == nch - 1) {
            asm volatile("cp.async.wait_group 0;" ::: "memory");
        } else {
            asm volatile("cp.async.wait_group 1;" ::: "memory");
        }
        __syncthreads();
        if (kt + 2 < nch) {
            load_chunk(kt + 2, ls);
            ls = (ls == 2) ? 0 : ls + 1;
        }

        const uint32_t base = sb + cs * STAGE;
        cs = (cs == 2) ? 0 : cs + 1;
#pragma unroll
        for (int ks = 0; ks < 4; ks++) {
            uint32_t ah[2][4];
#pragma unroll
            for (int i = 0; i < 2; i++) {
                const int rowA = wm * 32 + i * 16 + (mrow & 1) * 8 + mr;
                const uint32_t cA = ks * 32 + (mrow >> 1) * 16;
                ldm4(ah[i], base + rowA * PITCH + cA);
            }
#pragma unroll
            for (int jp = 0; jp < 4; jp++) {
                const int rowB = wn * 64 + jp * 16 + (mrow >> 1) * 8 + mr;
                const uint32_t cB = ks * 32 + (mrow & 1) * 16;
                uint32_t t0[4];
                ldm4(t0, base + ABYTES + rowB * PITCH + cB);
#pragma unroll
                for (int i = 0; i < 2; i++) {
                    mma16816(acc[i][2*jp],     ah[i], t0[0], t0[1]);
                    mma16816(acc[i][2*jp + 1], ah[i], t0[2], t0[3]);
                }
            }
        }
    }
    __syncthreads();

    const int tg = lane >> 2, ti = lane & 3;
#pragma unroll
    for (int i = 0; i < 2; i++) {
#pragma unroll
        for (int j = 0; j < 8; j++) {
            const int gr0 = bm + wm * 32 + i * 16 + tg;
            const int gc  = bn + wn * 64 + j * 8 + ti * 2;
            const float b0 = bias[gc], b1 = bias[gc + 1];
#pragma unroll
            for (int hfl = 0; hfl < 2; hfl++) {
                const int gr = gr0 + hfl * 8;
                float v0 = acc[i][j][2*hfl + 0] + b0;
                float v1 = acc[i][j][2*hfl + 1] + b1;
                const size_t off = (size_t)gr * N + gc;
                if (EPI == 1) {
                    float2 rv = *(const float2*)(res + off);
                    v0 += rv.x; v1 += rv.y;
                }
                if (EPI == 4) {
                    float2 rv = __half22float2(*(const __half2*)(resh + off));
                    v0 += rv.x; v1 += rv.y;
                }
                if (EPI == 2) {
                    float g0 = 0.5f * v0 * (1.0f + erff(v0 * 0.7071067811865476f));
                    float g1 = 0.5f * v1 * (1.0f + erff(v1 * 0.7071067811865476f));
                    v0 = g0 * g0; v1 = g1 * g1;
                }
                *(__half2*)(Ch + off) = __floats2half2_rn(v0, v1);
            }
        }
    }
}

// ------------------ fp32 -> fp16 convert ------------------------------------
__global__ void cvt_h(const float* __restrict__ in, __half* __restrict__ out, int n4)
{
    const int i = blockIdx.x * 256 + threadIdx.x;
    if (i >= n4) return;
    float4 v = ((const float4*)in)[i];
    ((__half2*)out)[2 * i]     = __floats2half2_rn(v.x, v.y);
    ((__half2*)out)[2 * i + 1] = __floats2half2_rn(v.z, v.w);
}

// ------------------ pack 3 bias vectors into one ----------------------------
__global__ void pack3(const float* __restrict__ a, const float* __restrict__ b,
                      const float* __restrict__ c, float* __restrict__ o)
{
    const int i = blockIdx.x * 256 + threadIdx.x;
    if (i < Dn)            o[i] = a[i];
    else if (i < 2 * Dn)   o[i] = b[i - Dn];
    else if (i < 3 * Dn)   o[i] = c[i - 2 * Dn];
}

// ------------- conv(q,k,v) + elu+1(q,k) + partial KV (HMMA) / Ksum ---------
#define CPITCH 144
__global__ __launch_bounds__(256) void conv_pre(
    const __half* __restrict__ qkv,
    const float* __restrict__ qcw, const float* __restrict__ qcb,
    const float* __restrict__ kcw, const float* __restrict__ kcb,
    const float* __restrict__ vcw, const float* __restrict__ vcb)
{
    const int c = blockIdx.x, h = blockIdx.y, b = blockIdx.z;
    const int t  = threadIdx.x;
    const int p  = t & 31;
    const int rl = t >> 5;
    const int ch = 2 * p;
    const int w = t >> 5, lane = t & 31;
    const int mrow = lane >> 3, mr = lane & 7;
    const int dbase = (w & 3) * 16, ebase = (w >> 2) * 32;

    __shared__ __align__(16) char k2s[64 * CPITCH];
    __shared__ __align__(16) char v2s[64 * CPITCH];
    const uint32_t kbse = smem_u32(k2s);
    const uint32_t vbse = smem_u32(v2s);

    const float qw0a = qcw[ch*3+0], qw1a = qcw[ch*3+1], qw2a = qcw[ch*3+2], qba = qcb[ch];
    const float qw0b = qcw[ch*3+3], qw1b = qcw[ch*3+4], qw2b = qcw[ch*3+5], qbb = qcb[ch+1];
    const float kw0a = kcw[ch*3+0], kw1a = kcw[ch*3+1], kw2a = kcw[ch*3+2], kba = kcb[ch];
    const float kw0b = kcw[ch*3+3], kw1b = kcw[ch*3+4], kw2b = kcw[ch*3+5], kbb = kcb[ch+1];
    const float vw0a = vcw[ch*3+0], vw1a = vcw[ch*3+1], vw2a = vcw[ch*3+2], vba = vcb[ch];
    const float vw0b = vcw[ch*3+3], vw1b = vcw[ch*3+4], vw2b = vcw[ch*3+5], vbb = vcb[ch+1];

    float accm[4][4];
#pragma unroll
    for (int i = 0; i < 4; i++)
#pragma unroll
        for (int j = 0; j < 4; j++) accm[i][j] = 0.f;
    float ksacc = 0.f;

    for (int sub = 0; sub < 4; sub++) {
        __syncthreads();
        const int s0 = c * CHROWS + sub * 64 + rl * 8;
        const size_t qb0  = ((size_t)(b * Sn + s0)) * D3 + h * DKn + ch;
        const size_t q2b0 = ((size_t)(b * Sn + s0)) * Dn + h * DKn + ch;
        float2 qm1 = {0.f,0.f}, qm2 = {0.f,0.f};
        float2 km1 = {0.f,0.f}, km2 = {0.f,0.f};
        float2 vm1 = {0.f,0.f}, vm2 = {0.f,0.f};
        if (s0 >= 1) {
            qm1 = __half22float2(*(const __half2*)(qkv + qb0 - D3));
            km1 = __half22float2(*(const __half2*)(qkv + qb0 - D3 + Dn));
            vm1 = __half22float2(*(const __half2*)(qkv + qb0 - D3 + 2 * Dn));
        }
        if (s0 >= 2) {
            qm2 = __half22float2(*(const __half2*)(qkv + qb0 - 2 * D3));
            km2 = __half22float2(*(const __half2*)(qkv + qb0 - 2 * D3 + Dn));
            vm2 = __half22float2(*(const __half2*)(qkv + qb0 - 2 * D3 + 2 * Dn));
        }
#pragma unroll
        for (int i = 0; i < 8; i++) {
            const int r = rl * 8 + i;
            const size_t base = qb0 + (size_t)i * D3;

            float2 q0 = __half22float2(*(const __half2*)(qkv + base));
            float qcx = qw0a*qm2.x + qw1a*qm1.x + qw2a*q0.x + qba;
            float qcy = qw0b*qm2.y + qw1b*qm1.y + qw2b*q0.y + qbb;
            qcx = qcx > 0.f ? qcx + 1.f : __expf(qcx);
            qcy = qcy > 0.f ? qcy + 1.f : __expf(qcy);
            *(__half2*)(g_q2h + q2b0 + (size_t)i * Dn) = __floats2half2_rn(qcx, qcy);
            qm2 = qm1; qm1 = q0;

            float2 k0 = __half22float2(*(const __half2*)(qkv + base + Dn));
            float kcx = kw0a*km2.x + kw1a*km1.x + kw2a*k0.x + kba;
            float kcy = kw0b*km2.y + kw1b*km1.y + kw2b*k0.y + kbb;
            kcx = kcx > 0.f ? kcx + 1.f : __expf(kcx);
            kcy = kcy > 0.f ? kcy + 1.f : __expf(kcy);
            *(__half2*)(k2s + r * CPITCH + ch * 2) = __floats2half2_rn(kcx, kcy);
            km2 = km1; km1 = k0;

            float2 v0 = __half22float2(*(const __half2*)(qkv + base + 2 * Dn));
            float vcx = vw0a*vm2.x + vw1a*vm1.x + vw2a*v0.x + vba;
            float vcy = vw0b*vm2.y + vw1b*vm1.y + vw2b*v0.y + vbb;
            *(__half2*)(v2s + r * CPITCH + ch * 2) = __floats2half2_rn(vcx, vcy);
            vm2 = vm1; vm1 = v0;
        }
        __syncthreads();
        if (t < 64) {
#pragma unroll 8
            for (int r = 0; r < 64; r++)
                ksacc += __half2float(*(const __half*)(k2s + r * CPITCH + t * 2));
        }
#pragma unroll
        for (int ksb = 0; ksb < 4; ksb++) {
            uint32_t a[4];
            ldm4t(a, kbse + (ksb * 16 + (mrow >> 1) * 8 + mr) * CPITCH
                      + dbase * 2 + (mrow & 1) * 16);
#pragma unroll
            for (int jb = 0; jb < 2; jb++) {
                uint32_t t4[4];
                ldm4t(t4, vbse + (ksb * 16 + (mrow & 1) * 8 + mr) * CPITCH
                          + (ebase + jb * 16) * 2 + (mrow >> 1) * 16);
                mma16816(accm[2*jb],     a, t4[0], t4[1]);
                mma16816(accm[2*jb + 1], a, t4[2], t4[3]);
            }
        }
    }

    const int bh = b * Hn + h;
    const size_t kvbase = ((size_t)bh * NCH + c) * (DKn * DKn);
    const int tg = lane >> 2, ti = lane & 3;
#pragma unroll
    for (int jn = 0; jn < 4; jn++) {
#pragma unroll
        for (int hfl = 0; hfl < 2; hfl++) {
            const int d = dbase + hfl * 8 + tg;
            const int e = ebase + jn * 8 + ti * 2;
            g_kvp[kvbase + (size_t)d * DKn + e]     = accm[jn][2*hfl];
            g_kvp[kvbase + (size_t)d * DKn + e + 1] = accm[jn][2*hfl + 1];
        }
    }
    if (t < 64)
        g_ksp[((size_t)bh * NCH + c) * DKn + t] = ksacc;
}

// ---- reduce partial KV (-> fp16 transposed) / Ksum over chunks ------------
__global__ void kv_reduce()
{
    const int bh = blockIdx.x, t = threadIdx.x;
    for (int idx = t; idx < DKn * DKn; idx += 256) {
        float s = 0.f;
#pragma unroll
        for (int c = 0; c < NCH; c++)
            s += g_kvp[((size_t)bh * NCH + c) * (DKn * DKn) + idx];
        const int d = idx >> 6, e = idx & 63;
        g_kvhT[(size_t)bh * (DKn * DKn) + e * DKn + d] = __float2half_rn(s);
    }
    if (t < DKn) {
        float s = 0.f;
#pragma unroll
        for (int c = 0; c < NCH; c++)
            s += g_ksp[((size_t)bh * NCH + c) * DKn + t];
        g_ks[(size_t)bh * DKn + t] = s;
    }
}

// ---- attn apply via HMMA: Vn = (Q @ KV) / (Q.(Ksum+eps)); 128 rows/block --
#define APITCH 144
__global__ __launch_bounds__(128) void attn_apply()
{
    const int st = blockIdx.x, h = blockIdx.y, b = blockIdx.z;
    const int t = threadIdx.x;
    const int bh = b * Hn + h;
    const int w = t >> 5, lane = t & 31;
    const int mrow = lane >> 3, mr = lane & 7;

    __shared__ __align__(16) char qsmem[64 * APITCH];
    __shared__ __align__(16) char ksmem[64 * APITCH];
    __shared__ float kss[64];
    __shared__ float zinv[64];

    const uint32_t qb = smem_u32(qsmem);
    const uint32_t kb = smem_u32(ksmem);

    // KV tile + Ksum loaded once, reused for both 64-row q tiles
    for (int idx = t; idx < 1024; idx += 128) {
        const int r = idx >> 4, c4 = idx & 15;
        *(uint2*)(ksmem + r * APITCH + c4 * 8) =
            *(const uint2*)(g_kvhT + (size_t)bh * (DKn * DKn) + r * DKn + c4 * 4);
    }
    if (t < DKn) kss[t] = g_ks[(size_t)bh * DKn + t] + EPSA;

    for (int tile = 0; tile < 2; tile++) {
        const int row0 = st * 128 + tile * 64;
        __syncthreads();   // ksmem ready (tile 0) / prev epilogue done (tile 1)
        for (int idx = t; idx < 1024; idx += 128) {
            const int r = idx >> 4, c4 = idx & 15;
            *(uint2*)(qsmem + r * APITCH + c4 * 8) =
                *(const uint2*)(g_q2h + ((size_t)(b * Sn + row0 + r)) * Dn
                                + h * DKn + c4 * 4);
        }
        __syncthreads();

        {
            const int s = t >> 1, part = t & 1;
            float z = 0.f;
            const char* rp = qsmem + s * APITCH + part * 64;
#pragma unroll
            for (int d = 0; d < 32; d++)
                z += __half2float(*(const __half*)(rp + d * 2)) * kss[part * 32 + d];
            z += __shfl_xor_sync(0xffffffffu, z, 1);
            if (part == 0) zinv[s] = 1.0f / z;
        }

        float acc[8][4];
#pragma unroll
        for (int j = 0; j < 8; j++)
#pragma unroll
            for (int q = 0; q < 4; q++) acc[j][q] = 0.f;

#pragma unroll
        for (int ks = 0; ks < 4; ks++) {
            uint32_t ah[4];
            const int rowA = w * 16 + (mrow & 1) * 8 + mr;
            ldm4(ah, qb + rowA * APITCH + ks * 32 + (mrow >> 1) * 16);
#pragma unroll
            for (int jp = 0; jp < 4; jp++) {
                const int rowB = jp * 16 + (mrow >> 1) * 8 + mr;
                uint32_t t0[4];
                ldm4(t0, kb + rowB * APITCH + ks * 32 + (mrow & 1) * 16);
                mma16816(acc[2*jp],     ah, t0[0], t0[1]);
                mma16816(acc[2*jp + 1], ah, t0[2], t0[3]);
            }
        }
        __syncthreads();   // zinv visible

        const int tg = lane >> 2, ti = lane & 3;
#pragma unroll
        for (int j = 0; j < 8; j++) {
            const int col = j * 8 + ti * 2;
#pragma unroll
            for (int hfl = 0; hfl < 2; hfl++) {
                const int row = w * 16 + hfl * 8 + tg;
                const float zi = zinv[row];
                const size_t off = ((size_t)(b * Sn + row0 + row)) * Dn
                                   + h * DKn + col;
                *(__half2*)(g_ath + off) =
                    __floats2half2_rn(zi * acc[j][2*hfl], zi * acc[j][2*hfl + 1]);
            }
        }
    }
}

// -------------------- LayerNorm (D=512), warp per row, fp16 in -------------
template<bool OUTF32>
__global__ __launch_bounds__(256) void ln_kernel(
    const __half* __restrict__ in, const float* __restrict__ gw,
    const float* __restrict__ bw, float* __restrict__ out,
    __half* __restrict__ oh)
{
    const int warp = threadIdx.x >> 5, lane = threadIdx.x & 31;
    const int row = blockIdx.x * 8 + warp;
    const uint4* rp = (const uint4*)(in + (size_t)row * Dn);

    float vals[16];
    float s1 = 0.f, s2 = 0.f;
#pragma unroll
    for (int i = 0; i < 2; i++) {
        uint4 raw = rp[lane + i * 32];
        const uint32_t u[4] = {raw.x, raw.y, raw.z, raw.w};
#pragma unroll
        for (int k = 0; k < 4; k++) {
            float2 f = __half22float2(*(const __half2*)&u[k]);
            vals[i * 8 + 2 * k]     = f.x;
            vals[i * 8 + 2 * k + 1] = f.y;
            s1 += f.x + f.y;
            s2 += f.x * f.x + f.y * f.y;
        }
    }
#pragma unroll
    for (int o = 16; o > 0; o >>= 1) {
        s1 += __shfl_xor_sync(0xffffffffu, s1, o);
        s2 += __shfl_xor_sync(0xffffffffu, s2, o);
    }
    const float m = s1 * (1.0f / Dn);
    const float rr = rsqrtf(s2 * (1.0f / Dn) - m * m + LNEPS);

#pragma unroll
    for (int i = 0; i < 2; i++) {
        const int c0 = (lane + i * 32) * 8;
        float o8[8];
#pragma unroll
        for (int k = 0; k < 2; k++) {
            const float4 g4 = *(const float4*)(gw + c0 + k * 4);
            const float4 b4 = *(const float4*)(bw + c0 + k * 4);
            o8[k*4+0] = (vals[i*8 + k*4 + 0] - m) * rr * g4.x + b4.x;
            o8[k*4+1] = (vals[i*8 + k*4 + 1] - m) * rr * g4.y + b4.y;
            o8[k*4+2] = (vals[i*8 + k*4 + 2] - m) * rr * g4.z + b4.z;
            o8[k*4+3] = (vals[i*8 + k*4 + 3] - m) * rr * g4.w + b4.w;
        }
        if (OUTF32) {
#pragma unroll
            for (int k = 0; k < 2; k++) {
                float4 o4; o4.x = o8[k*4]; o4.y = o8[k*4+1];
                o4.z = o8[k*4+2]; o4.w = o8[k*4+3];
                *(float4*)(out + (size_t)row * Dn + c0 + k * 4) = o4;
            }
        } else {
            uint4 packed;
            __half2 p0 = __floats2half2_rn(o8[0], o8[1]);
            __half2 p1 = __floats2half2_rn(o8[2], o8[3]);
            __half2 p2 = __floats2half2_rn(o8[4], o8[5]);
            __half2 p3 = __floats2half2_rn(o8[6], o8[7]);
            packed.x = *(uint32_t*)&p0; packed.y = *(uint32_t*)&p1;
            packed.z = *(uint32_t*)&p2; packed.w = *(uint32_t*)&p3;
            *(uint4*)(oh + (size_t)row * Dn + c0) = packed;
        }
    }
}

// ------------------------------- launch ------------------------------------
extern "C" void kernel_launch(void* const* d_in, const int* in_sizes, int n_in,
                              void* d_out, int out_size)
{
    const float* x    = (const float*)d_in[0];
    const float* wq   = (const float*)d_in[1];
    const float* bq   = (const float*)d_in[2];
    const float* wk   = (const float*)d_in[3];
    const float* bk   = (const float*)d_in[4];
    const float* wv   = (const float*)d_in[5];
    const float* bv   = (const float*)d_in[6];
    const float* wo   = (const float*)d_in[7];
    const float* bo   = (const float*)d_in[8];
    const float* qcw  = (const float*)d_in[9];
    const float* qcb  = (const float*)d_in[10];
    const float* kcw  = (const float*)d_in[11];
    const float* kcb  = (const float*)d_in[12];
    const float* vcw  = (const float*)d_in[13];
    const float* vcb  = (const float*)d_in[14];
    const float* w1   = (const float*)d_in[15];
    const float* b1   = (const float*)d_in[16];
    const float* w2   = (const float*)d_in[17];
    const float* b2   = (const float*)d_in[18];
    const float* ln1g = (const float*)d_in[19];
    const float* ln1b = (const float*)d_in[20];
    const float* ln2g = (const float*)d_in[21];
    const float* ln2b = (const float*)d_in[22];
    float* out = (float*)d_out;

    float* pbqkv;
    cudaGetSymbolAddress((void**)&pbqkv, g_bqkv);

    __half *pqkvh, *pxh, *path, *pyh, *px1h, *phh, *py2h;
    __half *pwqkvh, *pwoh, *pw1h, *pw2h;
    cudaGetSymbolAddress((void**)&pqkvh,  g_qkvh);
    cudaGetSymbolAddress((void**)&pxh,    g_xh);
    cudaGetSymbolAddress((void**)&path,   g_ath);
    cudaGetSymbolAddress((void**)&pyh,    g_yh);
    cudaGetSymbolAddress((void**)&px1h,   g_x1h);
    cudaGetSymbolAddress((void**)&phh,    g_hh);
    cudaGetSymbolAddress((void**)&py2h,   g_y2h);
    cudaGetSymbolAddress((void**)&pwqkvh, g_wqkvh);
    cudaGetSymbolAddress((void**)&pwoh,   g_woh);
    cudaGetSymbolAddress((void**)&pw1h,   g_w1h);
    cudaGetSymbolAddress((void**)&pw2h,   g_w2h);

    cudaFuncSetAttribute(gemm_mma<1>, cudaFuncAttributeMaxDynamicSharedMemorySize, GSMEM);
    cudaFuncSetAttribute(gemm_mma<2>, cudaFuncAttributeMaxDynamicSharedMemorySize, GSMEM);
    cudaFuncSetAttribute(gemm_mma<3>, cudaFuncAttributeMaxDynamicSharedMemorySize, GSMEM);
    cudaFuncSetAttribute(gemm_mma<4>, cudaFuncAttributeMaxDynamicSharedMemorySize, GSMEM);

    auto cvt = [](const float* p, __half* h, size_t n) {
        int n4 = (int)(n / 4);
        cvt_h<<<(n4 + 255) / 256, 256>>>(p, h, n4);
    };

    const dim3 gridQKV(D3 / 256, Mn / 128);   // (6, 256)
    const dim3 gridD(Dn / 256, Mn / 128);     // (2, 256)
    const dim3 gridF(DFFn / 256, Mn / 128);   // (4, 256)

    cvt(x,  pxh, (size_t)Mn * Dn);
    cvt(wq, pwqkvh,                       (size_t)Dn * Dn);
    cvt(wk, pwqkvh + (size_t)Dn * Dn,     (size_t)Dn * Dn);
    cvt(wv, pwqkvh + (size_t)2 * Dn * Dn, (size_t)Dn * Dn);
    pack3<<<(D3 + 255) / 256, 256>>>(bq, bk, bv, pbqkv);

    // merged QKV projection -> fp16
    gemm_mma<3><<<gridQKV, 512, GSMEM>>>(pxh, pwqkvh, pbqkv, nullptr, nullptr,
                                         pqkvh, Mn, D3, Dn);

    // remaining weight converts
    cvt(wo, pwoh, (size_t)Dn * Dn);
    cvt(w1, pw1h, (size_t)DFFn * Dn);
    cvt(w2, pw2h, (size_t)Dn * DFFn);

    // depthwise conv + elu+1 + partial KV (HMMA) / Ksum
    conv_pre<<<dim3(NCH, Hn, Bn), 256>>>(pqkvh, qcw, qcb, kcw, kcb, vcw, vcb);
    kv_reduce<<<Bn * Hn, 256>>>();
    attn_apply<<<dim3(Sn / 128, Hn, Bn), 128>>>();

    // O-proj + residual(x fp32) -> fp16 y; LN1 fp16->fp16
    gemm_mma<1><<<gridD, 512, GSMEM>>>(path, pwoh, bo, x, nullptr,
                                       pyh, Mn, Dn, Dn);
    ln_kernel<false><<<Mn / 8, 256>>>(pyh, ln1g, ln1b, nullptr, px1h);

    // FFN1 gelu^2 -> fp16; FFN2 + residual(x1h fp16) -> fp16; LN2 -> fp32 out
    gemm_mma<2><<<gridF, 512, GSMEM>>>(px1h, pw1h, b1, nullptr, nullptr,
                                       phh, Mn, DFFn, Dn);
    gemm_mma<4><<<gridD, 512, GSMEM>>>(phh, pw2h, b2, nullptr, px1h,
                                       py2h, Mn, Dn, DFFn);
    ln_kernel<true><<<Mn / 8, 256>>>(py2h, ln2g, ln2b, out, nullptr);
}